// round 1
// baseline (speedup 1.0000x reference)
#include <cuda_runtime.h>

#define S_LEN  2048
#define DMODEL 1024
#define NHEAD  16
#define DK     64
#define BATCH  4

// Scratch (module-scope device memory — allowed; no runtime allocation).
__device__ float g_Q[BATCH * NHEAD * S_LEN * DK];
__device__ float g_K[BATCH * NHEAD * S_LEN * DK];
__device__ float g_V[BATCH * NHEAD * S_LEN * DK];
__device__ float g_Ctx[BATCH * S_LEN * DMODEL];

// ---------------------------------------------------------------------------
// C = A[M,K] @ W[N,K]^T + bias[N]
// remap=1: scatter output into [B, H, S, dk] head-split layout
// remap=0: plain row-major [M, N]
// Tiles: 64x64x32, 256 threads, 4x4 accumulators per thread.
// ---------------------------------------------------------------------------
__global__ __launch_bounds__(256) void proj_gemm(
    const float* __restrict__ A, const float* __restrict__ W,
    const float* __restrict__ bias, float* __restrict__ C,
    int K, int remap)
{
    __shared__ float As[64][33];
    __shared__ float Ws[64][33];

    const int tid = threadIdx.x;
    const int tx = tid & 15, ty = tid >> 4;
    const int m0 = blockIdx.y << 6, n0 = blockIdx.x << 6;

    float acc[4][4] = {};

    for (int k0 = 0; k0 < K; k0 += 32) {
#pragma unroll
        for (int r = 0; r < 2; r++) {
            int f   = tid + (r << 8);
            int row = f >> 3;
            int c4  = (f & 7) << 2;
            float4 va = *(const float4*)(A + (size_t)(m0 + row) * K + k0 + c4);
            As[row][c4 + 0] = va.x; As[row][c4 + 1] = va.y;
            As[row][c4 + 2] = va.z; As[row][c4 + 3] = va.w;
            float4 vw = *(const float4*)(W + (size_t)(n0 + row) * K + k0 + c4);
            Ws[row][c4 + 0] = vw.x; Ws[row][c4 + 1] = vw.y;
            Ws[row][c4 + 2] = vw.z; Ws[row][c4 + 3] = vw.w;
        }
        __syncthreads();

#pragma unroll 16
        for (int k = 0; k < 32; k++) {
            float a[4], b[4];
#pragma unroll
            for (int i = 0; i < 4; i++) a[i] = As[(ty << 2) + i][k];
#pragma unroll
            for (int j = 0; j < 4; j++) b[j] = Ws[(tx << 2) + j][k];
#pragma unroll
            for (int i = 0; i < 4; i++)
#pragma unroll
                for (int j = 0; j < 4; j++)
                    acc[i][j] = fmaf(a[i], b[j], acc[i][j]);
        }
        __syncthreads();
    }

#pragma unroll
    for (int i = 0; i < 4; i++) {
        int m = m0 + (ty << 2) + i;
#pragma unroll
        for (int j = 0; j < 4; j++) {
            int n = n0 + (tx << 2) + j;
            float v = acc[i][j] + bias[n];
            if (remap) {
                int b = m >> 11, s = m & (S_LEN - 1);
                int h = n >> 6,  d = n & (DK - 1);
                g_dummy_noop:
                C[((size_t)((b << 4) + h) * S_LEN + s) * DK + d] = v;
            } else {
                C[(size_t)m * DMODEL + n] = v;
            }
        }
    }
}

// ---------------------------------------------------------------------------
// Causal flash attention, fp32. One block per (q-tile of 64 rows, b*h).
// Q/K/V: [B*H, S, 64]. Output context: [B, S, 1024].
// ---------------------------------------------------------------------------
__global__ __launch_bounds__(256) void flash_attn(
    const float* __restrict__ Qg, const float* __restrict__ Kg,
    const float* __restrict__ Vg, float* __restrict__ Ctx)
{
    __shared__ float Qs[64][65];
    __shared__ float Ks[64][65];
    __shared__ float Vs[64][64];
    __shared__ float Ps[64][65];

    const int tid = threadIdx.x;
    const int tx = tid & 15, ty = tid >> 4;
    const int qt = blockIdx.x;          // q tile (0..31)
    const int bh = blockIdx.y;          // 0..63

    const float* Qp = Qg + (size_t)bh * S_LEN * DK;
    const float* Kp = Kg + (size_t)bh * S_LEN * DK;
    const float* Vp = Vg + (size_t)bh * S_LEN * DK;

    // Load Q tile [64][64]
#pragma unroll
    for (int r = 0; r < 4; r++) {
        int f   = tid + (r << 8);
        int row = f >> 4;
        int c4  = (f & 15) << 2;
        float4 v = *(const float4*)(Qp + (size_t)(qt * 64 + row) * DK + c4);
        Qs[row][c4 + 0] = v.x; Qs[row][c4 + 1] = v.y;
        Qs[row][c4 + 2] = v.z; Qs[row][c4 + 3] = v.w;
    }

    float m_i[4], l_i[4], o[4][4];
#pragma unroll
    for (int i = 0; i < 4; i++) {
        m_i[i] = -1e30f;
        l_i[i] = 0.0f;
#pragma unroll
        for (int j = 0; j < 4; j++) o[i][j] = 0.0f;
    }

    for (int kt = 0; kt <= qt; kt++) {
        // Load K and V tiles
#pragma unroll
        for (int r = 0; r < 4; r++) {
            int f   = tid + (r << 8);
            int row = f >> 4;
            int c4  = (f & 15) << 2;
            float4 vk = *(const float4*)(Kp + (size_t)(kt * 64 + row) * DK + c4);
            Ks[row][c4 + 0] = vk.x; Ks[row][c4 + 1] = vk.y;
            Ks[row][c4 + 2] = vk.z; Ks[row][c4 + 3] = vk.w;
            float4 vv = *(const float4*)(Vp + (size_t)(kt * 64 + row) * DK + c4);
            *(float4*)&Vs[row][c4] = vv;
        }
        __syncthreads();

        // S = Q K^T
        float s[4][4] = {};
#pragma unroll 16
        for (int d = 0; d < 64; d++) {
            float a[4], b[4];
#pragma unroll
            for (int i = 0; i < 4; i++) a[i] = Qs[(ty << 2) + i][d];
#pragma unroll
            for (int j = 0; j < 4; j++) b[j] = Ks[(tx << 2) + j][d];
#pragma unroll
            for (int i = 0; i < 4; i++)
#pragma unroll
                for (int j = 0; j < 4; j++)
                    s[i][j] = fmaf(a[i], b[j], s[i][j]);
        }

        // scale + causal mask (only the diagonal tile needs masking)
        const float scale = 0.125f;   // 1/sqrt(64)
        if (kt == qt) {
#pragma unroll
            for (int i = 0; i < 4; i++)
#pragma unroll
                for (int j = 0; j < 4; j++)
                    s[i][j] = ((tx << 2) + j > (ty << 2) + i) ? -1e30f
                                                              : s[i][j] * scale;
        } else {
#pragma unroll
            for (int i = 0; i < 4; i++)
#pragma unroll
                for (int j = 0; j < 4; j++)
                    s[i][j] *= scale;
        }

        // online softmax per row (rows ty*4+i; 16 lanes of same ty own a row)
#pragma unroll
        for (int i = 0; i < 4; i++) {
            float mx = fmaxf(fmaxf(s[i][0], s[i][1]), fmaxf(s[i][2], s[i][3]));
#pragma unroll
            for (int off = 8; off >= 1; off >>= 1)
                mx = fmaxf(mx, __shfl_xor_sync(0xffffffffu, mx, off, 16));
            float mnew = fmaxf(m_i[i], mx);
            float corr = __expf(m_i[i] - mnew);
            float rs = 0.0f;
#pragma unroll
            for (int j = 0; j < 4; j++) {
                float p = __expf(s[i][j] - mnew);
                Ps[(ty << 2) + i][(tx << 2) + j] = p;
                rs += p;
            }
#pragma unroll
            for (int off = 8; off >= 1; off >>= 1)
                rs += __shfl_xor_sync(0xffffffffu, rs, off, 16);
            l_i[i] = l_i[i] * corr + rs;
            m_i[i] = mnew;
#pragma unroll
            for (int j = 0; j < 4; j++) o[i][j] *= corr;
        }
        __syncthreads();

        // O += P @ V
#pragma unroll 8
        for (int kv = 0; kv < 64; kv++) {
            float4 v4 = *(const float4*)&Vs[kv][tx << 2];
#pragma unroll
            for (int i = 0; i < 4; i++) {
                float p = Ps[(ty << 2) + i][kv];
                o[i][0] = fmaf(p, v4.x, o[i][0]);
                o[i][1] = fmaf(p, v4.y, o[i][1]);
                o[i][2] = fmaf(p, v4.z, o[i][2]);
                o[i][3] = fmaf(p, v4.w, o[i][3]);
            }
        }
        __syncthreads();
    }

    // Epilogue: normalize and write context [B, S, D]
    const int b = bh >> 4, h = bh & 15;
#pragma unroll
    for (int i = 0; i < 4; i++) {
        int qrow = qt * 64 + (ty << 2) + i;
        float inv = 1.0f / l_i[i];
        float4 v;
        v.x = o[i][0] * inv; v.y = o[i][1] * inv;
        v.z = o[i][2] * inv; v.w = o[i][3] * inv;
        *(float4*)(Ctx + ((size_t)(b * S_LEN + qrow)) * DMODEL
                   + h * DK + (tx << 2)) = v;
    }
}

// ---------------------------------------------------------------------------
extern "C" void kernel_launch(void* const* d_in, const int* in_sizes, int n_in,
                              void* d_out, int out_size)
{
    const float* query = (const float*)d_in[0];
    const float* key   = (const float*)d_in[1];
    const float* value = (const float*)d_in[2];
    // d_in[3] = causal mask (tril) — implemented analytically.
    const float* Wq = (const float*)d_in[4];
    const float* bq = (const float*)d_in[5];
    const float* Wk = (const float*)d_in[6];
    const float* bk = (const float*)d_in[7];
    const float* Wv = (const float*)d_in[8];
    const float* bv = (const float*)d_in[9];
    const float* Wo = (const float*)d_in[10];
    const float* bo = (const float*)d_in[11];
    float* out = (float*)d_out;

    float *Qb, *Kb, *Vb, *Cb;
    cudaGetSymbolAddress((void**)&Qb, g_Q);
    cudaGetSymbolAddress((void**)&Kb, g_K);
    cudaGetSymbolAddress((void**)&Vb, g_V);
    cudaGetSymbolAddress((void**)&Cb, g_Ctx);

    dim3 gg(DMODEL / 64, (BATCH * S_LEN) / 64);   // (16, 128)
    proj_gemm<<<gg, 256>>>(query, Wq, bq, Qb, DMODEL, 1);
    proj_gemm<<<gg, 256>>>(key,   Wk, bk, Kb, DMODEL, 1);
    proj_gemm<<<gg, 256>>>(value, Wv, bv, Vb, DMODEL, 1);

    flash_attn<<<dim3(S_LEN / 64, BATCH * NHEAD), 256>>>(Qb, Kb, Vb, Cb);

    proj_gemm<<<gg, 256>>>(Cb, Wo, bo, out, DMODEL, 0);
}

// round 3
// speedup vs baseline: 1.9599x; 1.9599x over previous
#include <cuda_runtime.h>
#include <cuda_fp16.h>
#include <cstdint>

#define S_LEN  2048
#define DMODEL 1024
#define NHEAD  16
#define DK     64
#define BATCH  4
#define MTOT   (BATCH * S_LEN)     // 8192

// ---------------- scratch (module-scope device memory) ----------------
__device__ float  g_Q[MTOT * DK * NHEAD / NHEAD * NHEAD];  // [B*H, S, DK] = MTOT*DMODEL? no:
// Q/K/V in head-split layout [B,H,S,DK] = BATCH*NHEAD*S_LEN*DK = 8.4M floats
__device__ float  g_Qh[BATCH * NHEAD * S_LEN * DK];
__device__ float  g_Kh[BATCH * NHEAD * S_LEN * DK];
__device__ float  g_Vh[BATCH * NHEAD * S_LEN * DK];
__device__ float  g_Ctx[MTOT * DMODEL];
__device__ __half g_Ah[MTOT * DMODEL];
__device__ __half g_Al[MTOT * DMODEL];
__device__ __half g_Wh[DMODEL * DMODEL];
__device__ __half g_Wl[DMODEL * DMODEL];

// ---------------- PTX helpers (baseline PTX only — no 'a' features) ----
__device__ __forceinline__ uint32_t cvta_smem(const void* p) {
    uint32_t a;
    asm("{ .reg .u64 t; cvta.to.shared.u64 t, %1; cvt.u32.u64 %0, t; }"
        : "=r"(a) : "l"(p));
    return a;
}
__device__ __forceinline__ void cp16(uint32_t dst, const void* src) {
    asm volatile("cp.async.cg.shared.global [%0], [%1], 16;"
                 :: "r"(dst), "l"(src));
}
#define CP_COMMIT() asm volatile("cp.async.commit_group;" ::: "memory")
#define CP_WAIT(n)  asm volatile("cp.async.wait_group %0;" :: "n"(n) : "memory")

__device__ __forceinline__ void ldsm4(uint32_t* r, uint32_t addr) {
    asm volatile("ldmatrix.sync.aligned.m8n8.x4.shared.b16 {%0,%1,%2,%3}, [%4];"
                 : "=r"(r[0]), "=r"(r[1]), "=r"(r[2]), "=r"(r[3]) : "r"(addr));
}
__device__ __forceinline__ void mma16816(float* d, const uint32_t* a,
                                         uint32_t b0, uint32_t b1) {
    asm volatile(
        "mma.sync.aligned.m16n8k16.row.col.f32.f16.f16.f32 "
        "{%0,%1,%2,%3}, {%4,%5,%6,%7}, {%8,%9}, {%0,%1,%2,%3};"
        : "+f"(d[0]), "+f"(d[1]), "+f"(d[2]), "+f"(d[3])
        : "r"(a[0]), "r"(a[1]), "r"(a[2]), "r"(a[3]), "r"(b0), "r"(b1));
}

// ---------------- fp32 -> split f16 (hi/lo) ----------------------------
__global__ __launch_bounds__(256) void split_f32(
    const float4* __restrict__ x, uint2* __restrict__ hi,
    uint2* __restrict__ lo, int n4)
{
    int i = blockIdx.x * 256 + threadIdx.x;
    if (i >= n4) return;
    float4 v = x[i];
    __half h0 = __float2half_rn(v.x), h1 = __float2half_rn(v.y);
    __half h2 = __float2half_rn(v.z), h3 = __float2half_rn(v.w);
    __half l0 = __float2half_rn(v.x - __half2float(h0));
    __half l1 = __float2half_rn(v.y - __half2float(h1));
    __half l2 = __float2half_rn(v.z - __half2float(h2));
    __half l3 = __float2half_rn(v.w - __half2float(h3));
    uint2 H, L;
    H.x = (uint32_t)__half_as_ushort(h0) | ((uint32_t)__half_as_ushort(h1) << 16);
    H.y = (uint32_t)__half_as_ushort(h2) | ((uint32_t)__half_as_ushort(h3) << 16);
    L.x = (uint32_t)__half_as_ushort(l0) | ((uint32_t)__half_as_ushort(l1) << 16);
    L.y = (uint32_t)__half_as_ushort(l2) | ((uint32_t)__half_as_ushort(l3) << 16);
    hi[i] = H;
    lo[i] = L;
}

// ---------------- HMMA projection GEMM ---------------------------------
// C[M,1024] = A[M,1024] @ W[1024,1024]^T + bias, A/W pre-split f16 hi/lo.
// CTA 128x128, warp 64x32, K-chunk 32, 2-stage cp.async pipeline.
#define KCH   32
#define NC    (DMODEL / KCH)   // 32
#define PITCH 40               // halves per smem row (80B — conflict-free LDSM)
#define BUF_B (128 * PITCH * 2)       // 10240 B per operand buffer
#define STG_B (4 * BUF_B)             // 40960 B per stage
#define SMEM_GEMM (2 * STG_B)         // 81920 B

__global__ __launch_bounds__(256) void proj_gemm_mma(
    const __half* __restrict__ Ahg, const __half* __restrict__ Alg,
    const __half* __restrict__ Whg, const __half* __restrict__ Wlg,
    const float* __restrict__ bias, float* __restrict__ C, int remap)
{
    extern __shared__ char sm[];
    const uint32_t smb = cvta_smem(sm);
    const int tid = threadIdx.x;
    const int wid = tid >> 5, lane = tid & 31;
    const int wm = wid & 1;          // m: 0..1 (64 rows each)
    const int wn = wid >> 1;         // n: 0..3 (32 cols each)
    const int m0 = blockIdx.y * 128;
    const int n0 = blockIdx.x * 128;

    // ldmatrix lane offsets (in halves)
    const int laneA = ((lane & 7) + ((lane >> 3) & 1) * 8) * PITCH + ((lane >> 4) & 1) * 8;
    const int laneB = ((lane & 7) + ((lane >> 4) & 1) * 8) * PITCH + ((lane >> 3) & 1) * 8;

    // per-thread cp.async coordinates: 512 x 16B fetches per operand buffer
    const int ldr = tid >> 2;        // row 0..63  (x2 iters -> 128 rows)
    const int ldq = tid & 3;         // 16B quad within 64B row

    auto load_chunk = [&](int c, int stage) {
        const uint32_t sbase = smb + stage * STG_B;
#pragma unroll
        for (int i = 0; i < 2; i++) {
            int row = ldr + i * 64;
            uint32_t soff = (uint32_t)row * 80u + (uint32_t)ldq * 16u;
            size_t goff = (size_t)row * DMODEL + c * KCH + ldq * 8;
            cp16(sbase + 0 * BUF_B + soff, Ahg + (size_t)m0 * DMODEL + goff);
            cp16(sbase + 1 * BUF_B + soff, Alg + (size_t)m0 * DMODEL + goff);
            cp16(sbase + 2 * BUF_B + soff, Whg + (size_t)n0 * DMODEL + goff);
            cp16(sbase + 3 * BUF_B + soff, Wlg + (size_t)n0 * DMODEL + goff);
        }
    };

    float acc[4][4][4] = {};

    load_chunk(0, 0);
    CP_COMMIT();

    for (int c = 0; c < NC; c++) {
        if (c + 1 < NC) {
            load_chunk(c + 1, (c + 1) & 1);
            CP_COMMIT();
            CP_WAIT(1);
        } else {
            CP_WAIT(0);
        }
        __syncthreads();

        const uint32_t sbase = smb + (c & 1) * STG_B;
        const uint32_t aHi = sbase;
        const uint32_t bHi = sbase + 2 * BUF_B;

#pragma unroll
        for (int ks = 0; ks < 2; ks++) {
            const int kk = ks * 16;
            uint32_t ah[4][4], al[4][4], bh[8], bl[8];
#pragma unroll
            for (int mf = 0; mf < 4; mf++) {
                uint32_t idx = (uint32_t)((wm * 64 + mf * 16) * PITCH + kk + laneA) * 2;
                ldsm4(ah[mf], aHi + idx);
                ldsm4(al[mf], aHi + BUF_B + idx);
            }
#pragma unroll
            for (int nf2 = 0; nf2 < 2; nf2++) {
                uint32_t idx = (uint32_t)((wn * 32 + nf2 * 16) * PITCH + kk + laneB) * 2;
                ldsm4(bh + nf2 * 4, bHi + idx);
                ldsm4(bl + nf2 * 4, bHi + BUF_B + idx);
            }
#pragma unroll
            for (int mf = 0; mf < 4; mf++)
#pragma unroll
                for (int nf = 0; nf < 4; nf++) {
                    uint32_t b0h = bh[(nf >> 1) * 4 + (nf & 1) * 2];
                    uint32_t b1h = bh[(nf >> 1) * 4 + (nf & 1) * 2 + 1];
                    uint32_t b0l = bl[(nf >> 1) * 4 + (nf & 1) * 2];
                    uint32_t b1l = bl[(nf >> 1) * 4 + (nf & 1) * 2 + 1];
                    mma16816(acc[mf][nf], ah[mf], b0h, b1h);
                    mma16816(acc[mf][nf], ah[mf], b0l, b1l);
                    mma16816(acc[mf][nf], al[mf], b0h, b1h);
                }
        }
        __syncthreads();
    }

    // epilogue: C frag -> global (+bias), optional head-split remap
#pragma unroll
    for (int mf = 0; mf < 4; mf++) {
#pragma unroll
        for (int nf = 0; nf < 4; nf++) {
            int m = m0 + wm * 64 + mf * 16 + (lane >> 2);
            int n = n0 + wn * 32 + nf * 8 + (lane & 3) * 2;
            float bx = bias[n], by = bias[n + 1];
#pragma unroll
            for (int half = 0; half < 2; half++) {
                int mm = m + half * 8;
                float2 v;
                v.x = acc[mf][nf][half * 2 + 0] + bx;
                v.y = acc[mf][nf][half * 2 + 1] + by;
                float* dst;
                if (remap) {
                    int b = mm >> 11, s = mm & (S_LEN - 1);
                    int h = n >> 6, d = n & (DK - 1);
                    dst = C + (((size_t)(b * NHEAD + h) * S_LEN + s) * DK + d);
                } else {
                    dst = C + (size_t)mm * DMODEL + n;
                }
                *(float2*)dst = v;
            }
        }
    }
}

// ---------------- causal flash attention (verified R1 version) ---------
__global__ __launch_bounds__(256) void flash_attn(
    const float* __restrict__ Qg, const float* __restrict__ Kg,
    const float* __restrict__ Vg, float* __restrict__ Ctx)
{
    __shared__ float Qs[64][65];
    __shared__ float Ks[64][65];
    __shared__ float Vs[64][64];
    __shared__ float Ps[64][65];

    const int tid = threadIdx.x;
    const int tx = tid & 15, ty = tid >> 4;
    const int qt = blockIdx.x;
    const int bh = blockIdx.y;

    const float* Qp = Qg + (size_t)bh * S_LEN * DK;
    const float* Kp = Kg + (size_t)bh * S_LEN * DK;
    const float* Vp = Vg + (size_t)bh * S_LEN * DK;

#pragma unroll
    for (int r = 0; r < 4; r++) {
        int f = tid + (r << 8);
        int row = f >> 4;
        int c4 = (f & 15) << 2;
        float4 v = *(const float4*)(Qp + (size_t)(qt * 64 + row) * DK + c4);
        Qs[row][c4 + 0] = v.x; Qs[row][c4 + 1] = v.y;
        Qs[row][c4 + 2] = v.z; Qs[row][c4 + 3] = v.w;
    }

    float m_i[4], l_i[4], o[4][4];
#pragma unroll
    for (int i = 0; i < 4; i++) {
        m_i[i] = -1e30f; l_i[i] = 0.0f;
#pragma unroll
        for (int j = 0; j < 4; j++) o[i][j] = 0.0f;
    }

    for (int kt = 0; kt <= qt; kt++) {
#pragma unroll
        for (int r = 0; r < 4; r++) {
            int f = tid + (r << 8);
            int row = f >> 4;
            int c4 = (f & 15) << 2;
            float4 vk = *(const float4*)(Kp + (size_t)(kt * 64 + row) * DK + c4);
            Ks[row][c4 + 0] = vk.x; Ks[row][c4 + 1] = vk.y;
            Ks[row][c4 + 2] = vk.z; Ks[row][c4 + 3] = vk.w;
            float4 vv = *(const float4*)(Vp + (size_t)(kt * 64 + row) * DK + c4);
            *(float4*)&Vs[row][c4] = vv;
        }
        __syncthreads();

        float s[4][4] = {};
#pragma unroll 16
        for (int d = 0; d < 64; d++) {
            float a[4], b[4];
#pragma unroll
            for (int i = 0; i < 4; i++) a[i] = Qs[(ty << 2) + i][d];
#pragma unroll
            for (int j = 0; j < 4; j++) b[j] = Ks[(tx << 2) + j][d];
#pragma unroll
            for (int i = 0; i < 4; i++)
#pragma unroll
                for (int j = 0; j < 4; j++)
                    s[i][j] = fmaf(a[i], b[j], s[i][j]);
        }

        const float scale = 0.125f;
        if (kt == qt) {
#pragma unroll
            for (int i = 0; i < 4; i++)
#pragma unroll
                for (int j = 0; j < 4; j++)
                    s[i][j] = ((tx << 2) + j > (ty << 2) + i) ? -1e30f : s[i][j] * scale;
        } else {
#pragma unroll
            for (int i = 0; i < 4; i++)
#pragma unroll
                for (int j = 0; j < 4; j++)
                    s[i][j] *= scale;
        }

#pragma unroll
        for (int i = 0; i < 4; i++) {
            float mx = fmaxf(fmaxf(s[i][0], s[i][1]), fmaxf(s[i][2], s[i][3]));
#pragma unroll
            for (int off = 8; off >= 1; off >>= 1)
                mx = fmaxf(mx, __shfl_xor_sync(0xffffffffu, mx, off, 16));
            float mnew = fmaxf(m_i[i], mx);
            float corr = __expf(m_i[i] - mnew);
            float rs = 0.0f;
#pragma unroll
            for (int j = 0; j < 4; j++) {
                float p = __expf(s[i][j] - mnew);
                Ps[(ty << 2) + i][(tx << 2) + j] = p;
                rs += p;
            }
#pragma unroll
            for (int off = 8; off >= 1; off >>= 1)
                rs += __shfl_xor_sync(0xffffffffu, rs, off, 16);
            l_i[i] = l_i[i] * corr + rs;
            m_i[i] = mnew;
#pragma unroll
            for (int j = 0; j < 4; j++) o[i][j] *= corr;
        }
        __syncthreads();

#pragma unroll 8
        for (int kv = 0; kv < 64; kv++) {
            float4 v4 = *(const float4*)&Vs[kv][tx << 2];
#pragma unroll
            for (int i = 0; i < 4; i++) {
                float p = Ps[(ty << 2) + i][kv];
                o[i][0] = fmaf(p, v4.x, o[i][0]);
                o[i][1] = fmaf(p, v4.y, o[i][1]);
                o[i][2] = fmaf(p, v4.z, o[i][2]);
                o[i][3] = fmaf(p, v4.w, o[i][3]);
            }
        }
        __syncthreads();
    }

    const int b = bh >> 4, h = bh & 15;
#pragma unroll
    for (int i = 0; i < 4; i++) {
        int qrow = qt * 64 + (ty << 2) + i;
        float inv = 1.0f / l_i[i];
        float4 v;
        v.x = o[i][0] * inv; v.y = o[i][1] * inv;
        v.z = o[i][2] * inv; v.w = o[i][3] * inv;
        *(float4*)(Ctx + ((size_t)(b * S_LEN + qrow)) * DMODEL + h * DK + (tx << 2)) = v;
    }
}

// ===========================================================================
extern "C" void kernel_launch(void* const* d_in, const int* in_sizes, int n_in,
                              void* d_out, int out_size)
{
    const float* query = (const float*)d_in[0];
    const float* key   = (const float*)d_in[1];
    const float* value = (const float*)d_in[2];
    // d_in[3] = causal mask — handled analytically.
    const float* Wq = (const float*)d_in[4];
    const float* bq = (const float*)d_in[5];
    const float* Wk = (const float*)d_in[6];
    const float* bk = (const float*)d_in[7];
    const float* Wv = (const float*)d_in[8];
    const float* bv = (const float*)d_in[9];
    const float* Wo = (const float*)d_in[10];
    const float* bo = (const float*)d_in[11];
    float* out = (float*)d_out;

    float *Qb, *Kb, *Vb, *Cb;
    __half *Ah, *Al, *Wh, *Wl;
    cudaGetSymbolAddress((void**)&Qb, g_Qh);
    cudaGetSymbolAddress((void**)&Kb, g_Kh);
    cudaGetSymbolAddress((void**)&Vb, g_Vh);
    cudaGetSymbolAddress((void**)&Cb, g_Ctx);
    cudaGetSymbolAddress((void**)&Ah, g_Ah);
    cudaGetSymbolAddress((void**)&Al, g_Al);
    cudaGetSymbolAddress((void**)&Wh, g_Wh);
    cudaGetSymbolAddress((void**)&Wl, g_Wl);

    cudaFuncSetAttribute(proj_gemm_mma,
                         cudaFuncAttributeMaxDynamicSharedMemorySize, SMEM_GEMM);

    const int n4A = MTOT * DMODEL / 4;      // 2,097,152
    const int n4W = DMODEL * DMODEL / 4;    // 262,144
    dim3 gg(DMODEL / 128, MTOT / 128);      // (8, 64)

    // Q = query @ Wq^T + bq
    split_f32<<<n4A / 256, 256>>>((const float4*)query, (uint2*)Ah, (uint2*)Al, n4A);
    split_f32<<<n4W / 256, 256>>>((const float4*)Wq, (uint2*)Wh, (uint2*)Wl, n4W);
    proj_gemm_mma<<<gg, 256, SMEM_GEMM>>>(Ah, Al, Wh, Wl, bq, Qb, 1);

    // K
    split_f32<<<n4A / 256, 256>>>((const float4*)key, (uint2*)Ah, (uint2*)Al, n4A);
    split_f32<<<n4W / 256, 256>>>((const float4*)Wk, (uint2*)Wh, (uint2*)Wl, n4W);
    proj_gemm_mma<<<gg, 256, SMEM_GEMM>>>(Ah, Al, Wh, Wl, bk, Kb, 1);

    // V
    split_f32<<<n4A / 256, 256>>>((const float4*)value, (uint2*)Ah, (uint2*)Al, n4A);
    split_f32<<<n4W / 256, 256>>>((const float4*)Wv, (uint2*)Wh, (uint2*)Wl, n4W);
    proj_gemm_mma<<<gg, 256, SMEM_GEMM>>>(Ah, Al, Wh, Wl, bv, Vb, 1);

    // attention
    flash_attn<<<dim3(S_LEN / 64, BATCH * NHEAD), 256>>>(Qb, Kb, Vb, Cb);

    // out = Ctx @ Wo^T + bo
    split_f32<<<n4A / 256, 256>>>((const float4*)Cb, (uint2*)Ah, (uint2*)Al, n4A);
    split_f32<<<n4W / 256, 256>>>((const float4*)Wo, (uint2*)Wh, (uint2*)Wl, n4W);
    proj_gemm_mma<<<gg, 256, SMEM_GEMM>>>(Ah, Al, Wh, Wl, bo, out, 0);
}

// round 4
// speedup vs baseline: 3.6759x; 1.8756x over previous
#include <cuda_runtime.h>
#include <cuda_fp16.h>
#include <cstdint>

#define S_LEN  2048
#define DMODEL 1024
#define NHEAD  16
#define DK     64
#define BATCH  4
#define MTOT   (BATCH * S_LEN)     // 8192

// ---------------- scratch (module-scope device memory) ----------------
__device__ __half g_Qh[BATCH * NHEAD * S_LEN * DK];
__device__ __half g_Ql[BATCH * NHEAD * S_LEN * DK];
__device__ __half g_Kh[BATCH * NHEAD * S_LEN * DK];
__device__ __half g_Kl[BATCH * NHEAD * S_LEN * DK];
__device__ __half g_Vh[BATCH * NHEAD * S_LEN * DK];
__device__ __half g_Vl[BATCH * NHEAD * S_LEN * DK];
__device__ __half g_Ah[MTOT * DMODEL];
__device__ __half g_Al[MTOT * DMODEL];
__device__ __half g_Wh[DMODEL * DMODEL];
__device__ __half g_Wl[DMODEL * DMODEL];

// ---------------- PTX helpers (baseline PTX only) ----------------------
__device__ __forceinline__ uint32_t cvta_smem(const void* p) {
    uint32_t a;
    asm("{ .reg .u64 t; cvta.to.shared.u64 t, %1; cvt.u32.u64 %0, t; }"
        : "=r"(a) : "l"(p));
    return a;
}
__device__ __forceinline__ void cp16(uint32_t dst, const void* src) {
    asm volatile("cp.async.cg.shared.global [%0], [%1], 16;"
                 :: "r"(dst), "l"(src));
}
#define CP_COMMIT() asm volatile("cp.async.commit_group;" ::: "memory")
#define CP_WAIT(n)  asm volatile("cp.async.wait_group %0;" :: "n"(n) : "memory")

__device__ __forceinline__ void ldsm4(uint32_t* r, uint32_t addr) {
    asm volatile("ldmatrix.sync.aligned.m8n8.x4.shared.b16 {%0,%1,%2,%3}, [%4];"
                 : "=r"(r[0]), "=r"(r[1]), "=r"(r[2]), "=r"(r[3]) : "r"(addr));
}
__device__ __forceinline__ void ldsm4t(uint32_t* r, uint32_t addr) {
    asm volatile("ldmatrix.sync.aligned.m8n8.x4.trans.shared.b16 {%0,%1,%2,%3}, [%4];"
                 : "=r"(r[0]), "=r"(r[1]), "=r"(r[2]), "=r"(r[3]) : "r"(addr));
}
__device__ __forceinline__ void mma16816(float* d, const uint32_t* a,
                                         uint32_t b0, uint32_t b1) {
    asm volatile(
        "mma.sync.aligned.m16n8k16.row.col.f32.f16.f16.f32 "
        "{%0,%1,%2,%3}, {%4,%5,%6,%7}, {%8,%9}, {%0,%1,%2,%3};"
        : "+f"(d[0]), "+f"(d[1]), "+f"(d[2]), "+f"(d[3])
        : "r"(a[0]), "r"(a[1]), "r"(a[2]), "r"(a[3]), "r"(b0), "r"(b1));
}
__device__ __forceinline__ float ex2(float x) {
    float y;
    asm("ex2.approx.f32 %0, %1;" : "=f"(y) : "f"(x));
    return y;
}

// ---------------- fp32 -> split f16 (hi/lo) ----------------------------
__global__ __launch_bounds__(256) void split_f32(
    const float4* __restrict__ x, uint2* __restrict__ hi,
    uint2* __restrict__ lo, int n4)
{
    int i = blockIdx.x * 256 + threadIdx.x;
    if (i >= n4) return;
    float4 v = x[i];
    __half h0 = __float2half_rn(v.x), h1 = __float2half_rn(v.y);
    __half h2 = __float2half_rn(v.z), h3 = __float2half_rn(v.w);
    __half l0 = __float2half_rn(v.x - __half2float(h0));
    __half l1 = __float2half_rn(v.y - __half2float(h1));
    __half l2 = __float2half_rn(v.z - __half2float(h2));
    __half l3 = __float2half_rn(v.w - __half2float(h3));
    uint2 H, L;
    H.x = (uint32_t)__half_as_ushort(h0) | ((uint32_t)__half_as_ushort(h1) << 16);
    H.y = (uint32_t)__half_as_ushort(h2) | ((uint32_t)__half_as_ushort(h3) << 16);
    L.x = (uint32_t)__half_as_ushort(l0) | ((uint32_t)__half_as_ushort(l1) << 16);
    L.y = (uint32_t)__half_as_ushort(l2) | ((uint32_t)__half_as_ushort(l3) << 16);
    hi[i] = H;
    lo[i] = L;
}

// ---------------- HMMA projection GEMM ---------------------------------
// C = A[M,1024] @ W[1024,1024]^T + bias.  A/W pre-split f16 hi/lo.
// remap=1: write split f16 hi/lo into [B,H,S,DK]; remap=0: fp32 [M,1024].
#define KCH   32
#define NC    (DMODEL / KCH)   // 32
#define PITCH 40               // halves per smem row (80B)
#define BUF_B (128 * PITCH * 2)       // 10240
#define STG_B (4 * BUF_B)             // 40960
#define SMEM_GEMM (2 * STG_B)         // 81920

__global__ __launch_bounds__(256) void proj_gemm_mma(
    const __half* __restrict__ Ahg, const __half* __restrict__ Alg,
    const __half* __restrict__ Whg, const __half* __restrict__ Wlg,
    const float* __restrict__ bias, float* __restrict__ Cf,
    __half* __restrict__ Ch, __half* __restrict__ Cl, int remap)
{
    extern __shared__ char sm[];
    const uint32_t smb = cvta_smem(sm);
    const int tid = threadIdx.x;
    const int wid = tid >> 5, lane = tid & 31;
    const int wm = wid & 1;
    const int wn = wid >> 1;
    const int m0 = blockIdx.y * 128;
    const int n0 = blockIdx.x * 128;

    const int laneA = ((lane & 15)) * PITCH + ((lane >> 4) & 1) * 8;
    const int laneB = ((lane & 7) + ((lane >> 4) & 1) * 8) * PITCH + ((lane >> 3) & 1) * 8;

    const int ldr = tid >> 2;
    const int ldq = tid & 3;

    auto load_chunk = [&](int c, int stage) {
        const uint32_t sbase = smb + stage * STG_B;
#pragma unroll
        for (int i = 0; i < 2; i++) {
            int row = ldr + i * 64;
            uint32_t soff = (uint32_t)row * 80u + (uint32_t)ldq * 16u;
            size_t goff = (size_t)row * DMODEL + c * KCH + ldq * 8;
            cp16(sbase + 0 * BUF_B + soff, Ahg + (size_t)m0 * DMODEL + goff);
            cp16(sbase + 1 * BUF_B + soff, Alg + (size_t)m0 * DMODEL + goff);
            cp16(sbase + 2 * BUF_B + soff, Whg + (size_t)n0 * DMODEL + goff);
            cp16(sbase + 3 * BUF_B + soff, Wlg + (size_t)n0 * DMODEL + goff);
        }
    };

    float acc[4][4][4] = {};

    load_chunk(0, 0);
    CP_COMMIT();

    for (int c = 0; c < NC; c++) {
        if (c + 1 < NC) {
            load_chunk(c + 1, (c + 1) & 1);
            CP_COMMIT();
            CP_WAIT(1);
        } else {
            CP_WAIT(0);
        }
        __syncthreads();

        const uint32_t sbase = smb + (c & 1) * STG_B;
        const uint32_t aHi = sbase;
        const uint32_t bHi = sbase + 2 * BUF_B;

#pragma unroll
        for (int ks = 0; ks < 2; ks++) {
            const int kk = ks * 16;
            uint32_t ah[4][4], al[4][4], bh[8], bl[8];
#pragma unroll
            for (int mf = 0; mf < 4; mf++) {
                uint32_t idx = (uint32_t)((wm * 64 + mf * 16) * PITCH + kk + laneA) * 2;
                ldsm4(ah[mf], aHi + idx);
                ldsm4(al[mf], aHi + BUF_B + idx);
            }
#pragma unroll
            for (int nf2 = 0; nf2 < 2; nf2++) {
                uint32_t idx = (uint32_t)((wn * 32 + nf2 * 16) * PITCH + kk + laneB) * 2;
                ldsm4(bh + nf2 * 4, bHi + idx);
                ldsm4(bl + nf2 * 4, bHi + BUF_B + idx);
            }
            // pass-major: 16 independent accumulators between reuses
#pragma unroll
            for (int mf = 0; mf < 4; mf++)
#pragma unroll
                for (int nf = 0; nf < 4; nf++) {
                    int bi = (nf >> 1) * 4 + (nf & 1) * 2;
                    mma16816(acc[mf][nf], ah[mf], bh[bi], bh[bi + 1]);
                }
#pragma unroll
            for (int mf = 0; mf < 4; mf++)
#pragma unroll
                for (int nf = 0; nf < 4; nf++) {
                    int bi = (nf >> 1) * 4 + (nf & 1) * 2;
                    mma16816(acc[mf][nf], ah[mf], bl[bi], bl[bi + 1]);
                }
#pragma unroll
            for (int mf = 0; mf < 4; mf++)
#pragma unroll
                for (int nf = 0; nf < 4; nf++) {
                    int bi = (nf >> 1) * 4 + (nf & 1) * 2;
                    mma16816(acc[mf][nf], al[mf], bh[bi], bh[bi + 1]);
                }
        }
        __syncthreads();
    }

    // epilogue
#pragma unroll
    for (int mf = 0; mf < 4; mf++) {
#pragma unroll
        for (int nf = 0; nf < 4; nf++) {
            int m = m0 + wm * 64 + mf * 16 + (lane >> 2);
            int n = n0 + wn * 32 + nf * 8 + (lane & 3) * 2;
            float bx = bias[n], by = bias[n + 1];
#pragma unroll
            for (int hh = 0; hh < 2; hh++) {
                int mm = m + hh * 8;
                float vx = acc[mf][nf][hh * 2 + 0] + bx;
                float vy = acc[mf][nf][hh * 2 + 1] + by;
                if (remap) {
                    int b = mm >> 11, s = mm & (S_LEN - 1);
                    int h = n >> 6, d = n & (DK - 1);
                    size_t idx = ((size_t)((b << 4) + h) * S_LEN + s) * DK + d;
                    __half2 hi2 = __floats2half2_rn(vx, vy);
                    float2 hf = __half22float2(hi2);
                    __half2 lo2 = __floats2half2_rn(vx - hf.x, vy - hf.y);
                    *(__half2*)(Ch + idx) = hi2;
                    *(__half2*)(Cl + idx) = lo2;
                } else {
                    float2 v; v.x = vx; v.y = vy;
                    *(float2*)(Cf + (size_t)mm * DMODEL + n) = v;
                }
            }
        }
    }
}

// ---------------- HMMA causal flash attention ---------------------------
// BQ=128 (8 warps x m16), BKV=64, d=64. 3-pass split-f16 QK and PV.
// Output: context split f16 hi/lo into [B,S,1024] (g_Ah/g_Al).
#define FPITCH 72                          // halves
#define QBUF   (128 * FPITCH * 2)          // 18432 B
#define KVBUF  (64 * FPITCH * 2)           // 9216 B
#define OFF_QH 0
#define OFF_QL QBUF
#define OFF_KV (2 * QBUF)                  // 36864
#define KVSTG  (4 * KVBUF)                 // 36864
#define SMEM_FLASH (OFF_KV + 2 * KVSTG)    // 110592

__global__ __launch_bounds__(256, 1) void flash_mma(
    const __half* __restrict__ Qh, const __half* __restrict__ Ql,
    const __half* __restrict__ Kh, const __half* __restrict__ Kl,
    const __half* __restrict__ Vh, const __half* __restrict__ Vl,
    __half* __restrict__ Oh, __half* __restrict__ Ol)
{
    extern __shared__ char sm[];
    const uint32_t smb = cvta_smem(sm);
    const int tid = threadIdx.x;
    const int w = tid >> 5, lane = tid & 31;
    const int qi = blockIdx.x;            // 0..15 (q0 = qi*128)
    const int bh = blockIdx.y;            // 0..63
    const int q0 = qi * 128;

    const size_t seqbase = (size_t)bh * S_LEN * DK;

    // loaders
    const int ldrow = tid >> 3;           // 0..31
    const int ldq = tid & 7;              // 16B quad (d: quad*8)
    auto load_Q = [&]() {
#pragma unroll
        for (int i = 0; i < 4; i++) {
            int r = ldrow + i * 32;       // 0..127
            uint32_t so = (uint32_t)r * (FPITCH * 2) + (uint32_t)ldq * 16u;
            size_t g = seqbase + (size_t)(q0 + r) * DK + ldq * 8;
            cp16(smb + OFF_QH + so, Qh + g);
            cp16(smb + OFF_QL + so, Ql + g);
        }
    };
    auto load_tile = [&](int kt, int stage) {
        const uint32_t sb = smb + OFF_KV + stage * KVSTG;
#pragma unroll
        for (int i = 0; i < 2; i++) {
            int r = ldrow + i * 32;       // 0..63
            uint32_t so = (uint32_t)r * (FPITCH * 2) + (uint32_t)ldq * 16u;
            size_t g = seqbase + (size_t)(kt * 64 + r) * DK + ldq * 8;
            cp16(sb + 0 * KVBUF + so, Kh + g);
            cp16(sb + 1 * KVBUF + so, Kl + g);
            cp16(sb + 2 * KVBUF + so, Vh + g);
            cp16(sb + 3 * KVBUF + so, Vl + g);
        }
    };

    load_Q();
    load_tile(0, 0);
    CP_COMMIT();
    CP_WAIT(0);
    __syncthreads();

    // Q fragments (A, m16k16 per ks)
    const int laneA = (lane & 15) * FPITCH + ((lane >> 4) & 1) * 8;
    uint32_t qhf[4][4], qlf[4][4];
#pragma unroll
    for (int ks = 0; ks < 4; ks++) {
        uint32_t a = smb + OFF_QH + (uint32_t)((w * 16) * FPITCH + ks * 16 + laneA) * 2;
        ldsm4(qhf[ks], a);
        ldsm4(qlf[ks], a + QBUF);
    }

    // lane offsets for K (B, non-trans) and V (B, trans)
    const int laneB = ((lane & 7) + ((lane >> 4) & 1) * 8) * FPITCH + ((lane >> 3) & 1) * 8;
    const int laneV = ((lane & 7) + ((lane >> 3) & 1) * 8) * FPITCH + ((lane >> 4) & 1) * 8;

    float oacc[8][4];
#pragma unroll
    for (int nf = 0; nf < 8; nf++)
#pragma unroll
        for (int j = 0; j < 4; j++) oacc[nf][j] = 0.0f;
    float m0r = -1e30f, m1r = -1e30f, l0r = 0.0f, l1r = 0.0f;

    const int T = 2 * qi + 2;
    const int ktmax_w = 2 * qi + (w >> 2);
    const float cs = 0.18033688f;         // (1/8) * log2(e)
    const int rbase = q0 + w * 16 + (lane >> 2);
    const int cbase = (lane & 3) * 2;

    for (int kt = 0; kt < T; kt++) {
        if (kt + 1 < T) {
            load_tile(kt + 1, (kt + 1) & 1);
            CP_COMMIT();
            CP_WAIT(1);
        } else {
            CP_WAIT(0);
        }
        __syncthreads();

        if (kt <= ktmax_w) {
            const uint32_t kvb = smb + OFF_KV + (kt & 1) * KVSTG;

            // ---- S = Q K^T (3-pass) ----
            float sacc[8][4];
#pragma unroll
            for (int nf = 0; nf < 8; nf++)
#pragma unroll
                for (int j = 0; j < 4; j++) sacc[nf][j] = 0.0f;

#pragma unroll
            for (int ks = 0; ks < 4; ks++) {
                uint32_t kb[16], kbl[16];
#pragma unroll
                for (int nb = 0; nb < 4; nb++) {
                    uint32_t a = kvb + (uint32_t)((nb * 16) * FPITCH + ks * 16 + laneB) * 2;
                    ldsm4(kb + nb * 4, a);
                    ldsm4(kbl + nb * 4, a + KVBUF);
                }
#pragma unroll
                for (int nf = 0; nf < 8; nf++) {
                    int bi = (nf >> 1) * 4 + (nf & 1) * 2;
                    mma16816(sacc[nf], qhf[ks], kb[bi], kb[bi + 1]);
                }
#pragma unroll
                for (int nf = 0; nf < 8; nf++) {
                    int bi = (nf >> 1) * 4 + (nf & 1) * 2;
                    mma16816(sacc[nf], qhf[ks], kbl[bi], kbl[bi + 1]);
                }
#pragma unroll
                for (int nf = 0; nf < 8; nf++) {
                    int bi = (nf >> 1) * 4 + (nf & 1) * 2;
                    mma16816(sacc[nf], qlf[ks], kb[bi], kb[bi + 1]);
                }
            }

            // ---- scale (+ causal mask on diagonal tiles) ----
            const bool need_mask = (kt * 64 + 63 > q0 + w * 16);
            if (need_mask) {
#pragma unroll
                for (int nf = 0; nf < 8; nf++) {
#pragma unroll
                    for (int j = 0; j < 4; j++) {
                        int col = kt * 64 + nf * 8 + cbase + (j & 1);
                        int row = rbase + ((j >> 1) << 3);
                        sacc[nf][j] = (col <= row) ? sacc[nf][j] * cs : -1e30f;
                    }
                }
            } else {
#pragma unroll
                for (int nf = 0; nf < 8; nf++)
#pragma unroll
                    for (int j = 0; j < 4; j++) sacc[nf][j] *= cs;
            }

            // ---- online softmax (base-2) ----
            float mx0 = -1e30f, mx1 = -1e30f;
#pragma unroll
            for (int nf = 0; nf < 8; nf++) {
                mx0 = fmaxf(mx0, fmaxf(sacc[nf][0], sacc[nf][1]));
                mx1 = fmaxf(mx1, fmaxf(sacc[nf][2], sacc[nf][3]));
            }
            mx0 = fmaxf(mx0, __shfl_xor_sync(0xffffffffu, mx0, 1));
            mx0 = fmaxf(mx0, __shfl_xor_sync(0xffffffffu, mx0, 2));
            mx1 = fmaxf(mx1, __shfl_xor_sync(0xffffffffu, mx1, 1));
            mx1 = fmaxf(mx1, __shfl_xor_sync(0xffffffffu, mx1, 2));

            float mn0 = fmaxf(m0r, mx0), mn1 = fmaxf(m1r, mx1);
            float c0 = ex2(m0r - mn0), c1 = ex2(m1r - mn1);
            m0r = mn0; m1r = mn1;

            uint32_t pHa[8], pHb[8], pLa[8], pLb[8];
            float ls0 = 0.0f, ls1 = 0.0f;
#pragma unroll
            for (int nf = 0; nf < 8; nf++) {
                float p0 = ex2(sacc[nf][0] - mn0);
                float p1 = ex2(sacc[nf][1] - mn0);
                float p2 = ex2(sacc[nf][2] - mn1);
                float p3 = ex2(sacc[nf][3] - mn1);
                ls0 += p0 + p1;
                ls1 += p2 + p3;
                __half2 h01 = __floats2half2_rn(p0, p1);
                float2 f01 = __half22float2(h01);
                __half2 l01 = __floats2half2_rn(p0 - f01.x, p1 - f01.y);
                __half2 h23 = __floats2half2_rn(p2, p3);
                float2 f23 = __half22float2(h23);
                __half2 l23 = __floats2half2_rn(p2 - f23.x, p3 - f23.y);
                pHa[nf] = *(uint32_t*)&h01;
                pLa[nf] = *(uint32_t*)&l01;
                pHb[nf] = *(uint32_t*)&h23;
                pLb[nf] = *(uint32_t*)&l23;
            }
            ls0 += __shfl_xor_sync(0xffffffffu, ls0, 1);
            ls0 += __shfl_xor_sync(0xffffffffu, ls0, 2);
            ls1 += __shfl_xor_sync(0xffffffffu, ls1, 1);
            ls1 += __shfl_xor_sync(0xffffffffu, ls1, 2);
            l0r = l0r * c0 + ls0;
            l1r = l1r * c1 + ls1;
#pragma unroll
            for (int nf = 0; nf < 8; nf++) {
                oacc[nf][0] *= c0; oacc[nf][1] *= c0;
                oacc[nf][2] *= c1; oacc[nf][3] *= c1;
            }

            // ---- O += P V (3-pass) ----
            const uint32_t vbb = kvb + 2 * KVBUF;
#pragma unroll
            for (int ks = 0; ks < 4; ks++) {
                uint32_t vb[16], vbl[16];
#pragma unroll
                for (int nb = 0; nb < 4; nb++) {
                    uint32_t a = vbb + (uint32_t)((ks * 16) * FPITCH + nb * 16 + laneV) * 2;
                    ldsm4t(vb + nb * 4, a);
                    ldsm4t(vbl + nb * 4, a + KVBUF);
                }
                uint32_t pa[4] = { pHa[2 * ks], pHb[2 * ks], pHa[2 * ks + 1], pHb[2 * ks + 1] };
                uint32_t la[4] = { pLa[2 * ks], pLb[2 * ks], pLa[2 * ks + 1], pLb[2 * ks + 1] };
#pragma unroll
                for (int nf = 0; nf < 8; nf++) {
                    int bi = (nf >> 1) * 4 + (nf & 1) * 2;
                    mma16816(oacc[nf], pa, vb[bi], vb[bi + 1]);
                }
#pragma unroll
                for (int nf = 0; nf < 8; nf++) {
                    int bi = (nf >> 1) * 4 + (nf & 1) * 2;
                    mma16816(oacc[nf], pa, vbl[bi], vbl[bi + 1]);
                }
#pragma unroll
                for (int nf = 0; nf < 8; nf++) {
                    int bi = (nf >> 1) * 4 + (nf & 1) * 2;
                    mma16816(oacc[nf], la, vb[bi], vb[bi + 1]);
                }
            }
        }
        __syncthreads();
    }

    // ---- epilogue: write split context [B,S,1024] ----
    const float inv0 = 1.0f / l0r, inv1 = 1.0f / l1r;
    const int b = bh >> 4, h = bh & 15;
    const int s0 = q0 + w * 16 + (lane >> 2);
#pragma unroll
    for (int nf = 0; nf < 8; nf++) {
        int col = h * DK + nf * 8 + cbase;
#pragma unroll
        for (int hh = 0; hh < 2; hh++) {
            int s = s0 + hh * 8;
            float vx = oacc[nf][hh * 2 + 0] * (hh ? inv1 : inv0);
            float vy = oacc[nf][hh * 2 + 1] * (hh ? inv1 : inv0);
            size_t idx = ((size_t)(b * S_LEN + s)) * DMODEL + col;
            __half2 hi2 = __floats2half2_rn(vx, vy);
            float2 hf = __half22float2(hi2);
            __half2 lo2 = __floats2half2_rn(vx - hf.x, vy - hf.y);
            *(__half2*)(Oh + idx) = hi2;
            *(__half2*)(Ol + idx) = lo2;
        }
    }
}

// ===========================================================================
extern "C" void kernel_launch(void* const* d_in, const int* in_sizes, int n_in,
                              void* d_out, int out_size)
{
    const float* query = (const float*)d_in[0];
    const float* key   = (const float*)d_in[1];
    const float* value = (const float*)d_in[2];
    // d_in[3] = causal mask — handled analytically.
    const float* Wq = (const float*)d_in[4];
    const float* bq = (const float*)d_in[5];
    const float* Wk = (const float*)d_in[6];
    const float* bk = (const float*)d_in[7];
    const float* Wv = (const float*)d_in[8];
    const float* bv = (const float*)d_in[9];
    const float* Wo = (const float*)d_in[10];
    const float* bo = (const float*)d_in[11];
    float* out = (float*)d_out;

    __half *Qh, *Ql, *Kh, *Kl, *Vh, *Vl, *Ah, *Al, *Wh, *Wl;
    cudaGetSymbolAddress((void**)&Qh, g_Qh);
    cudaGetSymbolAddress((void**)&Ql, g_Ql);
    cudaGetSymbolAddress((void**)&Kh, g_Kh);
    cudaGetSymbolAddress((void**)&Kl, g_Kl);
    cudaGetSymbolAddress((void**)&Vh, g_Vh);
    cudaGetSymbolAddress((void**)&Vl, g_Vl);
    cudaGetSymbolAddress((void**)&Ah, g_Ah);
    cudaGetSymbolAddress((void**)&Al, g_Al);
    cudaGetSymbolAddress((void**)&Wh, g_Wh);
    cudaGetSymbolAddress((void**)&Wl, g_Wl);

    cudaFuncSetAttribute(proj_gemm_mma,
                         cudaFuncAttributeMaxDynamicSharedMemorySize, SMEM_GEMM);
    cudaFuncSetAttribute(flash_mma,
                         cudaFuncAttributeMaxDynamicSharedMemorySize, SMEM_FLASH);

    const int n4A = MTOT * DMODEL / 4;
    const int n4W = DMODEL * DMODEL / 4;
    dim3 gg(DMODEL / 128, MTOT / 128);      // (8, 64)

    // Q
    split_f32<<<n4A / 256, 256>>>((const float4*)query, (uint2*)Ah, (uint2*)Al, n4A);
    split_f32<<<n4W / 256, 256>>>((const float4*)Wq, (uint2*)Wh, (uint2*)Wl, n4W);
    proj_gemm_mma<<<gg, 256, SMEM_GEMM>>>(Ah, Al, Wh, Wl, bq, nullptr, Qh, Ql, 1);
    // K
    split_f32<<<n4A / 256, 256>>>((const float4*)key, (uint2*)Ah, (uint2*)Al, n4A);
    split_f32<<<n4W / 256, 256>>>((const float4*)Wk, (uint2*)Wh, (uint2*)Wl, n4W);
    proj_gemm_mma<<<gg, 256, SMEM_GEMM>>>(Ah, Al, Wh, Wl, bk, nullptr, Kh, Kl, 1);
    // V
    split_f32<<<n4A / 256, 256>>>((const float4*)value, (uint2*)Ah, (uint2*)Al, n4A);
    split_f32<<<n4W / 256, 256>>>((const float4*)Wv, (uint2*)Wh, (uint2*)Wl, n4W);
    proj_gemm_mma<<<gg, 256, SMEM_GEMM>>>(Ah, Al, Wh, Wl, bv, nullptr, Vh, Vl, 1);

    // attention: writes split context into Ah/Al
    flash_mma<<<dim3(16, BATCH * NHEAD), 256, SMEM_FLASH>>>(Qh, Ql, Kh, Kl, Vh, Vl, Ah, Al);

    // out = Ctx @ Wo^T + bo (fp32 out)
    split_f32<<<n4W / 256, 256>>>((const float4*)Wo, (uint2*)Wh, (uint2*)Wl, n4W);
    proj_gemm_mma<<<gg, 256, SMEM_GEMM>>>(Ah, Al, Wh, Wl, bo, out, nullptr, nullptr, 0);
}

// round 5
// speedup vs baseline: 3.9349x; 1.0705x over previous
#include <cuda_runtime.h>
#include <cuda_fp16.h>
#include <cstdint>

#define S_LEN  2048
#define DMODEL 1024
#define NHEAD  16
#define DK     64
#define BATCH  4
#define MTOT   (BATCH * S_LEN)     // 8192

// ---------------- scratch (module-scope device memory) ----------------
__device__ __half g_Qh[BATCH * NHEAD * S_LEN * DK];
__device__ __half g_Ql[BATCH * NHEAD * S_LEN * DK];
__device__ __half g_Kh[BATCH * NHEAD * S_LEN * DK];
__device__ __half g_Kl[BATCH * NHEAD * S_LEN * DK];
__device__ __half g_Vh[BATCH * NHEAD * S_LEN * DK];
__device__ __half g_Vl[BATCH * NHEAD * S_LEN * DK];
__device__ __half g_Ah[MTOT * DMODEL];
__device__ __half g_Al[MTOT * DMODEL];
__device__ __half g_Wh[DMODEL * DMODEL];
__device__ __half g_Wl[DMODEL * DMODEL];

// ---------------- PTX helpers (baseline PTX only) ----------------------
__device__ __forceinline__ uint32_t cvta_smem(const void* p) {
    uint32_t a;
    asm("{ .reg .u64 t; cvta.to.shared.u64 t, %1; cvt.u32.u64 %0, t; }"
        : "=r"(a) : "l"(p));
    return a;
}
__device__ __forceinline__ void cp16(uint32_t dst, const void* src) {
    asm volatile("cp.async.cg.shared.global [%0], [%1], 16;"
                 :: "r"(dst), "l"(src));
}
#define CP_COMMIT() asm volatile("cp.async.commit_group;" ::: "memory")
#define CP_WAIT(n)  asm volatile("cp.async.wait_group %0;" :: "n"(n) : "memory")

__device__ __forceinline__ void ldsm4(uint32_t* r, uint32_t addr) {
    asm volatile("ldmatrix.sync.aligned.m8n8.x4.shared.b16 {%0,%1,%2,%3}, [%4];"
                 : "=r"(r[0]), "=r"(r[1]), "=r"(r[2]), "=r"(r[3]) : "r"(addr));
}
__device__ __forceinline__ void ldsm4t(uint32_t* r, uint32_t addr) {
    asm volatile("ldmatrix.sync.aligned.m8n8.x4.trans.shared.b16 {%0,%1,%2,%3}, [%4];"
                 : "=r"(r[0]), "=r"(r[1]), "=r"(r[2]), "=r"(r[3]) : "r"(addr));
}
__device__ __forceinline__ void mma16816(float* d, const uint32_t* a,
                                         uint32_t b0, uint32_t b1) {
    asm volatile(
        "mma.sync.aligned.m16n8k16.row.col.f32.f16.f16.f32 "
        "{%0,%1,%2,%3}, {%4,%5,%6,%7}, {%8,%9}, {%0,%1,%2,%3};"
        : "+f"(d[0]), "+f"(d[1]), "+f"(d[2]), "+f"(d[3])
        : "r"(a[0]), "r"(a[1]), "r"(a[2]), "r"(a[3]), "r"(b0), "r"(b1));
}
__device__ __forceinline__ float ex2(float x) {
    float y;
    asm("ex2.approx.f32 %0, %1;" : "=f"(y) : "f"(x));
    return y;
}

// ---------------- fp32 -> split f16 (hi/lo; lo optional) ---------------
__global__ __launch_bounds__(256) void split_f32(
    const float4* __restrict__ x, uint2* __restrict__ hi,
    uint2* __restrict__ lo, int n4)
{
    int i = blockIdx.x * 256 + threadIdx.x;
    if (i >= n4) return;
    float4 v = x[i];
    __half h0 = __float2half_rn(v.x), h1 = __float2half_rn(v.y);
    __half h2 = __float2half_rn(v.z), h3 = __float2half_rn(v.w);
    uint2 H;
    H.x = (uint32_t)__half_as_ushort(h0) | ((uint32_t)__half_as_ushort(h1) << 16);
    H.y = (uint32_t)__half_as_ushort(h2) | ((uint32_t)__half_as_ushort(h3) << 16);
    hi[i] = H;
    if (lo) {
        __half l0 = __float2half_rn(v.x - __half2float(h0));
        __half l1 = __float2half_rn(v.y - __half2float(h1));
        __half l2 = __float2half_rn(v.z - __half2float(h2));
        __half l3 = __float2half_rn(v.w - __half2float(h3));
        uint2 L;
        L.x = (uint32_t)__half_as_ushort(l0) | ((uint32_t)__half_as_ushort(l1) << 16);
        L.y = (uint32_t)__half_as_ushort(l2) | ((uint32_t)__half_as_ushort(l3) << 16);
        lo[i] = L;
    }
}

// ---------------- HMMA projection GEMM ---------------------------------
// C = A[M,1024] @ W[1024,1024]^T + bias.  A/W pre-split f16 hi/lo.
// NPASS=3: Ah*Wh + Ah*Wl + Al*Wh.  NPASS=2: Ah*Wh + Ah*Wl (A_lo not loaded).
// remap=1: write split f16 hi/lo into [B,H,S,DK]; remap=0: fp32 [M,1024].
#define KCH   32
#define NC    (DMODEL / KCH)   // 32
#define PITCH 40               // halves per smem row (80B)
#define BUF_B (128 * PITCH * 2)       // 10240
#define STG_B (4 * BUF_B)             // 40960 (A_lo slot present; unused if NPASS=2)
#define SMEM_GEMM (3 * STG_B)         // 122880

template <int NPASS>
__global__ __launch_bounds__(256) void proj_gemm_mma(
    const __half* __restrict__ Ahg, const __half* __restrict__ Alg,
    const __half* __restrict__ Whg, const __half* __restrict__ Wlg,
    const float* __restrict__ bias, float* __restrict__ Cf,
    __half* __restrict__ Ch, __half* __restrict__ Cl, int remap)
{
    extern __shared__ char sm[];
    const uint32_t smb = cvta_smem(sm);
    const int tid = threadIdx.x;
    const int wid = tid >> 5, lane = tid & 31;
    const int wm = wid & 1;
    const int wn = wid >> 1;
    const int m0 = blockIdx.y * 128;
    const int n0 = blockIdx.x * 128;

    const int laneA = ((lane & 15)) * PITCH + ((lane >> 4) & 1) * 8;
    const int laneB = ((lane & 7) + ((lane >> 4) & 1) * 8) * PITCH + ((lane >> 3) & 1) * 8;

    const int ldr = tid >> 2;
    const int ldq = tid & 3;

    auto load_chunk = [&](int c, int stage) {
        const uint32_t sbase = smb + stage * STG_B;
#pragma unroll
        for (int i = 0; i < 2; i++) {
            int row = ldr + i * 64;
            uint32_t soff = (uint32_t)row * 80u + (uint32_t)ldq * 16u;
            size_t goff = (size_t)row * DMODEL + c * KCH + ldq * 8;
            cp16(sbase + 0 * BUF_B + soff, Ahg + (size_t)m0 * DMODEL + goff);
            if (NPASS == 3)
                cp16(sbase + 1 * BUF_B + soff, Alg + (size_t)m0 * DMODEL + goff);
            cp16(sbase + 2 * BUF_B + soff, Whg + (size_t)n0 * DMODEL + goff);
            cp16(sbase + 3 * BUF_B + soff, Wlg + (size_t)n0 * DMODEL + goff);
        }
    };

    float acc[4][4][4] = {};

    load_chunk(0, 0);
    CP_COMMIT();
    load_chunk(1, 1);
    CP_COMMIT();

    for (int c = 0; c < NC; c++) {
        if (c + 1 < NC) { CP_WAIT(1); } else { CP_WAIT(0); }
        __syncthreads();
        if (c + 2 < NC) {
            int ls = c + 2;
            load_chunk(ls, ls - (ls / 3) * 3);
            CP_COMMIT();
        }

        const uint32_t sbase = smb + (uint32_t)(c - (c / 3) * 3) * STG_B;
        const uint32_t aHi = sbase;
        const uint32_t bHi = sbase + 2 * BUF_B;

#pragma unroll
        for (int ks = 0; ks < 2; ks++) {
            const int kk = ks * 16;
            uint32_t ah[4][4], al[4][4], bh[8], bl[8];
#pragma unroll
            for (int mf = 0; mf < 4; mf++) {
                uint32_t idx = (uint32_t)((wm * 64 + mf * 16) * PITCH + kk + laneA) * 2;
                ldsm4(ah[mf], aHi + idx);
                if (NPASS == 3) ldsm4(al[mf], aHi + BUF_B + idx);
            }
#pragma unroll
            for (int nf2 = 0; nf2 < 2; nf2++) {
                uint32_t idx = (uint32_t)((wn * 32 + nf2 * 16) * PITCH + kk + laneB) * 2;
                ldsm4(bh + nf2 * 4, bHi + idx);
                ldsm4(bl + nf2 * 4, bHi + BUF_B + idx);
            }
            // pass-major: 16 independent accumulators between reuses
#pragma unroll
            for (int mf = 0; mf < 4; mf++)
#pragma unroll
                for (int nf = 0; nf < 4; nf++) {
                    int bi = (nf >> 1) * 4 + (nf & 1) * 2;
                    mma16816(acc[mf][nf], ah[mf], bh[bi], bh[bi + 1]);
                }
#pragma unroll
            for (int mf = 0; mf < 4; mf++)
#pragma unroll
                for (int nf = 0; nf < 4; nf++) {
                    int bi = (nf >> 1) * 4 + (nf & 1) * 2;
                    mma16816(acc[mf][nf], ah[mf], bl[bi], bl[bi + 1]);
                }
            if (NPASS == 3) {
#pragma unroll
                for (int mf = 0; mf < 4; mf++)
#pragma unroll
                    for (int nf = 0; nf < 4; nf++) {
                        int bi = (nf >> 1) * 4 + (nf & 1) * 2;
                        mma16816(acc[mf][nf], al[mf], bh[bi], bh[bi + 1]);
                    }
            }
        }
    }

    // epilogue
#pragma unroll
    for (int mf = 0; mf < 4; mf++) {
#pragma unroll
        for (int nf = 0; nf < 4; nf++) {
            int m = m0 + wm * 64 + mf * 16 + (lane >> 2);
            int n = n0 + wn * 32 + nf * 8 + (lane & 3) * 2;
            float bx = bias[n], by = bias[n + 1];
#pragma unroll
            for (int hh = 0; hh < 2; hh++) {
                int mm = m + hh * 8;
                float vx = acc[mf][nf][hh * 2 + 0] + bx;
                float vy = acc[mf][nf][hh * 2 + 1] + by;
                if (remap) {
                    int b = mm >> 11, s = mm & (S_LEN - 1);
                    int h = n >> 6, d = n & (DK - 1);
                    size_t idx = ((size_t)((b << 4) + h) * S_LEN + s) * DK + d;
                    __half2 hi2 = __floats2half2_rn(vx, vy);
                    float2 hf = __half22float2(hi2);
                    __half2 lo2 = __floats2half2_rn(vx - hf.x, vy - hf.y);
                    *(__half2*)(Ch + idx) = hi2;
                    *(__half2*)(Cl + idx) = lo2;
                } else {
                    float2 v; v.x = vx; v.y = vy;
                    *(float2*)(Cf + (size_t)mm * DMODEL + n) = v;
                }
            }
        }
    }
}

// ---------------- HMMA causal flash attention ---------------------------
// BQ=128 (8 warps x m16), BKV=64, d=64. QK 3-pass, PV 2-pass (P not split).
// 3-stage KV pipeline; heavy q-tiles launch first (reversed blockIdx.x).
#define FPITCH 72                          // halves
#define QBUF   (128 * FPITCH * 2)          // 18432 B
#define KVBUF  (64 * FPITCH * 2)           // 9216 B
#define OFF_QH 0
#define OFF_QL QBUF
#define OFF_KV (2 * QBUF)                  // 36864
#define KVSTG  (4 * KVBUF)                 // 36864
#define SMEM_FLASH (OFF_KV + 3 * KVSTG)    // 147456

__global__ __launch_bounds__(256, 1) void flash_mma(
    const __half* __restrict__ Qh, const __half* __restrict__ Ql,
    const __half* __restrict__ Kh, const __half* __restrict__ Kl,
    const __half* __restrict__ Vh, const __half* __restrict__ Vl,
    __half* __restrict__ Oh, __half* __restrict__ Ol)
{
    extern __shared__ char sm[];
    const uint32_t smb = cvta_smem(sm);
    const int tid = threadIdx.x;
    const int w = tid >> 5, lane = tid & 31;
    const int qi = 15 - blockIdx.x;       // reversed: heavy first
    const int bh = blockIdx.y;            // 0..63
    const int q0 = qi * 128;

    const size_t seqbase = (size_t)bh * S_LEN * DK;

    const int ldrow = tid >> 3;           // 0..31
    const int ldq = tid & 7;
    auto load_Q = [&]() {
#pragma unroll
        for (int i = 0; i < 4; i++) {
            int r = ldrow + i * 32;
            uint32_t so = (uint32_t)r * (FPITCH * 2) + (uint32_t)ldq * 16u;
            size_t g = seqbase + (size_t)(q0 + r) * DK + ldq * 8;
            cp16(smb + OFF_QH + so, Qh + g);
            cp16(smb + OFF_QL + so, Ql + g);
        }
    };
    auto load_tile = [&](int kt, int stage) {
        const uint32_t sb = smb + OFF_KV + (uint32_t)stage * KVSTG;
#pragma unroll
        for (int i = 0; i < 2; i++) {
            int r = ldrow + i * 32;
            uint32_t so = (uint32_t)r * (FPITCH * 2) + (uint32_t)ldq * 16u;
            size_t g = seqbase + (size_t)(kt * 64 + r) * DK + ldq * 8;
            cp16(sb + 0 * KVBUF + so, Kh + g);
            cp16(sb + 1 * KVBUF + so, Kl + g);
            cp16(sb + 2 * KVBUF + so, Vh + g);
            cp16(sb + 3 * KVBUF + so, Vl + g);
        }
    };

    const int T = 2 * qi + 2;

    load_Q();
    load_tile(0, 0);
    CP_COMMIT();
    load_tile(1, 1);
    CP_COMMIT();

    const int laneA = (lane & 15) * FPITCH + ((lane >> 4) & 1) * 8;
    const int laneB = ((lane & 7) + ((lane >> 4) & 1) * 8) * FPITCH + ((lane >> 3) & 1) * 8;
    const int laneV = ((lane & 7) + ((lane >> 3) & 1) * 8) * FPITCH + ((lane >> 4) & 1) * 8;

    uint32_t qhf[4][4], qlf[4][4];

    float oacc[8][4];
#pragma unroll
    for (int nf = 0; nf < 8; nf++)
#pragma unroll
        for (int j = 0; j < 4; j++) oacc[nf][j] = 0.0f;
    float m0r = -1e30f, m1r = -1e30f, l0r = 0.0f, l1r = 0.0f;

    const int ktmax_w = 2 * qi + (w >> 2);
    const float cs = 0.18033688f;         // (1/8) * log2(e)
    const int rbase = q0 + w * 16 + (lane >> 2);
    const int cbase = (lane & 3) * 2;

    for (int kt = 0; kt < T; kt++) {
        if (kt + 1 < T) { CP_WAIT(1); } else { CP_WAIT(0); }
        __syncthreads();

        if (kt == 0) {
#pragma unroll
            for (int ks = 0; ks < 4; ks++) {
                uint32_t a = smb + OFF_QH + (uint32_t)((w * 16) * FPITCH + ks * 16 + laneA) * 2;
                ldsm4(qhf[ks], a);
                ldsm4(qlf[ks], a + QBUF);
            }
        }
        if (kt + 2 < T) {
            int ls = kt + 2;
            load_tile(ls, ls - (ls / 3) * 3);
            CP_COMMIT();
        }

        if (kt <= ktmax_w) {
            const uint32_t kvb = smb + OFF_KV + (uint32_t)(kt - (kt / 3) * 3) * KVSTG;

            // ---- S = Q K^T (3-pass) ----
            float sacc[8][4];
#pragma unroll
            for (int nf = 0; nf < 8; nf++)
#pragma unroll
                for (int j = 0; j < 4; j++) sacc[nf][j] = 0.0f;

#pragma unroll
            for (int ks = 0; ks < 4; ks++) {
                uint32_t kb[16], kbl[16];
#pragma unroll
                for (int nb = 0; nb < 4; nb++) {
                    uint32_t a = kvb + (uint32_t)((nb * 16) * FPITCH + ks * 16 + laneB) * 2;
                    ldsm4(kb + nb * 4, a);
                    ldsm4(kbl + nb * 4, a + KVBUF);
                }
#pragma unroll
                for (int nf = 0; nf < 8; nf++) {
                    int bi = (nf >> 1) * 4 + (nf & 1) * 2;
                    mma16816(sacc[nf], qhf[ks], kb[bi], kb[bi + 1]);
                }
#pragma unroll
                for (int nf = 0; nf < 8; nf++) {
                    int bi = (nf >> 1) * 4 + (nf & 1) * 2;
                    mma16816(sacc[nf], qhf[ks], kbl[bi], kbl[bi + 1]);
                }
#pragma unroll
                for (int nf = 0; nf < 8; nf++) {
                    int bi = (nf >> 1) * 4 + (nf & 1) * 2;
                    mma16816(sacc[nf], qlf[ks], kb[bi], kb[bi + 1]);
                }
            }

            // ---- scale (+ causal mask on diagonal tiles) ----
            const bool need_mask = (kt * 64 + 63 > q0 + w * 16);
            if (need_mask) {
#pragma unroll
                for (int nf = 0; nf < 8; nf++) {
#pragma unroll
                    for (int j = 0; j < 4; j++) {
                        int col = kt * 64 + nf * 8 + cbase + (j & 1);
                        int row = rbase + ((j >> 1) << 3);
                        sacc[nf][j] = (col <= row) ? sacc[nf][j] * cs : -1e30f;
                    }
                }
            } else {
#pragma unroll
                for (int nf = 0; nf < 8; nf++)
#pragma unroll
                    for (int j = 0; j < 4; j++) sacc[nf][j] *= cs;
            }

            // ---- online softmax (base-2) ----
            float mx0 = -1e30f, mx1 = -1e30f;
#pragma unroll
            for (int nf = 0; nf < 8; nf++) {
                mx0 = fmaxf(mx0, fmaxf(sacc[nf][0], sacc[nf][1]));
                mx1 = fmaxf(mx1, fmaxf(sacc[nf][2], sacc[nf][3]));
            }
            mx0 = fmaxf(mx0, __shfl_xor_sync(0xffffffffu, mx0, 1));
            mx0 = fmaxf(mx0, __shfl_xor_sync(0xffffffffu, mx0, 2));
            mx1 = fmaxf(mx1, __shfl_xor_sync(0xffffffffu, mx1, 1));
            mx1 = fmaxf(mx1, __shfl_xor_sync(0xffffffffu, mx1, 2));

            float mn0 = fmaxf(m0r, mx0), mn1 = fmaxf(m1r, mx1);
            float c0 = ex2(m0r - mn0), c1 = ex2(m1r - mn1);
            m0r = mn0; m1r = mn1;

            uint32_t pHa[8], pHb[8];
            float ls0 = 0.0f, ls1 = 0.0f;
#pragma unroll
            for (int nf = 0; nf < 8; nf++) {
                float p0 = ex2(sacc[nf][0] - mn0);
                float p1 = ex2(sacc[nf][1] - mn0);
                float p2 = ex2(sacc[nf][2] - mn1);
                float p3 = ex2(sacc[nf][3] - mn1);
                ls0 += p0 + p1;
                ls1 += p2 + p3;
                __half2 h01 = __floats2half2_rn(p0, p1);
                __half2 h23 = __floats2half2_rn(p2, p3);
                pHa[nf] = *(uint32_t*)&h01;
                pHb[nf] = *(uint32_t*)&h23;
            }
            ls0 += __shfl_xor_sync(0xffffffffu, ls0, 1);
            ls0 += __shfl_xor_sync(0xffffffffu, ls0, 2);
            ls1 += __shfl_xor_sync(0xffffffffu, ls1, 1);
            ls1 += __shfl_xor_sync(0xffffffffu, ls1, 2);
            l0r = l0r * c0 + ls0;
            l1r = l1r * c1 + ls1;
#pragma unroll
            for (int nf = 0; nf < 8; nf++) {
                oacc[nf][0] *= c0; oacc[nf][1] *= c0;
                oacc[nf][2] *= c1; oacc[nf][3] *= c1;
            }

            // ---- O += P V (2-pass: P_h*V_h + P_h*V_l) ----
            const uint32_t vbb = kvb + 2 * KVBUF;
#pragma unroll
            for (int ks = 0; ks < 4; ks++) {
                uint32_t vb[16], vbl[16];
#pragma unroll
                for (int nb = 0; nb < 4; nb++) {
                    uint32_t a = vbb + (uint32_t)((ks * 16) * FPITCH + nb * 16 + laneV) * 2;
                    ldsm4t(vb + nb * 4, a);
                    ldsm4t(vbl + nb * 4, a + KVBUF);
                }
                uint32_t pa[4] = { pHa[2 * ks], pHb[2 * ks], pHa[2 * ks + 1], pHb[2 * ks + 1] };
#pragma unroll
                for (int nf = 0; nf < 8; nf++) {
                    int bi = (nf >> 1) * 4 + (nf & 1) * 2;
                    mma16816(oacc[nf], pa, vb[bi], vb[bi + 1]);
                }
#pragma unroll
                for (int nf = 0; nf < 8; nf++) {
                    int bi = (nf >> 1) * 4 + (nf & 1) * 2;
                    mma16816(oacc[nf], pa, vbl[bi], vbl[bi + 1]);
                }
            }
        }
    }

    // ---- epilogue: write split context [B,S,1024] ----
    const float inv0 = 1.0f / l0r, inv1 = 1.0f / l1r;
    const int b = bh >> 4, h = bh & 15;
    const int s0 = q0 + w * 16 + (lane >> 2);
#pragma unroll
    for (int nf = 0; nf < 8; nf++) {
        int col = h * DK + nf * 8 + cbase;
#pragma unroll
        for (int hh = 0; hh < 2; hh++) {
            int s = s0 + hh * 8;
            float vx = oacc[nf][hh * 2 + 0] * (hh ? inv1 : inv0);
            float vy = oacc[nf][hh * 2 + 1] * (hh ? inv1 : inv0);
            size_t idx = ((size_t)(b * S_LEN + s)) * DMODEL + col;
            __half2 hi2 = __floats2half2_rn(vx, vy);
            float2 hf = __half22float2(hi2);
            __half2 lo2 = __floats2half2_rn(vx - hf.x, vy - hf.y);
            *(__half2*)(Oh + idx) = hi2;
            *(__half2*)(Ol + idx) = lo2;
        }
    }
}

// ===========================================================================
extern "C" void kernel_launch(void* const* d_in, const int* in_sizes, int n_in,
                              void* d_out, int out_size)
{
    const float* query = (const float*)d_in[0];
    const float* key   = (const float*)d_in[1];
    const float* value = (const float*)d_in[2];
    // d_in[3] = causal mask — handled analytically.
    const float* Wq = (const float*)d_in[4];
    const float* bq = (const float*)d_in[5];
    const float* Wk = (const float*)d_in[6];
    const float* bk = (const float*)d_in[7];
    const float* Wv = (const float*)d_in[8];
    const float* bv = (const float*)d_in[9];
    const float* Wo = (const float*)d_in[10];
    const float* bo = (const float*)d_in[11];
    float* out = (float*)d_out;

    __half *Qh, *Ql, *Kh, *Kl, *Vh, *Vl, *Ah, *Al, *Wh, *Wl;
    cudaGetSymbolAddress((void**)&Qh, g_Qh);
    cudaGetSymbolAddress((void**)&Ql, g_Ql);
    cudaGetSymbolAddress((void**)&Kh, g_Kh);
    cudaGetSymbolAddress((void**)&Kl, g_Kl);
    cudaGetSymbolAddress((void**)&Vh, g_Vh);
    cudaGetSymbolAddress((void**)&Vl, g_Vl);
    cudaGetSymbolAddress((void**)&Ah, g_Ah);
    cudaGetSymbolAddress((void**)&Al, g_Al);
    cudaGetSymbolAddress((void**)&Wh, g_Wh);
    cudaGetSymbolAddress((void**)&Wl, g_Wl);

    cudaFuncSetAttribute(proj_gemm_mma<2>,
                         cudaFuncAttributeMaxDynamicSharedMemorySize, SMEM_GEMM);
    cudaFuncSetAttribute(proj_gemm_mma<3>,
                         cudaFuncAttributeMaxDynamicSharedMemorySize, SMEM_GEMM);
    cudaFuncSetAttribute(flash_mma,
                         cudaFuncAttributeMaxDynamicSharedMemorySize, SMEM_FLASH);

    const int n4A = MTOT * DMODEL / 4;
    const int n4W = DMODEL * DMODEL / 4;
    dim3 gg(DMODEL / 128, MTOT / 128);      // (8, 64)

    // Q (2-pass: A_lo not needed)
    split_f32<<<n4A / 256, 256>>>((const float4*)query, (uint2*)Ah, nullptr, n4A);
    split_f32<<<n4W / 256, 256>>>((const float4*)Wq, (uint2*)Wh, (uint2*)Wl, n4W);
    proj_gemm_mma<2><<<gg, 256, SMEM_GEMM>>>(Ah, nullptr, Wh, Wl, bq, nullptr, Qh, Ql, 1);
    // K (2-pass)
    split_f32<<<n4A / 256, 256>>>((const float4*)key, (uint2*)Ah, nullptr, n4A);
    split_f32<<<n4W / 256, 256>>>((const float4*)Wk, (uint2*)Wh, (uint2*)Wl, n4W);
    proj_gemm_mma<2><<<gg, 256, SMEM_GEMM>>>(Ah, nullptr, Wh, Wl, bk, nullptr, Kh, Kl, 1);
    // V (3-pass: enters output linearly)
    split_f32<<<n4A / 256, 256>>>((const float4*)value, (uint2*)Ah, (uint2*)Al, n4A);
    split_f32<<<n4W / 256, 256>>>((const float4*)Wv, (uint2*)Wh, (uint2*)Wl, n4W);
    proj_gemm_mma<3><<<gg, 256, SMEM_GEMM>>>(Ah, Al, Wh, Wl, bv, nullptr, Vh, Vl, 1);

    // attention: writes split context into Ah/Al
    flash_mma<<<dim3(16, BATCH * NHEAD), 256, SMEM_FLASH>>>(Qh, Ql, Kh, Kl, Vh, Vl, Ah, Al);

    // out = Ctx @ Wo^T + bo (3-pass, fp32 out)
    split_f32<<<n4W / 256, 256>>>((const float4*)Wo, (uint2*)Wh, (uint2*)Wl, n4W);
    proj_gemm_mma<3><<<gg, 256, SMEM_GEMM>>>(Ah, Al, Wh, Wl, bo, out, nullptr, nullptr, 0);
}

// round 6
// speedup vs baseline: 4.4273x; 1.1251x over previous
#include <cuda_runtime.h>
#include <cuda_fp16.h>
#include <cstdint>

#define S_LEN  2048
#define DMODEL 1024
#define NHEAD  16
#define DK     64
#define BATCH  4
#define MTOT   (BATCH * S_LEN)     // 8192

// ---------------- scratch (module-scope device memory) ----------------
__device__ __half g_Qh[BATCH * NHEAD * S_LEN * DK];
__device__ __half g_Kh[BATCH * NHEAD * S_LEN * DK];
__device__ __half g_Kl[BATCH * NHEAD * S_LEN * DK];
__device__ __half g_Vh[BATCH * NHEAD * S_LEN * DK];
__device__ __half g_Vl[BATCH * NHEAD * S_LEN * DK];
__device__ __half g_Ah[MTOT * DMODEL];
__device__ __half g_Al[MTOT * DMODEL];
__device__ __half g_Wh[DMODEL * DMODEL];
__device__ __half g_Wl[DMODEL * DMODEL];

// ---------------- PTX helpers (baseline PTX only) ----------------------
__device__ __forceinline__ uint32_t cvta_smem(const void* p) {
    uint32_t a;
    asm("{ .reg .u64 t; cvta.to.shared.u64 t, %1; cvt.u32.u64 %0, t; }"
        : "=r"(a) : "l"(p));
    return a;
}
__device__ __forceinline__ void cp16(uint32_t dst, const void* src) {
    asm volatile("cp.async.cg.shared.global [%0], [%1], 16;"
                 :: "r"(dst), "l"(src));
}
#define CP_COMMIT() asm volatile("cp.async.commit_group;" ::: "memory")
#define CP_WAIT(n)  asm volatile("cp.async.wait_group %0;" :: "n"(n) : "memory")

__device__ __forceinline__ void ldsm4(uint32_t* r, uint32_t addr) {
    asm volatile("ldmatrix.sync.aligned.m8n8.x4.shared.b16 {%0,%1,%2,%3}, [%4];"
                 : "=r"(r[0]), "=r"(r[1]), "=r"(r[2]), "=r"(r[3]) : "r"(addr));
}
__device__ __forceinline__ void ldsm4t(uint32_t* r, uint32_t addr) {
    asm volatile("ldmatrix.sync.aligned.m8n8.x4.trans.shared.b16 {%0,%1,%2,%3}, [%4];"
                 : "=r"(r[0]), "=r"(r[1]), "=r"(r[2]), "=r"(r[3]) : "r"(addr));
}
__device__ __forceinline__ void mma16816(float* d, const uint32_t* a,
                                         uint32_t b0, uint32_t b1) {
    asm volatile(
        "mma.sync.aligned.m16n8k16.row.col.f32.f16.f16.f32 "
        "{%0,%1,%2,%3}, {%4,%5,%6,%7}, {%8,%9}, {%0,%1,%2,%3};"
        : "+f"(d[0]), "+f"(d[1]), "+f"(d[2]), "+f"(d[3])
        : "r"(a[0]), "r"(a[1]), "r"(a[2]), "r"(a[3]), "r"(b0), "r"(b1));
}
__device__ __forceinline__ float ex2(float x) {
    float y;
    asm("ex2.approx.f32 %0, %1;" : "=f"(y) : "f"(x));
    return y;
}

// ---------------- fp32 -> split f16 (hi/lo; lo optional) ---------------
__global__ __launch_bounds__(256) void split_f32(
    const float4* __restrict__ x, uint2* __restrict__ hi,
    uint2* __restrict__ lo, int n4)
{
    int i = blockIdx.x * 256 + threadIdx.x;
    if (i >= n4) return;
    float4 v = x[i];
    __half h0 = __float2half_rn(v.x), h1 = __float2half_rn(v.y);
    __half h2 = __float2half_rn(v.z), h3 = __float2half_rn(v.w);
    uint2 H;
    H.x = (uint32_t)__half_as_ushort(h0) | ((uint32_t)__half_as_ushort(h1) << 16);
    H.y = (uint32_t)__half_as_ushort(h2) | ((uint32_t)__half_as_ushort(h3) << 16);
    hi[i] = H;
    if (lo) {
        __half l0 = __float2half_rn(v.x - __half2float(h0));
        __half l1 = __float2half_rn(v.y - __half2float(h1));
        __half l2 = __float2half_rn(v.z - __half2float(h2));
        __half l3 = __float2half_rn(v.w - __half2float(h3));
        uint2 L;
        L.x = (uint32_t)__half_as_ushort(l0) | ((uint32_t)__half_as_ushort(l1) << 16);
        L.y = (uint32_t)__half_as_ushort(l2) | ((uint32_t)__half_as_ushort(l3) << 16);
        lo[i] = L;
    }
}

// ---------------- HMMA projection GEMM (256x128 tile) -------------------
// C = A[M,1024] @ W[1024,1024]^T + bias.  A/W pre-split f16 hi/lo.
// NPASS=3: Ah*Wh + Ah*Wl + Al*Wh.  NPASS=2: Ah*Wh + Ah*Wl (A_lo not loaded).
// remap=1: head-split [B,H,S,DK] as f16 hi (+lo if Cl); remap=0: fp32 [M,1024].
// 8 warps, warp tile 64x64 (mf 4 x nf 8), K-chunk 32, 3-stage pipeline.
#define TILE_M 256
#define TILE_N 128
#define KCH    32
#define NC     (DMODEL / KCH)  // 32
#define PITCH  40              // halves per smem row (80B)
// per-stage offsets (bytes)
#define AH_OFF 0
#define AL_OFF 20480
#define BH_OFF 40960
#define BL_OFF 51200
#define STG_B  61440
#define SMEM_GEMM (3 * STG_B)  // 184320

template <int NPASS>
__global__ __launch_bounds__(256) void proj_gemm_mma(
    const __half* __restrict__ Ahg, const __half* __restrict__ Alg,
    const __half* __restrict__ Whg, const __half* __restrict__ Wlg,
    const float* __restrict__ bias, float* __restrict__ Cf,
    __half* __restrict__ Ch, __half* __restrict__ Cl, int remap)
{
    extern __shared__ char sm[];
    const uint32_t smb = cvta_smem(sm);
    const int tid = threadIdx.x;
    const int wid = tid >> 5, lane = tid & 31;
    const int wm = wid & 3;          // 4 m-slices of 64
    const int wn = wid >> 2;         // 2 n-slices of 64
    const int m0 = blockIdx.y * TILE_M;
    const int n0 = blockIdx.x * TILE_N;

    const int laneA = (lane & 15) * PITCH + ((lane >> 4) & 1) * 8;
    const int laneB = ((lane & 7) + ((lane >> 4) & 1) * 8) * PITCH + ((lane >> 3) & 1) * 8;

    auto load_chunk = [&](int c, int stage) {
        const uint32_t sbase = smb + (uint32_t)stage * STG_B;
        // A: 256 rows x 4 quads = 1024 slots (4 iters of 256 threads)
#pragma unroll
        for (int i = 0; i < 4; i++) {
            int slot = tid + i * 256;
            int row = slot >> 2, quad = slot & 3;
            uint32_t soff = (uint32_t)row * 80u + (uint32_t)quad * 16u;
            size_t goff = (size_t)(m0 + row) * DMODEL + c * KCH + quad * 8;
            cp16(sbase + AH_OFF + soff, Ahg + goff);
            if (NPASS == 3) cp16(sbase + AL_OFF + soff, Alg + goff);
        }
        // B: 128 rows x 4 quads = 512 slots (2 iters)
#pragma unroll
        for (int i = 0; i < 2; i++) {
            int slot = tid + i * 256;
            int row = slot >> 2, quad = slot & 3;
            uint32_t soff = (uint32_t)row * 80u + (uint32_t)quad * 16u;
            size_t goff = (size_t)(n0 + row) * DMODEL + c * KCH + quad * 8;
            cp16(sbase + BH_OFF + soff, Whg + goff);
            cp16(sbase + BL_OFF + soff, Wlg + goff);
        }
    };

    float acc[4][8][4] = {};

    load_chunk(0, 0);
    CP_COMMIT();
    load_chunk(1, 1);
    CP_COMMIT();

    for (int c = 0; c < NC; c++) {
        if (c + 1 < NC) { CP_WAIT(1); } else { CP_WAIT(0); }
        __syncthreads();
        if (c + 2 < NC) {
            int ls = c + 2;
            load_chunk(ls, ls - (ls / 3) * 3);
            CP_COMMIT();
        }

        const uint32_t sbase = smb + (uint32_t)(c - (c / 3) * 3) * STG_B;

#pragma unroll
        for (int ks = 0; ks < 2; ks++) {
            const int kk = ks * 16;
            uint32_t ah[4][4], al[4][4], bh[16], bl[16];
#pragma unroll
            for (int mf = 0; mf < 4; mf++) {
                uint32_t idx = (uint32_t)((wm * 64 + mf * 16) * PITCH + kk + laneA) * 2;
                ldsm4(ah[mf], sbase + AH_OFF + idx);
                if (NPASS == 3) ldsm4(al[mf], sbase + AL_OFF + idx);
            }
#pragma unroll
            for (int nf2 = 0; nf2 < 4; nf2++) {
                uint32_t idx = (uint32_t)((wn * 64 + nf2 * 16) * PITCH + kk + laneB) * 2;
                ldsm4(bh + nf2 * 4, sbase + BH_OFF + idx);
                ldsm4(bl + nf2 * 4, sbase + BL_OFF + idx);
            }
            // pass-major: 32 independent accumulators between reuses
#pragma unroll
            for (int mf = 0; mf < 4; mf++)
#pragma unroll
                for (int nf = 0; nf < 8; nf++) {
                    int bi = (nf >> 1) * 4 + (nf & 1) * 2;
                    mma16816(acc[mf][nf], ah[mf], bh[bi], bh[bi + 1]);
                }
#pragma unroll
            for (int mf = 0; mf < 4; mf++)
#pragma unroll
                for (int nf = 0; nf < 8; nf++) {
                    int bi = (nf >> 1) * 4 + (nf & 1) * 2;
                    mma16816(acc[mf][nf], ah[mf], bl[bi], bl[bi + 1]);
                }
            if (NPASS == 3) {
#pragma unroll
                for (int mf = 0; mf < 4; mf++)
#pragma unroll
                    for (int nf = 0; nf < 8; nf++) {
                        int bi = (nf >> 1) * 4 + (nf & 1) * 2;
                        mma16816(acc[mf][nf], al[mf], bh[bi], bh[bi + 1]);
                    }
            }
        }
    }

    // epilogue
#pragma unroll
    for (int mf = 0; mf < 4; mf++) {
#pragma unroll
        for (int nf = 0; nf < 8; nf++) {
            int m = m0 + wm * 64 + mf * 16 + (lane >> 2);
            int n = n0 + wn * 64 + nf * 8 + (lane & 3) * 2;
            float bx = bias[n], by = bias[n + 1];
#pragma unroll
            for (int hh = 0; hh < 2; hh++) {
                int mm = m + hh * 8;
                float vx = acc[mf][nf][hh * 2 + 0] + bx;
                float vy = acc[mf][nf][hh * 2 + 1] + by;
                if (remap) {
                    int b = mm >> 11, s = mm & (S_LEN - 1);
                    int h = n >> 6, d = n & (DK - 1);
                    size_t idx = ((size_t)((b << 4) + h) * S_LEN + s) * DK + d;
                    __half2 hi2 = __floats2half2_rn(vx, vy);
                    *(__half2*)(Ch + idx) = hi2;
                    if (Cl) {
                        float2 hf = __half22float2(hi2);
                        __half2 lo2 = __floats2half2_rn(vx - hf.x, vy - hf.y);
                        *(__half2*)(Cl + idx) = lo2;
                    }
                } else {
                    float2 v; v.x = vx; v.y = vy;
                    *(float2*)(Cf + (size_t)mm * DMODEL + n) = v;
                }
            }
        }
    }
}

// ---------------- HMMA causal flash attention ---------------------------
// BQ=128 (8 warps x m16), BKV=64, d=64.
// QK 2-pass: Qh*Kh + Qh*Kl (Q stored fp16-only). PV 2-pass: P*Vh + P*Vl.
// 3-stage KV pipeline; heavy q-tiles launch first (reversed blockIdx.x).
#define FPITCH 72                          // halves
#define QBUF   (128 * FPITCH * 2)          // 18432 B
#define KVBUF  (64 * FPITCH * 2)           // 9216 B
#define OFF_QH 0
#define OFF_KV QBUF                        // 18432
#define KVSTG  (4 * KVBUF)                 // 36864
#define SMEM_FLASH (OFF_KV + 3 * KVSTG)    // 129024

__global__ __launch_bounds__(256, 1) void flash_mma(
    const __half* __restrict__ Qh,
    const __half* __restrict__ Kh, const __half* __restrict__ Kl,
    const __half* __restrict__ Vh, const __half* __restrict__ Vl,
    __half* __restrict__ Oh, __half* __restrict__ Ol)
{
    extern __shared__ char sm[];
    const uint32_t smb = cvta_smem(sm);
    const int tid = threadIdx.x;
    const int w = tid >> 5, lane = tid & 31;
    const int qi = 15 - blockIdx.x;       // reversed: heavy first
    const int bh = blockIdx.y;            // 0..63
    const int q0 = qi * 128;

    const size_t seqbase = (size_t)bh * S_LEN * DK;

    const int ldrow = tid >> 3;           // 0..31
    const int ldq = tid & 7;
    auto load_Q = [&]() {
#pragma unroll
        for (int i = 0; i < 4; i++) {
            int r = ldrow + i * 32;
            uint32_t so = (uint32_t)r * (FPITCH * 2) + (uint32_t)ldq * 16u;
            size_t g = seqbase + (size_t)(q0 + r) * DK + ldq * 8;
            cp16(smb + OFF_QH + so, Qh + g);
        }
    };
    auto load_tile = [&](int kt, int stage) {
        const uint32_t sb = smb + OFF_KV + (uint32_t)stage * KVSTG;
#pragma unroll
        for (int i = 0; i < 2; i++) {
            int r = ldrow + i * 32;
            uint32_t so = (uint32_t)r * (FPITCH * 2) + (uint32_t)ldq * 16u;
            size_t g = seqbase + (size_t)(kt * 64 + r) * DK + ldq * 8;
            cp16(sb + 0 * KVBUF + so, Kh + g);
            cp16(sb + 1 * KVBUF + so, Kl + g);
            cp16(sb + 2 * KVBUF + so, Vh + g);
            cp16(sb + 3 * KVBUF + so, Vl + g);
        }
    };

    const int T = 2 * qi + 2;

    load_Q();
    load_tile(0, 0);
    CP_COMMIT();
    load_tile(1, 1);
    CP_COMMIT();

    const int laneA = (lane & 15) * FPITCH + ((lane >> 4) & 1) * 8;
    const int laneB = ((lane & 7) + ((lane >> 4) & 1) * 8) * FPITCH + ((lane >> 3) & 1) * 8;
    const int laneV = ((lane & 7) + ((lane >> 3) & 1) * 8) * FPITCH + ((lane >> 4) & 1) * 8;

    uint32_t qhf[4][4];

    float oacc[8][4];
#pragma unroll
    for (int nf = 0; nf < 8; nf++)
#pragma unroll
        for (int j = 0; j < 4; j++) oacc[nf][j] = 0.0f;
    float m0r = -1e30f, m1r = -1e30f, l0r = 0.0f, l1r = 0.0f;

    const int ktmax_w = 2 * qi + (w >> 2);
    const float cs = 0.18033688f;         // (1/8) * log2(e)
    const int rbase = q0 + w * 16 + (lane >> 2);
    const int cbase = (lane & 3) * 2;

    for (int kt = 0; kt < T; kt++) {
        if (kt + 1 < T) { CP_WAIT(1); } else { CP_WAIT(0); }
        __syncthreads();

        if (kt == 0) {
#pragma unroll
            for (int ks = 0; ks < 4; ks++) {
                uint32_t a = smb + OFF_QH + (uint32_t)((w * 16) * FPITCH + ks * 16 + laneA) * 2;
                ldsm4(qhf[ks], a);
            }
        }
        if (kt + 2 < T) {
            int ls = kt + 2;
            load_tile(ls, ls - (ls / 3) * 3);
            CP_COMMIT();
        }

        if (kt <= ktmax_w) {
            const uint32_t kvb = smb + OFF_KV + (uint32_t)(kt - (kt / 3) * 3) * KVSTG;

            // ---- S = Q K^T (2-pass: Qh*Kh + Qh*Kl) ----
            float sacc[8][4];
#pragma unroll
            for (int nf = 0; nf < 8; nf++)
#pragma unroll
                for (int j = 0; j < 4; j++) sacc[nf][j] = 0.0f;

#pragma unroll
            for (int ks = 0; ks < 4; ks++) {
                uint32_t kb[16], kbl[16];
#pragma unroll
                for (int nb = 0; nb < 4; nb++) {
                    uint32_t a = kvb + (uint32_t)((nb * 16) * FPITCH + ks * 16 + laneB) * 2;
                    ldsm4(kb + nb * 4, a);
                    ldsm4(kbl + nb * 4, a + KVBUF);
                }
#pragma unroll
                for (int nf = 0; nf < 8; nf++) {
                    int bi = (nf >> 1) * 4 + (nf & 1) * 2;
                    mma16816(sacc[nf], qhf[ks], kb[bi], kb[bi + 1]);
                }
#pragma unroll
                for (int nf = 0; nf < 8; nf++) {
                    int bi = (nf >> 1) * 4 + (nf & 1) * 2;
                    mma16816(sacc[nf], qhf[ks], kbl[bi], kbl[bi + 1]);
                }
            }

            // ---- scale (+ causal mask on diagonal tiles) ----
            const bool need_mask = (kt * 64 + 63 > q0 + w * 16);
            if (need_mask) {
#pragma unroll
                for (int nf = 0; nf < 8; nf++) {
#pragma unroll
                    for (int j = 0; j < 4; j++) {
                        int col = kt * 64 + nf * 8 + cbase + (j & 1);
                        int row = rbase + ((j >> 1) << 3);
                        sacc[nf][j] = (col <= row) ? sacc[nf][j] * cs : -1e30f;
                    }
                }
            } else {
#pragma unroll
                for (int nf = 0; nf < 8; nf++)
#pragma unroll
                    for (int j = 0; j < 4; j++) sacc[nf][j] *= cs;
            }

            // ---- online softmax (base-2) ----
            float mx0 = -1e30f, mx1 = -1e30f;
#pragma unroll
            for (int nf = 0; nf < 8; nf++) {
                mx0 = fmaxf(mx0, fmaxf(sacc[nf][0], sacc[nf][1]));
                mx1 = fmaxf(mx1, fmaxf(sacc[nf][2], sacc[nf][3]));
            }
            mx0 = fmaxf(mx0, __shfl_xor_sync(0xffffffffu, mx0, 1));
            mx0 = fmaxf(mx0, __shfl_xor_sync(0xffffffffu, mx0, 2));
            mx1 = fmaxf(mx1, __shfl_xor_sync(0xffffffffu, mx1, 1));
            mx1 = fmaxf(mx1, __shfl_xor_sync(0xffffffffu, mx1, 2));

            float mn0 = fmaxf(m0r, mx0), mn1 = fmaxf(m1r, mx1);
            float c0 = ex2(m0r - mn0), c1 = ex2(m1r - mn1);
            m0r = mn0; m1r = mn1;

            uint32_t pHa[8], pHb[8];
            float ls0 = 0.0f, ls1 = 0.0f;
#pragma unroll
            for (int nf = 0; nf < 8; nf++) {
                float p0 = ex2(sacc[nf][0] - mn0);
                float p1 = ex2(sacc[nf][1] - mn0);
                float p2 = ex2(sacc[nf][2] - mn1);
                float p3 = ex2(sacc[nf][3] - mn1);
                ls0 += p0 + p1;
                ls1 += p2 + p3;
                __half2 h01 = __floats2half2_rn(p0, p1);
                __half2 h23 = __floats2half2_rn(p2, p3);
                pHa[nf] = *(uint32_t*)&h01;
                pHb[nf] = *(uint32_t*)&h23;
            }
            ls0 += __shfl_xor_sync(0xffffffffu, ls0, 1);
            ls0 += __shfl_xor_sync(0xffffffffu, ls0, 2);
            ls1 += __shfl_xor_sync(0xffffffffu, ls1, 1);
            ls1 += __shfl_xor_sync(0xffffffffu, ls1, 2);
            l0r = l0r * c0 + ls0;
            l1r = l1r * c1 + ls1;
#pragma unroll
            for (int nf = 0; nf < 8; nf++) {
                oacc[nf][0] *= c0; oacc[nf][1] *= c0;
                oacc[nf][2] *= c1; oacc[nf][3] *= c1;
            }

            // ---- O += P V (2-pass: P*Vh + P*Vl) ----
            const uint32_t vbb = kvb + 2 * KVBUF;
#pragma unroll
            for (int ks = 0; ks < 4; ks++) {
                uint32_t vb[16], vbl[16];
#pragma unroll
                for (int nb = 0; nb < 4; nb++) {
                    uint32_t a = vbb + (uint32_t)((ks * 16) * FPITCH + nb * 16 + laneV) * 2;
                    ldsm4t(vb + nb * 4, a);
                    ldsm4t(vbl + nb * 4, a + KVBUF);
                }
                uint32_t pa[4] = { pHa[2 * ks], pHb[2 * ks], pHa[2 * ks + 1], pHb[2 * ks + 1] };
#pragma unroll
                for (int nf = 0; nf < 8; nf++) {
                    int bi = (nf >> 1) * 4 + (nf & 1) * 2;
                    mma16816(oacc[nf], pa, vb[bi], vb[bi + 1]);
                }
#pragma unroll
                for (int nf = 0; nf < 8; nf++) {
                    int bi = (nf >> 1) * 4 + (nf & 1) * 2;
                    mma16816(oacc[nf], pa, vbl[bi], vbl[bi + 1]);
                }
            }
        }
    }

    // ---- epilogue: write split context [B,S,1024] ----
    const float inv0 = 1.0f / l0r, inv1 = 1.0f / l1r;
    const int b = bh >> 4, h = bh & 15;
    const int s0 = q0 + w * 16 + (lane >> 2);
#pragma unroll
    for (int nf = 0; nf < 8; nf++) {
        int col = h * DK + nf * 8 + cbase;
#pragma unroll
        for (int hh = 0; hh < 2; hh++) {
            int s = s0 + hh * 8;
            float vx = oacc[nf][hh * 2 + 0] * (hh ? inv1 : inv0);
            float vy = oacc[nf][hh * 2 + 1] * (hh ? inv1 : inv0);
            size_t idx = ((size_t)(b * S_LEN + s)) * DMODEL + col;
            __half2 hi2 = __floats2half2_rn(vx, vy);
            float2 hf = __half22float2(hi2);
            __half2 lo2 = __floats2half2_rn(vx - hf.x, vy - hf.y);
            *(__half2*)(Oh + idx) = hi2;
            *(__half2*)(Ol + idx) = lo2;
        }
    }
}

// ===========================================================================
extern "C" void kernel_launch(void* const* d_in, const int* in_sizes, int n_in,
                              void* d_out, int out_size)
{
    const float* query = (const float*)d_in[0];
    const float* key   = (const float*)d_in[1];
    const float* value = (const float*)d_in[2];
    // d_in[3] = causal mask — handled analytically.
    const float* Wq = (const float*)d_in[4];
    const float* bq = (const float*)d_in[5];
    const float* Wk = (const float*)d_in[6];
    const float* bk = (const float*)d_in[7];
    const float* Wv = (const float*)d_in[8];
    const float* bv = (const float*)d_in[9];
    const float* Wo = (const float*)d_in[10];
    const float* bo = (const float*)d_in[11];
    float* out = (float*)d_out;

    __half *Qh, *Kh, *Kl, *Vh, *Vl, *Ah, *Al, *Wh, *Wl;
    cudaGetSymbolAddress((void**)&Qh, g_Qh);
    cudaGetSymbolAddress((void**)&Kh, g_Kh);
    cudaGetSymbolAddress((void**)&Kl, g_Kl);
    cudaGetSymbolAddress((void**)&Vh, g_Vh);
    cudaGetSymbolAddress((void**)&Vl, g_Vl);
    cudaGetSymbolAddress((void**)&Ah, g_Ah);
    cudaGetSymbolAddress((void**)&Al, g_Al);
    cudaGetSymbolAddress((void**)&Wh, g_Wh);
    cudaGetSymbolAddress((void**)&Wl, g_Wl);

    cudaFuncSetAttribute(proj_gemm_mma<2>,
                         cudaFuncAttributeMaxDynamicSharedMemorySize, SMEM_GEMM);
    cudaFuncSetAttribute(proj_gemm_mma<3>,
                         cudaFuncAttributeMaxDynamicSharedMemorySize, SMEM_GEMM);
    cudaFuncSetAttribute(flash_mma,
                         cudaFuncAttributeMaxDynamicSharedMemorySize, SMEM_FLASH);

    const int n4A = MTOT * DMODEL / 4;
    const int n4W = DMODEL * DMODEL / 4;
    dim3 gg(DMODEL / TILE_N, MTOT / TILE_M);   // (8, 32)

    // Q (2-pass GEMM, fp16-only output)
    split_f32<<<n4A / 256, 256>>>((const float4*)query, (uint2*)Ah, nullptr, n4A);
    split_f32<<<n4W / 256, 256>>>((const float4*)Wq, (uint2*)Wh, (uint2*)Wl, n4W);
    proj_gemm_mma<2><<<gg, 256, SMEM_GEMM>>>(Ah, nullptr, Wh, Wl, bq, nullptr, Qh, nullptr, 1);
    // K (2-pass GEMM, hi+lo output)
    split_f32<<<n4A / 256, 256>>>((const float4*)key, (uint2*)Ah, nullptr, n4A);
    split_f32<<<n4W / 256, 256>>>((const float4*)Wk, (uint2*)Wh, (uint2*)Wl, n4W);
    proj_gemm_mma<2><<<gg, 256, SMEM_GEMM>>>(Ah, nullptr, Wh, Wl, bk, nullptr, Kh, Kl, 1);
    // V (3-pass GEMM, hi+lo output)
    split_f32<<<n4A / 256, 256>>>((const float4*)value, (uint2*)Ah, (uint2*)Al, n4A);
    split_f32<<<n4W / 256, 256>>>((const float4*)Wv, (uint2*)Wh, (uint2*)Wl, n4W);
    proj_gemm_mma<3><<<gg, 256, SMEM_GEMM>>>(Ah, Al, Wh, Wl, bv, nullptr, Vh, Vl, 1);

    // attention: writes split context into Ah/Al
    flash_mma<<<dim3(16, BATCH * NHEAD), 256, SMEM_FLASH>>>(Qh, Kh, Kl, Vh, Vl, Ah, Al);

    // out = Ctx @ Wo^T + bo (3-pass, fp32 out)
    split_f32<<<n4W / 256, 256>>>((const float4*)Wo, (uint2*)Wh, (uint2*)Wl, n4W);
    proj_gemm_mma<3><<<gg, 256, SMEM_GEMM>>>(Ah, Al, Wh, Wl, bo, out, nullptr, nullptr, 0);
}

// round 7
// speedup vs baseline: 5.8009x; 1.3103x over previous
#include <cuda_runtime.h>
#include <cuda_fp16.h>
#include <cstdint>

#define S_LEN  2048
#define DMODEL 1024
#define NHEAD  16
#define DK     64
#define BATCH  4
#define MTOT   (BATCH * S_LEN)     // 8192

// ---------------- scratch (module-scope device memory) ----------------
__device__ __half g_Qh[BATCH * NHEAD * S_LEN * DK];
__device__ __half g_Kh[BATCH * NHEAD * S_LEN * DK];
__device__ __half g_Vh[BATCH * NHEAD * S_LEN * DK];
__device__ __half g_Ah[MTOT * DMODEL];
__device__ __half g_Wh[DMODEL * DMODEL];
__device__ __half g_Wl[DMODEL * DMODEL];

// ---------------- PTX helpers (baseline PTX only) ----------------------
__device__ __forceinline__ uint32_t cvta_smem(const void* p) {
    uint32_t a;
    asm("{ .reg .u64 t; cvta.to.shared.u64 t, %1; cvt.u32.u64 %0, t; }"
        : "=r"(a) : "l"(p));
    return a;
}
__device__ __forceinline__ void cp16(uint32_t dst, const void* src) {
    asm volatile("cp.async.cg.shared.global [%0], [%1], 16;"
                 :: "r"(dst), "l"(src));
}
#define CP_COMMIT() asm volatile("cp.async.commit_group;" ::: "memory")
#define CP_WAIT(n)  asm volatile("cp.async.wait_group %0;" :: "n"(n) : "memory")

__device__ __forceinline__ void ldsm4(uint32_t* r, uint32_t addr) {
    asm volatile("ldmatrix.sync.aligned.m8n8.x4.shared.b16 {%0,%1,%2,%3}, [%4];"
                 : "=r"(r[0]), "=r"(r[1]), "=r"(r[2]), "=r"(r[3]) : "r"(addr));
}
__device__ __forceinline__ void ldsm4t(uint32_t* r, uint32_t addr) {
    asm volatile("ldmatrix.sync.aligned.m8n8.x4.trans.shared.b16 {%0,%1,%2,%3}, [%4];"
                 : "=r"(r[0]), "=r"(r[1]), "=r"(r[2]), "=r"(r[3]) : "r"(addr));
}
__device__ __forceinline__ void mma16816(float* d, const uint32_t* a,
                                         uint32_t b0, uint32_t b1) {
    asm volatile(
        "mma.sync.aligned.m16n8k16.row.col.f32.f16.f16.f32 "
        "{%0,%1,%2,%3}, {%4,%5,%6,%7}, {%8,%9}, {%0,%1,%2,%3};"
        : "+f"(d[0]), "+f"(d[1]), "+f"(d[2]), "+f"(d[3])
        : "r"(a[0]), "r"(a[1]), "r"(a[2]), "r"(a[3]), "r"(b0), "r"(b1));
}
__device__ __forceinline__ float ex2(float x) {
    float y;
    asm("ex2.approx.f32 %0, %1;" : "=f"(y) : "f"(x));
    return y;
}

// ---------------- fp32 -> f16 hi (+ optional lo residual) --------------
__global__ __launch_bounds__(256) void split_f32(
    const float4* __restrict__ x, uint2* __restrict__ hi,
    uint2* __restrict__ lo, int n4)
{
    int i = blockIdx.x * 256 + threadIdx.x;
    if (i >= n4) return;
    float4 v = x[i];
    __half h0 = __float2half_rn(v.x), h1 = __float2half_rn(v.y);
    __half h2 = __float2half_rn(v.z), h3 = __float2half_rn(v.w);
    uint2 H;
    H.x = (uint32_t)__half_as_ushort(h0) | ((uint32_t)__half_as_ushort(h1) << 16);
    H.y = (uint32_t)__half_as_ushort(h2) | ((uint32_t)__half_as_ushort(h3) << 16);
    hi[i] = H;
    if (lo) {
        __half l0 = __float2half_rn(v.x - __half2float(h0));
        __half l1 = __float2half_rn(v.y - __half2float(h1));
        __half l2 = __float2half_rn(v.z - __half2float(h2));
        __half l3 = __float2half_rn(v.w - __half2float(h3));
        uint2 L;
        L.x = (uint32_t)__half_as_ushort(l0) | ((uint32_t)__half_as_ushort(l1) << 16);
        L.y = (uint32_t)__half_as_ushort(l2) | ((uint32_t)__half_as_ushort(l3) << 16);
        lo[i] = L;
    }
}

// ---------------- HMMA projection GEMM (256x128 tile, 2-pass) -----------
// C = A[M,1024] @ W[1024,1024]^T + bias.  A fp16-hi; W split hi/lo.
// Passes: Ah*Wh + Ah*Wl.
// remap=1: head-split [B,H,S,DK] fp16; remap=0: fp32 [M,1024].
// 8 warps, warp tile 64x64, K-chunk 32, 4-stage cp.async pipeline.
#define TILE_M 256
#define TILE_N 128
#define KCH    32
#define NC     (DMODEL / KCH)  // 32
#define PITCH  40              // halves per smem row (80B)
#define AH_OFF 0
#define BH_OFF 20480
#define BL_OFF 30720
#define STG_B  40960
#define SMEM_GEMM (4 * STG_B)  // 163840

__global__ __launch_bounds__(256) void proj_gemm_mma(
    const __half* __restrict__ Ahg,
    const __half* __restrict__ Whg, const __half* __restrict__ Wlg,
    const float* __restrict__ bias, float* __restrict__ Cf,
    __half* __restrict__ Ch, int remap)
{
    extern __shared__ char sm[];
    const uint32_t smb = cvta_smem(sm);
    const int tid = threadIdx.x;
    const int wid = tid >> 5, lane = tid & 31;
    const int wm = wid & 3;
    const int wn = wid >> 2;
    const int m0 = blockIdx.y * TILE_M;
    const int n0 = blockIdx.x * TILE_N;

    const int laneA = (lane & 15) * PITCH + ((lane >> 4) & 1) * 8;
    const int laneB = ((lane & 7) + ((lane >> 4) & 1) * 8) * PITCH + ((lane >> 3) & 1) * 8;

    auto load_chunk = [&](int c, int stage) {
        const uint32_t sbase = smb + (uint32_t)stage * STG_B;
#pragma unroll
        for (int i = 0; i < 4; i++) {
            int slot = tid + i * 256;
            int row = slot >> 2, quad = slot & 3;
            uint32_t soff = (uint32_t)row * 80u + (uint32_t)quad * 16u;
            size_t goff = (size_t)(m0 + row) * DMODEL + c * KCH + quad * 8;
            cp16(sbase + AH_OFF + soff, Ahg + goff);
        }
#pragma unroll
        for (int i = 0; i < 2; i++) {
            int slot = tid + i * 256;
            int row = slot >> 2, quad = slot & 3;
            uint32_t soff = (uint32_t)row * 80u + (uint32_t)quad * 16u;
            size_t goff = (size_t)(n0 + row) * DMODEL + c * KCH + quad * 8;
            cp16(sbase + BH_OFF + soff, Whg + goff);
            cp16(sbase + BL_OFF + soff, Wlg + goff);
        }
    };

    float acc[4][8][4] = {};

    load_chunk(0, 0); CP_COMMIT();
    load_chunk(1, 1); CP_COMMIT();
    load_chunk(2, 2); CP_COMMIT();

    for (int c = 0; c < NC; c++) {
        if (c < NC - 2)       { CP_WAIT(2); }
        else if (c == NC - 2) { CP_WAIT(1); }
        else                  { CP_WAIT(0); }
        __syncthreads();
        if (c + 3 < NC) {
            load_chunk(c + 3, (c + 3) & 3);
            CP_COMMIT();
        }

        const uint32_t sbase = smb + (uint32_t)(c & 3) * STG_B;

#pragma unroll
        for (int ks = 0; ks < 2; ks++) {
            const int kk = ks * 16;
            uint32_t ah[4][4], bh[16], bl[16];
#pragma unroll
            for (int mf = 0; mf < 4; mf++) {
                uint32_t idx = (uint32_t)((wm * 64 + mf * 16) * PITCH + kk + laneA) * 2;
                ldsm4(ah[mf], sbase + AH_OFF + idx);
            }
#pragma unroll
            for (int nf2 = 0; nf2 < 4; nf2++) {
                uint32_t idx = (uint32_t)((wn * 64 + nf2 * 16) * PITCH + kk + laneB) * 2;
                ldsm4(bh + nf2 * 4, sbase + BH_OFF + idx);
                ldsm4(bl + nf2 * 4, sbase + BL_OFF + idx);
            }
            // pass-major: 32 independent accumulators between reuses
#pragma unroll
            for (int mf = 0; mf < 4; mf++)
#pragma unroll
                for (int nf = 0; nf < 8; nf++) {
                    int bi = (nf >> 1) * 4 + (nf & 1) * 2;
                    mma16816(acc[mf][nf], ah[mf], bh[bi], bh[bi + 1]);
                }
#pragma unroll
            for (int mf = 0; mf < 4; mf++)
#pragma unroll
                for (int nf = 0; nf < 8; nf++) {
                    int bi = (nf >> 1) * 4 + (nf & 1) * 2;
                    mma16816(acc[mf][nf], ah[mf], bl[bi], bl[bi + 1]);
                }
        }
    }

    // epilogue
#pragma unroll
    for (int mf = 0; mf < 4; mf++) {
#pragma unroll
        for (int nf = 0; nf < 8; nf++) {
            int m = m0 + wm * 64 + mf * 16 + (lane >> 2);
            int n = n0 + wn * 64 + nf * 8 + (lane & 3) * 2;
            float bx = bias[n], by = bias[n + 1];
#pragma unroll
            for (int hh = 0; hh < 2; hh++) {
                int mm = m + hh * 8;
                float vx = acc[mf][nf][hh * 2 + 0] + bx;
                float vy = acc[mf][nf][hh * 2 + 1] + by;
                if (remap) {
                    int b = mm >> 11, s = mm & (S_LEN - 1);
                    int h = n >> 6, d = n & (DK - 1);
                    size_t idx = ((size_t)((b << 4) + h) * S_LEN + s) * DK + d;
                    *(__half2*)(Ch + idx) = __floats2half2_rn(vx, vy);
                } else {
                    float2 v; v.x = vx; v.y = vy;
                    *(float2*)(Cf + (size_t)mm * DMODEL + n) = v;
                }
            }
        }
    }
}

// ---------------- HMMA causal flash attention (all fp16, 1-pass) --------
// BQ=128 (8 warps x m16), BKV=64, d=64. QK = Qh*Kh, PV = P*Vh.
// 4-stage KV pipeline; heavy q-tiles launch first.
#define FPITCH 72                          // halves
#define QBUF   (128 * FPITCH * 2)          // 18432 B
#define KVBUF  (64 * FPITCH * 2)           // 9216 B
#define OFF_QH 0
#define OFF_KV QBUF
#define KVSTG  (2 * KVBUF)                 // 18432 (K + V)
#define SMEM_FLASH (OFF_KV + 4 * KVSTG)    // 92160

__global__ __launch_bounds__(256, 1) void flash_mma(
    const __half* __restrict__ Qh,
    const __half* __restrict__ Kh, const __half* __restrict__ Vh,
    __half* __restrict__ Oh)
{
    extern __shared__ char sm[];
    const uint32_t smb = cvta_smem(sm);
    const int tid = threadIdx.x;
    const int w = tid >> 5, lane = tid & 31;
    const int qi = 15 - blockIdx.x;       // reversed: heavy first
    const int bh = blockIdx.y;
    const int q0 = qi * 128;

    const size_t seqbase = (size_t)bh * S_LEN * DK;

    const int ldrow = tid >> 3;           // 0..31
    const int ldq = tid & 7;
    auto load_Q = [&]() {
#pragma unroll
        for (int i = 0; i < 4; i++) {
            int r = ldrow + i * 32;
            uint32_t so = (uint32_t)r * (FPITCH * 2) + (uint32_t)ldq * 16u;
            size_t g = seqbase + (size_t)(q0 + r) * DK + ldq * 8;
            cp16(smb + OFF_QH + so, Qh + g);
        }
    };
    auto load_tile = [&](int kt, int stage) {
        const uint32_t sb = smb + OFF_KV + (uint32_t)stage * KVSTG;
#pragma unroll
        for (int i = 0; i < 2; i++) {
            int r = ldrow + i * 32;
            uint32_t so = (uint32_t)r * (FPITCH * 2) + (uint32_t)ldq * 16u;
            size_t g = seqbase + (size_t)(kt * 64 + r) * DK + ldq * 8;
            cp16(sb + 0 * KVBUF + so, Kh + g);
            cp16(sb + 1 * KVBUF + so, Vh + g);
        }
    };

    const int T = 2 * qi + 2;

    load_Q();
    load_tile(0, 0); CP_COMMIT();
    if (T > 1) { load_tile(1, 1); CP_COMMIT(); }
    if (T > 2) { load_tile(2, 2); CP_COMMIT(); }

    const int laneA = (lane & 15) * FPITCH + ((lane >> 4) & 1) * 8;
    const int laneB = ((lane & 7) + ((lane >> 4) & 1) * 8) * FPITCH + ((lane >> 3) & 1) * 8;
    const int laneV = ((lane & 7) + ((lane >> 3) & 1) * 8) * FPITCH + ((lane >> 4) & 1) * 8;

    uint32_t qhf[4][4];

    float oacc[8][4];
#pragma unroll
    for (int nf = 0; nf < 8; nf++)
#pragma unroll
        for (int j = 0; j < 4; j++) oacc[nf][j] = 0.0f;
    float m0r = -1e30f, m1r = -1e30f, l0r = 0.0f, l1r = 0.0f;

    const int ktmax_w = 2 * qi + (w >> 2);
    const float cs = 0.18033688f;         // (1/8) * log2(e)
    const int rbase = q0 + w * 16 + (lane >> 2);
    const int cbase = (lane & 3) * 2;

    for (int kt = 0; kt < T; kt++) {
        int rem = T - 1 - kt;
        if (rem >= 2)      { CP_WAIT(2); }
        else if (rem == 1) { CP_WAIT(1); }
        else               { CP_WAIT(0); }
        __syncthreads();

        if (kt == 0) {
#pragma unroll
            for (int ks = 0; ks < 4; ks++) {
                uint32_t a = smb + OFF_QH + (uint32_t)((w * 16) * FPITCH + ks * 16 + laneA) * 2;
                ldsm4(qhf[ks], a);
            }
        }
        if (kt + 3 < T) {
            load_tile(kt + 3, (kt + 3) & 3);
            CP_COMMIT();
        }

        if (kt <= ktmax_w) {
            const uint32_t kvb = smb + OFF_KV + (uint32_t)(kt & 3) * KVSTG;

            // ---- S = Q K^T (1 pass) ----
            float sacc[8][4];
#pragma unroll
            for (int nf = 0; nf < 8; nf++)
#pragma unroll
                for (int j = 0; j < 4; j++) sacc[nf][j] = 0.0f;

#pragma unroll
            for (int ks = 0; ks < 4; ks++) {
                uint32_t kb[16];
#pragma unroll
                for (int nb = 0; nb < 4; nb++) {
                    uint32_t a = kvb + (uint32_t)((nb * 16) * FPITCH + ks * 16 + laneB) * 2;
                    ldsm4(kb + nb * 4, a);
                }
#pragma unroll
                for (int nf = 0; nf < 8; nf++) {
                    int bi = (nf >> 1) * 4 + (nf & 1) * 2;
                    mma16816(sacc[nf], qhf[ks], kb[bi], kb[bi + 1]);
                }
            }

            // ---- scale (+ causal mask on diagonal tiles) ----
            const bool need_mask = (kt * 64 + 63 > q0 + w * 16);
            if (need_mask) {
#pragma unroll
                for (int nf = 0; nf < 8; nf++) {
#pragma unroll
                    for (int j = 0; j < 4; j++) {
                        int col = kt * 64 + nf * 8 + cbase + (j & 1);
                        int row = rbase + ((j >> 1) << 3);
                        sacc[nf][j] = (col <= row) ? sacc[nf][j] * cs : -1e30f;
                    }
                }
            } else {
#pragma unroll
                for (int nf = 0; nf < 8; nf++)
#pragma unroll
                    for (int j = 0; j < 4; j++) sacc[nf][j] *= cs;
            }

            // ---- online softmax (base-2) ----
            float mx0 = -1e30f, mx1 = -1e30f;
#pragma unroll
            for (int nf = 0; nf < 8; nf++) {
                mx0 = fmaxf(mx0, fmaxf(sacc[nf][0], sacc[nf][1]));
                mx1 = fmaxf(mx1, fmaxf(sacc[nf][2], sacc[nf][3]));
            }
            mx0 = fmaxf(mx0, __shfl_xor_sync(0xffffffffu, mx0, 1));
            mx0 = fmaxf(mx0, __shfl_xor_sync(0xffffffffu, mx0, 2));
            mx1 = fmaxf(mx1, __shfl_xor_sync(0xffffffffu, mx1, 1));
            mx1 = fmaxf(mx1, __shfl_xor_sync(0xffffffffu, mx1, 2));

            float mn0 = fmaxf(m0r, mx0), mn1 = fmaxf(m1r, mx1);
            float c0 = ex2(m0r - mn0), c1 = ex2(m1r - mn1);
            m0r = mn0; m1r = mn1;

            uint32_t pHa[8], pHb[8];
            float ls0 = 0.0f, ls1 = 0.0f;
#pragma unroll
            for (int nf = 0; nf < 8; nf++) {
                float p0 = ex2(sacc[nf][0] - mn0);
                float p1 = ex2(sacc[nf][1] - mn0);
                float p2 = ex2(sacc[nf][2] - mn1);
                float p3 = ex2(sacc[nf][3] - mn1);
                ls0 += p0 + p1;
                ls1 += p2 + p3;
                __half2 h01 = __floats2half2_rn(p0, p1);
                __half2 h23 = __floats2half2_rn(p2, p3);
                pHa[nf] = *(uint32_t*)&h01;
                pHb[nf] = *(uint32_t*)&h23;
            }
            ls0 += __shfl_xor_sync(0xffffffffu, ls0, 1);
            ls0 += __shfl_xor_sync(0xffffffffu, ls0, 2);
            ls1 += __shfl_xor_sync(0xffffffffu, ls1, 1);
            ls1 += __shfl_xor_sync(0xffffffffu, ls1, 2);
            l0r = l0r * c0 + ls0;
            l1r = l1r * c1 + ls1;
#pragma unroll
            for (int nf = 0; nf < 8; nf++) {
                oacc[nf][0] *= c0; oacc[nf][1] *= c0;
                oacc[nf][2] *= c1; oacc[nf][3] *= c1;
            }

            // ---- O += P V (1 pass) ----
            const uint32_t vbb = kvb + KVBUF;
#pragma unroll
            for (int ks = 0; ks < 4; ks++) {
                uint32_t vb[16];
#pragma unroll
                for (int nb = 0; nb < 4; nb++) {
                    uint32_t a = vbb + (uint32_t)((ks * 16) * FPITCH + nb * 16 + laneV) * 2;
                    ldsm4t(vb + nb * 4, a);
                }
                uint32_t pa[4] = { pHa[2 * ks], pHb[2 * ks], pHa[2 * ks + 1], pHb[2 * ks + 1] };
#pragma unroll
                for (int nf = 0; nf < 8; nf++) {
                    int bi = (nf >> 1) * 4 + (nf & 1) * 2;
                    mma16816(oacc[nf], pa, vb[bi], vb[bi + 1]);
                }
            }
        }
    }

    // ---- epilogue: write fp16 context [B,S,1024] ----
    const float inv0 = 1.0f / l0r, inv1 = 1.0f / l1r;
    const int b = bh >> 4, h = bh & 15;
    const int s0 = q0 + w * 16 + (lane >> 2);
#pragma unroll
    for (int nf = 0; nf < 8; nf++) {
        int col = h * DK + nf * 8 + cbase;
#pragma unroll
        for (int hh = 0; hh < 2; hh++) {
            int s = s0 + hh * 8;
            float vx = oacc[nf][hh * 2 + 0] * (hh ? inv1 : inv0);
            float vy = oacc[nf][hh * 2 + 1] * (hh ? inv1 : inv0);
            size_t idx = ((size_t)(b * S_LEN + s)) * DMODEL + col;
            *(__half2*)(Oh + idx) = __floats2half2_rn(vx, vy);
        }
    }
}

// ===========================================================================
extern "C" void kernel_launch(void* const* d_in, const int* in_sizes, int n_in,
                              void* d_out, int out_size)
{
    const float* query = (const float*)d_in[0];
    const float* key   = (const float*)d_in[1];
    const float* value = (const float*)d_in[2];
    // d_in[3] = causal mask — handled analytically.
    const float* Wq = (const float*)d_in[4];
    const float* bq = (const float*)d_in[5];
    const float* Wk = (const float*)d_in[6];
    const float* bk = (const float*)d_in[7];
    const float* Wv = (const float*)d_in[8];
    const float* bv = (const float*)d_in[9];
    const float* Wo = (const float*)d_in[10];
    const float* bo = (const float*)d_in[11];
    float* out = (float*)d_out;

    __half *Qh, *Kh, *Vh, *Ah, *Wh, *Wl;
    cudaGetSymbolAddress((void**)&Qh, g_Qh);
    cudaGetSymbolAddress((void**)&Kh, g_Kh);
    cudaGetSymbolAddress((void**)&Vh, g_Vh);
    cudaGetSymbolAddress((void**)&Ah, g_Ah);
    cudaGetSymbolAddress((void**)&Wh, g_Wh);
    cudaGetSymbolAddress((void**)&Wl, g_Wl);

    cudaFuncSetAttribute(proj_gemm_mma,
                         cudaFuncAttributeMaxDynamicSharedMemorySize, SMEM_GEMM);
    cudaFuncSetAttribute(flash_mma,
                         cudaFuncAttributeMaxDynamicSharedMemorySize, SMEM_FLASH);

    const int n4A = MTOT * DMODEL / 4;
    const int n4W = DMODEL * DMODEL / 4;
    dim3 gg(DMODEL / TILE_N, MTOT / TILE_M);   // (8, 32)

    // Q projection
    split_f32<<<n4A / 256, 256>>>((const float4*)query, (uint2*)Ah, nullptr, n4A);
    split_f32<<<n4W / 256, 256>>>((const float4*)Wq, (uint2*)Wh, (uint2*)Wl, n4W);
    proj_gemm_mma<<<gg, 256, SMEM_GEMM>>>(Ah, Wh, Wl, bq, nullptr, Qh, 1);
    // K projection
    split_f32<<<n4A / 256, 256>>>((const float4*)key, (uint2*)Ah, nullptr, n4A);
    split_f32<<<n4W / 256, 256>>>((const float4*)Wk, (uint2*)Wh, (uint2*)Wl, n4W);
    proj_gemm_mma<<<gg, 256, SMEM_GEMM>>>(Ah, Wh, Wl, bk, nullptr, Kh, 1);
    // V projection
    split_f32<<<n4A / 256, 256>>>((const float4*)value, (uint2*)Ah, nullptr, n4A);
    split_f32<<<n4W / 256, 256>>>((const float4*)Wv, (uint2*)Wh, (uint2*)Wl, n4W);
    proj_gemm_mma<<<gg, 256, SMEM_GEMM>>>(Ah, Wh, Wl, bv, nullptr, Vh, 1);

    // attention: writes fp16 context into Ah
    flash_mma<<<dim3(16, BATCH * NHEAD), 256, SMEM_FLASH>>>(Qh, Kh, Vh, Ah);

    // out = Ctx @ Wo^T + bo (fp32 out)
    split_f32<<<n4W / 256, 256>>>((const float4*)Wo, (uint2*)Wh, (uint2*)Wl, n4W);
    proj_gemm_mma<<<gg, 256, SMEM_GEMM>>>(Ah, Wh, Wl, bo, out, nullptr, 0);
}

// round 8
// speedup vs baseline: 6.6566x; 1.1475x over previous
#include <cuda_runtime.h>
#include <cuda_fp16.h>
#include <cstdint>

#define S_LEN  2048
#define DMODEL 1024
#define NHEAD  16
#define DK     64
#define BATCH  4
#define MTOT   (BATCH * S_LEN)     // 8192

// ---------------- scratch (module-scope device memory) ----------------
__device__ __half g_Aq[MTOT * DMODEL];   // query f16 (later: ctx f16)
__device__ __half g_Ak[MTOT * DMODEL];   // key f16
__device__ __half g_Av[MTOT * DMODEL];   // value f16
__device__ __half g_Qh[BATCH * NHEAD * S_LEN * DK];
__device__ __half g_Kh[BATCH * NHEAD * S_LEN * DK];
__device__ __half g_Vh[BATCH * NHEAD * S_LEN * DK];
__device__ __half g_Wqh[DMODEL * DMODEL];
__device__ __half g_Wkh[DMODEL * DMODEL];
__device__ __half g_Wvh[DMODEL * DMODEL];
__device__ __half g_Wvl[DMODEL * DMODEL];
__device__ __half g_Woh[DMODEL * DMODEL];
__device__ __half g_Wol[DMODEL * DMODEL];

// ---------------- PTX helpers (baseline PTX only) ----------------------
__device__ __forceinline__ uint32_t cvta_smem(const void* p) {
    uint32_t a;
    asm("{ .reg .u64 t; cvta.to.shared.u64 t, %1; cvt.u32.u64 %0, t; }"
        : "=r"(a) : "l"(p));
    return a;
}
__device__ __forceinline__ void cp16(uint32_t dst, const void* src) {
    asm volatile("cp.async.cg.shared.global [%0], [%1], 16;"
                 :: "r"(dst), "l"(src));
}
#define CP_COMMIT() asm volatile("cp.async.commit_group;" ::: "memory")
#define CP_WAIT(n)  asm volatile("cp.async.wait_group %0;" :: "n"(n) : "memory")

__device__ __forceinline__ void ldsm4(uint32_t* r, uint32_t addr) {
    asm volatile("ldmatrix.sync.aligned.m8n8.x4.shared.b16 {%0,%1,%2,%3}, [%4];"
                 : "=r"(r[0]), "=r"(r[1]), "=r"(r[2]), "=r"(r[3]) : "r"(addr));
}
__device__ __forceinline__ void ldsm4t(uint32_t* r, uint32_t addr) {
    asm volatile("ldmatrix.sync.aligned.m8n8.x4.trans.shared.b16 {%0,%1,%2,%3}, [%4];"
                 : "=r"(r[0]), "=r"(r[1]), "=r"(r[2]), "=r"(r[3]) : "r"(addr));
}
__device__ __forceinline__ void mma16816(float* d, const uint32_t* a,
                                         uint32_t b0, uint32_t b1) {
    asm volatile(
        "mma.sync.aligned.m16n8k16.row.col.f32.f16.f16.f32 "
        "{%0,%1,%2,%3}, {%4,%5,%6,%7}, {%8,%9}, {%0,%1,%2,%3};"
        : "+f"(d[0]), "+f"(d[1]), "+f"(d[2]), "+f"(d[3])
        : "r"(a[0]), "r"(a[1]), "r"(a[2]), "r"(a[3]), "r"(b0), "r"(b1));
}
__device__ __forceinline__ float ex2(float x) {
    float y;
    asm("ex2.approx.f32 %0, %1;" : "=f"(y) : "f"(x));
    return y;
}

__device__ __forceinline__ uint2 pack_hi(float4 v) {
    __half h0 = __float2half_rn(v.x), h1 = __float2half_rn(v.y);
    __half h2 = __float2half_rn(v.z), h3 = __float2half_rn(v.w);
    uint2 H;
    H.x = (uint32_t)__half_as_ushort(h0) | ((uint32_t)__half_as_ushort(h1) << 16);
    H.y = (uint32_t)__half_as_ushort(h2) | ((uint32_t)__half_as_ushort(h3) << 16);
    return H;
}
__device__ __forceinline__ uint2 pack_lo(float4 v, uint2 H) {
    __half h0 = __ushort_as_half((unsigned short)(H.x & 0xffff));
    __half h1 = __ushort_as_half((unsigned short)(H.x >> 16));
    __half h2 = __ushort_as_half((unsigned short)(H.y & 0xffff));
    __half h3 = __ushort_as_half((unsigned short)(H.y >> 16));
    __half l0 = __float2half_rn(v.x - __half2float(h0));
    __half l1 = __float2half_rn(v.y - __half2float(h1));
    __half l2 = __float2half_rn(v.z - __half2float(h2));
    __half l3 = __float2half_rn(v.w - __half2float(h3));
    uint2 L;
    L.x = (uint32_t)__half_as_ushort(l0) | ((uint32_t)__half_as_ushort(l1) << 16);
    L.y = (uint32_t)__half_as_ushort(l2) | ((uint32_t)__half_as_ushort(l3) << 16);
    return L;
}

// ---------------- single consolidated split kernel ----------------------
// blocks [0, 24576): activations q/k/v -> f16 hi
// blocks [24576, 28672): weights wq,wk (hi only), wv,wo (hi+lo)
#define ACT_BLKS  8192        // (MTOT*DMODEL/4)/256
#define W_BLKS    1024        // (DMODEL*DMODEL/4)/256
#define SPLIT_GRID (3 * ACT_BLKS + 4 * W_BLKS)

__global__ __launch_bounds__(256) void split_all(
    const float4* __restrict__ q, const float4* __restrict__ k,
    const float4* __restrict__ v,
    const float4* __restrict__ wq, const float4* __restrict__ wk,
    const float4* __restrict__ wv, const float4* __restrict__ wo,
    uint2* __restrict__ aq, uint2* __restrict__ ak, uint2* __restrict__ av,
    uint2* __restrict__ wqh, uint2* __restrict__ wkh,
    uint2* __restrict__ wvh, uint2* __restrict__ wvl,
    uint2* __restrict__ woh, uint2* __restrict__ wol)
{
    const int b = blockIdx.x, t = threadIdx.x;
    if (b < 3 * ACT_BLKS) {
        const int which = b / ACT_BLKS;
        const int i = (b % ACT_BLKS) * 256 + t;
        const float4* src = which == 0 ? q : (which == 1 ? k : v);
        uint2* dst = which == 0 ? aq : (which == 1 ? ak : av);
        dst[i] = pack_hi(src[i]);
    } else {
        const int wb = b - 3 * ACT_BLKS;
        const int which = wb / W_BLKS;
        const int i = (wb % W_BLKS) * 256 + t;
        if (which == 0) {
            wqh[i] = pack_hi(wq[i]);
        } else if (which == 1) {
            wkh[i] = pack_hi(wk[i]);
        } else if (which == 2) {
            float4 val = wv[i];
            uint2 H = pack_hi(val);
            wvh[i] = H;
            wvl[i] = pack_lo(val, H);
        } else {
            float4 val = wo[i];
            uint2 H = pack_hi(val);
            woh[i] = H;
            wol[i] = pack_lo(val, H);
        }
    }
}

// ---------------- HMMA projection GEMM (256x128 tile) -------------------
// C = A[M,1024] @ W[1024,1024]^T + bias.  A fp16; W fp16 hi (+lo if NPASS=2).
// remap=1: head-split [B,H,S,DK] fp16; remap=0: fp32 [M,1024].
// 8 warps, warp tile 64x64, K-chunk 32, 4-stage cp.async pipeline.
#define TILE_M 256
#define TILE_N 128
#define KCH    32
#define NC     (DMODEL / KCH)  // 32
#define PITCH  40              // halves per smem row (80B)
#define AH_OFF 0
#define BH_OFF 20480
#define BL_OFF 30720
#define STG_B  40960
#define SMEM_GEMM (4 * STG_B)  // 163840

template <int NPASS>
__global__ __launch_bounds__(256) void proj_gemm_mma(
    const __half* __restrict__ Ahg,
    const __half* __restrict__ Whg, const __half* __restrict__ Wlg,
    const float* __restrict__ bias, float* __restrict__ Cf,
    __half* __restrict__ Ch, int remap)
{
    extern __shared__ char sm[];
    const uint32_t smb = cvta_smem(sm);
    const int tid = threadIdx.x;
    const int wid = tid >> 5, lane = tid & 31;
    const int wm = wid & 3;
    const int wn = wid >> 2;
    const int m0 = blockIdx.y * TILE_M;
    const int n0 = blockIdx.x * TILE_N;

    const int laneA = (lane & 15) * PITCH + ((lane >> 4) & 1) * 8;
    const int laneB = ((lane & 7) + ((lane >> 4) & 1) * 8) * PITCH + ((lane >> 3) & 1) * 8;

    auto load_chunk = [&](int c, int stage) {
        const uint32_t sbase = smb + (uint32_t)stage * STG_B;
#pragma unroll
        for (int i = 0; i < 4; i++) {
            int slot = tid + i * 256;
            int row = slot >> 2, quad = slot & 3;
            uint32_t soff = (uint32_t)row * 80u + (uint32_t)quad * 16u;
            size_t goff = (size_t)(m0 + row) * DMODEL + c * KCH + quad * 8;
            cp16(sbase + AH_OFF + soff, Ahg + goff);
        }
#pragma unroll
        for (int i = 0; i < 2; i++) {
            int slot = tid + i * 256;
            int row = slot >> 2, quad = slot & 3;
            uint32_t soff = (uint32_t)row * 80u + (uint32_t)quad * 16u;
            size_t goff = (size_t)(n0 + row) * DMODEL + c * KCH + quad * 8;
            cp16(sbase + BH_OFF + soff, Whg + goff);
            if (NPASS == 2) cp16(sbase + BL_OFF + soff, Wlg + goff);
        }
    };

    float acc[4][8][4] = {};

    load_chunk(0, 0); CP_COMMIT();
    load_chunk(1, 1); CP_COMMIT();
    load_chunk(2, 2); CP_COMMIT();

    for (int c = 0; c < NC; c++) {
        if (c < NC - 2)       { CP_WAIT(2); }
        else if (c == NC - 2) { CP_WAIT(1); }
        else                  { CP_WAIT(0); }
        __syncthreads();
        if (c + 3 < NC) {
            load_chunk(c + 3, (c + 3) & 3);
            CP_COMMIT();
        }

        const uint32_t sbase = smb + (uint32_t)(c & 3) * STG_B;

#pragma unroll
        for (int ks = 0; ks < 2; ks++) {
            const int kk = ks * 16;
            uint32_t ah[4][4], bh[16], bl[16];
#pragma unroll
            for (int mf = 0; mf < 4; mf++) {
                uint32_t idx = (uint32_t)((wm * 64 + mf * 16) * PITCH + kk + laneA) * 2;
                ldsm4(ah[mf], sbase + AH_OFF + idx);
            }
#pragma unroll
            for (int nf2 = 0; nf2 < 4; nf2++) {
                uint32_t idx = (uint32_t)((wn * 64 + nf2 * 16) * PITCH + kk + laneB) * 2;
                ldsm4(bh + nf2 * 4, sbase + BH_OFF + idx);
                if (NPASS == 2) ldsm4(bl + nf2 * 4, sbase + BL_OFF + idx);
            }
#pragma unroll
            for (int mf = 0; mf < 4; mf++)
#pragma unroll
                for (int nf = 0; nf < 8; nf++) {
                    int bi = (nf >> 1) * 4 + (nf & 1) * 2;
                    mma16816(acc[mf][nf], ah[mf], bh[bi], bh[bi + 1]);
                }
            if (NPASS == 2) {
#pragma unroll
                for (int mf = 0; mf < 4; mf++)
#pragma unroll
                    for (int nf = 0; nf < 8; nf++) {
                        int bi = (nf >> 1) * 4 + (nf & 1) * 2;
                        mma16816(acc[mf][nf], ah[mf], bl[bi], bl[bi + 1]);
                    }
            }
        }
    }

    // epilogue
#pragma unroll
    for (int mf = 0; mf < 4; mf++) {
#pragma unroll
        for (int nf = 0; nf < 8; nf++) {
            int m = m0 + wm * 64 + mf * 16 + (lane >> 2);
            int n = n0 + wn * 64 + nf * 8 + (lane & 3) * 2;
            float bx = bias[n], by = bias[n + 1];
#pragma unroll
            for (int hh = 0; hh < 2; hh++) {
                int mm = m + hh * 8;
                float vx = acc[mf][nf][hh * 2 + 0] + bx;
                float vy = acc[mf][nf][hh * 2 + 1] + by;
                if (remap) {
                    int b = mm >> 11, s = mm & (S_LEN - 1);
                    int h = n >> 6, d = n & (DK - 1);
                    size_t idx = ((size_t)((b << 4) + h) * S_LEN + s) * DK + d;
                    *(__half2*)(Ch + idx) = __floats2half2_rn(vx, vy);
                } else {
                    float2 v; v.x = vx; v.y = vy;
                    *(float2*)(Cf + (size_t)mm * DMODEL + n) = v;
                }
            }
        }
    }
}

// ---------------- HMMA causal flash attention (paired q-tiles) ----------
// Each CTA processes q-tiles (pair, 15-pair) sequentially -> uniform work.
// BQ=128 (8 warps x m16), BKV=64, d=64. QK/PV 1-pass fp16.
#define FPITCH 72                          // halves
#define QBUF   (128 * FPITCH * 2)          // 18432 B
#define KVBUF  (64 * FPITCH * 2)           // 9216 B
#define OFF_QH 0
#define OFF_KV QBUF
#define KVSTG  (2 * KVBUF)                 // 18432 (K + V)
#define SMEM_FLASH (OFF_KV + 4 * KVSTG)    // 92160

__global__ __launch_bounds__(256, 1) void flash_mma(
    const __half* __restrict__ Qh,
    const __half* __restrict__ Kh, const __half* __restrict__ Vh,
    __half* __restrict__ Oh)
{
    extern __shared__ char sm[];
    const uint32_t smb = cvta_smem(sm);
    const int tid = threadIdx.x;
    const int w = tid >> 5, lane = tid & 31;
    const int pair = blockIdx.x;          // 0..7
    const int bh = blockIdx.y;            // 0..63

    const size_t seqbase = (size_t)bh * S_LEN * DK;

    const int ldrow = tid >> 3;           // 0..31
    const int ldq = tid & 7;

    const int laneA = (lane & 15) * FPITCH + ((lane >> 4) & 1) * 8;
    const int laneB = ((lane & 7) + ((lane >> 4) & 1) * 8) * FPITCH + ((lane >> 3) & 1) * 8;
    const int laneV = ((lane & 7) + ((lane >> 3) & 1) * 8) * FPITCH + ((lane >> 4) & 1) * 8;

    const float cs = 0.18033688f;         // (1/8) * log2(e)
    const int b = bh >> 4, h = bh & 15;
    const int cbase = (lane & 3) * 2;

    for (int ph = 0; ph < 2; ph++) {
        const int qi = ph == 0 ? (15 - pair) : pair;   // heavy tile first
        const int q0 = qi * 128;
        const int T = 2 * qi + 2;
        const int ktmax_w = 2 * qi + (w >> 2);
        const int rbase = q0 + w * 16 + (lane >> 2);

        if (ph == 1) __syncthreads();     // protect smem reuse across phases

        // load Q tile + prime KV pipeline
#pragma unroll
        for (int i = 0; i < 4; i++) {
            int r = ldrow + i * 32;
            uint32_t so = (uint32_t)r * (FPITCH * 2) + (uint32_t)ldq * 16u;
            size_t g = seqbase + (size_t)(q0 + r) * DK + ldq * 8;
            cp16(smb + OFF_QH + so, Qh + g);
        }
        auto load_tile = [&](int kt, int stage) {
            const uint32_t sb = smb + OFF_KV + (uint32_t)stage * KVSTG;
#pragma unroll
            for (int i = 0; i < 2; i++) {
                int r = ldrow + i * 32;
                uint32_t so = (uint32_t)r * (FPITCH * 2) + (uint32_t)ldq * 16u;
                size_t g = seqbase + (size_t)(kt * 64 + r) * DK + ldq * 8;
                cp16(sb + 0 * KVBUF + so, Kh + g);
                cp16(sb + 1 * KVBUF + so, Vh + g);
            }
        };
        load_tile(0, 0); CP_COMMIT();
        if (T > 1) { load_tile(1, 1); CP_COMMIT(); }
        if (T > 2) { load_tile(2, 2); CP_COMMIT(); }

        uint32_t qhf[4][4];
        float oacc[8][4];
#pragma unroll
        for (int nf = 0; nf < 8; nf++)
#pragma unroll
            for (int j = 0; j < 4; j++) oacc[nf][j] = 0.0f;
        float m0r = -1e30f, m1r = -1e30f, l0r = 0.0f, l1r = 0.0f;

        for (int kt = 0; kt < T; kt++) {
            int rem = T - 1 - kt;
            if (rem >= 2)      { CP_WAIT(2); }
            else if (rem == 1) { CP_WAIT(1); }
            else               { CP_WAIT(0); }
            __syncthreads();

            if (kt == 0) {
#pragma unroll
                for (int ks = 0; ks < 4; ks++) {
                    uint32_t a = smb + OFF_QH +
                        (uint32_t)((w * 16) * FPITCH + ks * 16 + laneA) * 2;
                    ldsm4(qhf[ks], a);
                }
            }
            if (kt + 3 < T) {
                load_tile(kt + 3, (kt + 3) & 3);
                CP_COMMIT();
            }

            if (kt <= ktmax_w) {
                const uint32_t kvb = smb + OFF_KV + (uint32_t)(kt & 3) * KVSTG;

                // ---- S = Q K^T ----
                float sacc[8][4];
#pragma unroll
                for (int nf = 0; nf < 8; nf++)
#pragma unroll
                    for (int j = 0; j < 4; j++) sacc[nf][j] = 0.0f;

#pragma unroll
                for (int ks = 0; ks < 4; ks++) {
                    uint32_t kb[16];
#pragma unroll
                    for (int nb = 0; nb < 4; nb++) {
                        uint32_t a = kvb +
                            (uint32_t)((nb * 16) * FPITCH + ks * 16 + laneB) * 2;
                        ldsm4(kb + nb * 4, a);
                    }
#pragma unroll
                    for (int nf = 0; nf < 8; nf++) {
                        int bi = (nf >> 1) * 4 + (nf & 1) * 2;
                        mma16816(sacc[nf], qhf[ks], kb[bi], kb[bi + 1]);
                    }
                }

                // ---- scale (+ causal mask on diagonal tiles) ----
                const bool need_mask = (kt * 64 + 63 > q0 + w * 16);
                if (need_mask) {
#pragma unroll
                    for (int nf = 0; nf < 8; nf++) {
#pragma unroll
                        for (int j = 0; j < 4; j++) {
                            int col = kt * 64 + nf * 8 + cbase + (j & 1);
                            int row = rbase + ((j >> 1) << 3);
                            sacc[nf][j] = (col <= row) ? sacc[nf][j] * cs : -1e30f;
                        }
                    }
                } else {
#pragma unroll
                    for (int nf = 0; nf < 8; nf++)
#pragma unroll
                        for (int j = 0; j < 4; j++) sacc[nf][j] *= cs;
                }

                // ---- online softmax (base-2) ----
                float mx0 = -1e30f, mx1 = -1e30f;
#pragma unroll
                for (int nf = 0; nf < 8; nf++) {
                    mx0 = fmaxf(mx0, fmaxf(sacc[nf][0], sacc[nf][1]));
                    mx1 = fmaxf(mx1, fmaxf(sacc[nf][2], sacc[nf][3]));
                }
                mx0 = fmaxf(mx0, __shfl_xor_sync(0xffffffffu, mx0, 1));
                mx0 = fmaxf(mx0, __shfl_xor_sync(0xffffffffu, mx0, 2));
                mx1 = fmaxf(mx1, __shfl_xor_sync(0xffffffffu, mx1, 1));
                mx1 = fmaxf(mx1, __shfl_xor_sync(0xffffffffu, mx1, 2));

                float mn0 = fmaxf(m0r, mx0), mn1 = fmaxf(m1r, mx1);
                float c0 = ex2(m0r - mn0), c1 = ex2(m1r - mn1);
                m0r = mn0; m1r = mn1;

                uint32_t pHa[8], pHb[8];
                float ls0 = 0.0f, ls1 = 0.0f;
#pragma unroll
                for (int nf = 0; nf < 8; nf++) {
                    float p0 = ex2(sacc[nf][0] - mn0);
                    float p1 = ex2(sacc[nf][1] - mn0);
                    float p2 = ex2(sacc[nf][2] - mn1);
                    float p3 = ex2(sacc[nf][3] - mn1);
                    ls0 += p0 + p1;
                    ls1 += p2 + p3;
                    __half2 h01 = __floats2half2_rn(p0, p1);
                    __half2 h23 = __floats2half2_rn(p2, p3);
                    pHa[nf] = *(uint32_t*)&h01;
                    pHb[nf] = *(uint32_t*)&h23;
                }
                ls0 += __shfl_xor_sync(0xffffffffu, ls0, 1);
                ls0 += __shfl_xor_sync(0xffffffffu, ls0, 2);
                ls1 += __shfl_xor_sync(0xffffffffu, ls1, 1);
                ls1 += __shfl_xor_sync(0xffffffffu, ls1, 2);
                l0r = l0r * c0 + ls0;
                l1r = l1r * c1 + ls1;
#pragma unroll
                for (int nf = 0; nf < 8; nf++) {
                    oacc[nf][0] *= c0; oacc[nf][1] *= c0;
                    oacc[nf][2] *= c1; oacc[nf][3] *= c1;
                }

                // ---- O += P V ----
                const uint32_t vbb = kvb + KVBUF;
#pragma unroll
                for (int ks = 0; ks < 4; ks++) {
                    uint32_t vb[16];
#pragma unroll
                    for (int nb = 0; nb < 4; nb++) {
                        uint32_t a = vbb +
                            (uint32_t)((ks * 16) * FPITCH + nb * 16 + laneV) * 2;
                        ldsm4t(vb + nb * 4, a);
                    }
                    uint32_t pa[4] = { pHa[2 * ks], pHb[2 * ks],
                                       pHa[2 * ks + 1], pHb[2 * ks + 1] };
#pragma unroll
                    for (int nf = 0; nf < 8; nf++) {
                        int bi = (nf >> 1) * 4 + (nf & 1) * 2;
                        mma16816(oacc[nf], pa, vb[bi], vb[bi + 1]);
                    }
                }
            }
        }

        // ---- epilogue: write fp16 context [B,S,1024] for this q-tile ----
        const float inv0 = 1.0f / l0r, inv1 = 1.0f / l1r;
        const int s0 = q0 + w * 16 + (lane >> 2);
#pragma unroll
        for (int nf = 0; nf < 8; nf++) {
            int col = h * DK + nf * 8 + cbase;
#pragma unroll
            for (int hh = 0; hh < 2; hh++) {
                int s = s0 + hh * 8;
                float vx = oacc[nf][hh * 2 + 0] * (hh ? inv1 : inv0);
                float vy = oacc[nf][hh * 2 + 1] * (hh ? inv1 : inv0);
                size_t idx = ((size_t)(b * S_LEN + s)) * DMODEL + col;
                *(__half2*)(Oh + idx) = __floats2half2_rn(vx, vy);
            }
        }
    }
}

// ===========================================================================
extern "C" void kernel_launch(void* const* d_in, const int* in_sizes, int n_in,
                              void* d_out, int out_size)
{
    const float* query = (const float*)d_in[0];
    const float* key   = (const float*)d_in[1];
    const float* value = (const float*)d_in[2];
    // d_in[3] = causal mask — handled analytically.
    const float* Wq = (const float*)d_in[4];
    const float* bq = (const float*)d_in[5];
    const float* Wk = (const float*)d_in[6];
    const float* bk = (const float*)d_in[7];
    const float* Wv = (const float*)d_in[8];
    const float* bv = (const float*)d_in[9];
    const float* Wo = (const float*)d_in[10];
    const float* bo = (const float*)d_in[11];
    float* out = (float*)d_out;

    __half *Aq, *Ak, *Av, *Qh, *Kh, *Vh;
    __half *Wqh, *Wkh, *Wvh, *Wvl, *Woh, *Wol;
    cudaGetSymbolAddress((void**)&Aq, g_Aq);
    cudaGetSymbolAddress((void**)&Ak, g_Ak);
    cudaGetSymbolAddress((void**)&Av, g_Av);
    cudaGetSymbolAddress((void**)&Qh, g_Qh);
    cudaGetSymbolAddress((void**)&Kh, g_Kh);
    cudaGetSymbolAddress((void**)&Vh, g_Vh);
    cudaGetSymbolAddress((void**)&Wqh, g_Wqh);
    cudaGetSymbolAddress((void**)&Wkh, g_Wkh);
    cudaGetSymbolAddress((void**)&Wvh, g_Wvh);
    cudaGetSymbolAddress((void**)&Wvl, g_Wvl);
    cudaGetSymbolAddress((void**)&Woh, g_Woh);
    cudaGetSymbolAddress((void**)&Wol, g_Wol);

    cudaFuncSetAttribute(proj_gemm_mma<1>,
                         cudaFuncAttributeMaxDynamicSharedMemorySize, SMEM_GEMM);
    cudaFuncSetAttribute(proj_gemm_mma<2>,
                         cudaFuncAttributeMaxDynamicSharedMemorySize, SMEM_GEMM);
    cudaFuncSetAttribute(flash_mma,
                         cudaFuncAttributeMaxDynamicSharedMemorySize, SMEM_FLASH);

    dim3 gg(DMODEL / TILE_N, MTOT / TILE_M);   // (8, 32)

    // one consolidated conversion pass
    split_all<<<SPLIT_GRID, 256>>>(
        (const float4*)query, (const float4*)key, (const float4*)value,
        (const float4*)Wq, (const float4*)Wk, (const float4*)Wv, (const float4*)Wo,
        (uint2*)Aq, (uint2*)Ak, (uint2*)Av,
        (uint2*)Wqh, (uint2*)Wkh,
        (uint2*)Wvh, (uint2*)Wvl, (uint2*)Woh, (uint2*)Wol);

    // projections
    proj_gemm_mma<1><<<gg, 256, SMEM_GEMM>>>(Aq, Wqh, nullptr, bq, nullptr, Qh, 1);
    proj_gemm_mma<1><<<gg, 256, SMEM_GEMM>>>(Ak, Wkh, nullptr, bk, nullptr, Kh, 1);
    proj_gemm_mma<2><<<gg, 256, SMEM_GEMM>>>(Av, Wvh, Wvl, bv, nullptr, Vh, 1);

    // attention: writes fp16 context into Aq (query f16 no longer needed)
    flash_mma<<<dim3(8, BATCH * NHEAD), 256, SMEM_FLASH>>>(Qh, Kh, Vh, Aq);

    // out = Ctx @ Wo^T + bo (fp32 out)
    proj_gemm_mma<2><<<gg, 256, SMEM_GEMM>>>(Aq, Woh, Wol, bo, out, nullptr, 0);
}

// round 9
// speedup vs baseline: 7.9375x; 1.1924x over previous
#include <cuda_runtime.h>
#include <cuda_fp16.h>
#include <cstdint>

#define S_LEN  2048
#define DMODEL 1024
#define NHEAD  16
#define DK     64
#define BATCH  4
#define MTOT   (BATCH * S_LEN)     // 8192

// ---------------- scratch (module-scope device memory) ----------------
__device__ __half g_Aq[MTOT * DMODEL];   // query f16 (later: ctx f16)
__device__ __half g_Ak[MTOT * DMODEL];   // key f16
__device__ __half g_Av[MTOT * DMODEL];   // value f16
__device__ __half g_Qh[BATCH * NHEAD * S_LEN * DK];
__device__ __half g_Kh[BATCH * NHEAD * S_LEN * DK];
__device__ __half g_Vh[BATCH * NHEAD * S_LEN * DK];
__device__ __half g_Wqh[DMODEL * DMODEL];
__device__ __half g_Wkh[DMODEL * DMODEL];
__device__ __half g_Wvh[DMODEL * DMODEL];
__device__ __half g_Woh[DMODEL * DMODEL];

// ---------------- PTX helpers (baseline PTX only) ----------------------
__device__ __forceinline__ uint32_t cvta_smem(const void* p) {
    uint32_t a;
    asm("{ .reg .u64 t; cvta.to.shared.u64 t, %1; cvt.u32.u64 %0, t; }"
        : "=r"(a) : "l"(p));
    return a;
}
__device__ __forceinline__ void cp16(uint32_t dst, const void* src) {
    asm volatile("cp.async.cg.shared.global [%0], [%1], 16;"
                 :: "r"(dst), "l"(src));
}
#define CP_COMMIT() asm volatile("cp.async.commit_group;" ::: "memory")
#define CP_WAIT(n)  asm volatile("cp.async.wait_group %0;" :: "n"(n) : "memory")

__device__ __forceinline__ void ldsm4(uint32_t* r, uint32_t addr) {
    asm volatile("ldmatrix.sync.aligned.m8n8.x4.shared.b16 {%0,%1,%2,%3}, [%4];"
                 : "=r"(r[0]), "=r"(r[1]), "=r"(r[2]), "=r"(r[3]) : "r"(addr));
}
__device__ __forceinline__ void ldsm4t(uint32_t* r, uint32_t addr) {
    asm volatile("ldmatrix.sync.aligned.m8n8.x4.trans.shared.b16 {%0,%1,%2,%3}, [%4];"
                 : "=r"(r[0]), "=r"(r[1]), "=r"(r[2]), "=r"(r[3]) : "r"(addr));
}
__device__ __forceinline__ void mma16816(float* d, const uint32_t* a,
                                         uint32_t b0, uint32_t b1) {
    asm volatile(
        "mma.sync.aligned.m16n8k16.row.col.f32.f16.f16.f32 "
        "{%0,%1,%2,%3}, {%4,%5,%6,%7}, {%8,%9}, {%0,%1,%2,%3};"
        : "+f"(d[0]), "+f"(d[1]), "+f"(d[2]), "+f"(d[3])
        : "r"(a[0]), "r"(a[1]), "r"(a[2]), "r"(a[3]), "r"(b0), "r"(b1));
}
__device__ __forceinline__ float ex2(float x) {
    float y;
    asm("ex2.approx.f32 %0, %1;" : "=f"(y) : "f"(x));
    return y;
}

__device__ __forceinline__ uint2 pack_hi(float4 v) {
    __half h0 = __float2half_rn(v.x), h1 = __float2half_rn(v.y);
    __half h2 = __float2half_rn(v.z), h3 = __float2half_rn(v.w);
    uint2 H;
    H.x = (uint32_t)__half_as_ushort(h0) | ((uint32_t)__half_as_ushort(h1) << 16);
    H.y = (uint32_t)__half_as_ushort(h2) | ((uint32_t)__half_as_ushort(h3) << 16);
    return H;
}

// ---------------- single consolidated split kernel ----------------------
// blocks [0, 24576): activations q/k/v -> f16
// blocks [24576, 28672): weights wq,wk,wv,wo -> f16
#define ACT_BLKS  8192        // (MTOT*DMODEL/4)/256
#define W_BLKS    1024        // (DMODEL*DMODEL/4)/256
#define SPLIT_GRID (3 * ACT_BLKS + 4 * W_BLKS)

__global__ __launch_bounds__(256) void split_all(
    const float4* __restrict__ q, const float4* __restrict__ k,
    const float4* __restrict__ v,
    const float4* __restrict__ wq, const float4* __restrict__ wk,
    const float4* __restrict__ wv, const float4* __restrict__ wo,
    uint2* __restrict__ aq, uint2* __restrict__ ak, uint2* __restrict__ av,
    uint2* __restrict__ wqh, uint2* __restrict__ wkh,
    uint2* __restrict__ wvh, uint2* __restrict__ woh)
{
    const int b = blockIdx.x, t = threadIdx.x;
    if (b < 3 * ACT_BLKS) {
        const int which = b / ACT_BLKS;
        const int i = (b % ACT_BLKS) * 256 + t;
        const float4* src = which == 0 ? q : (which == 1 ? k : v);
        uint2* dst = which == 0 ? aq : (which == 1 ? ak : av);
        dst[i] = pack_hi(src[i]);
    } else {
        const int wb = b - 3 * ACT_BLKS;
        const int which = wb / W_BLKS;
        const int i = (wb % W_BLKS) * 256 + t;
        const float4* src = which == 0 ? wq : (which == 1 ? wk
                          : (which == 2 ? wv : wo));
        uint2* dst = which == 0 ? wqh : (which == 1 ? wkh
                   : (which == 2 ? wvh : woh));
        dst[i] = pack_hi(src[i]);
    }
}

// ---------------- HMMA projection GEMM (256x128 tile, 1-pass) -----------
// C = A[M,1024] @ W[1024,1024]^T + bias.  A, W fp16.
// remap=1: head-split [B,H,S,DK] fp16; remap=0: fp32 [M,1024].
// 8 warps, warp tile 64x64, K-chunk 32, 4-stage cp.async pipeline.
#define TILE_M 256
#define TILE_N 128
#define KCH    32
#define NC     (DMODEL / KCH)  // 32
#define PITCH  40              // halves per smem row (80B)
#define AH_OFF 0
#define BH_OFF 20480
#define STG_B  30720
#define SMEM_GEMM (4 * STG_B)  // 122880

__global__ __launch_bounds__(256) void proj_gemm_mma(
    const __half* __restrict__ Ahg, const __half* __restrict__ Whg,
    const float* __restrict__ bias, float* __restrict__ Cf,
    __half* __restrict__ Ch, int remap)
{
    extern __shared__ char sm[];
    const uint32_t smb = cvta_smem(sm);
    const int tid = threadIdx.x;
    const int wid = tid >> 5, lane = tid & 31;
    const int wm = wid & 3;
    const int wn = wid >> 2;
    const int m0 = blockIdx.y * TILE_M;
    const int n0 = blockIdx.x * TILE_N;

    const int laneA = (lane & 15) * PITCH + ((lane >> 4) & 1) * 8;
    const int laneB = ((lane & 7) + ((lane >> 4) & 1) * 8) * PITCH + ((lane >> 3) & 1) * 8;

    auto load_chunk = [&](int c, int stage) {
        const uint32_t sbase = smb + (uint32_t)stage * STG_B;
#pragma unroll
        for (int i = 0; i < 4; i++) {
            int slot = tid + i * 256;
            int row = slot >> 2, quad = slot & 3;
            uint32_t soff = (uint32_t)row * 80u + (uint32_t)quad * 16u;
            size_t goff = (size_t)(m0 + row) * DMODEL + c * KCH + quad * 8;
            cp16(sbase + AH_OFF + soff, Ahg + goff);
        }
#pragma unroll
        for (int i = 0; i < 2; i++) {
            int slot = tid + i * 256;
            int row = slot >> 2, quad = slot & 3;
            uint32_t soff = (uint32_t)row * 80u + (uint32_t)quad * 16u;
            size_t goff = (size_t)(n0 + row) * DMODEL + c * KCH + quad * 8;
            cp16(sbase + BH_OFF + soff, Whg + goff);
        }
    };

    float acc[4][8][4] = {};

    load_chunk(0, 0); CP_COMMIT();
    load_chunk(1, 1); CP_COMMIT();
    load_chunk(2, 2); CP_COMMIT();

    for (int c = 0; c < NC; c++) {
        if (c < NC - 2)       { CP_WAIT(2); }
        else if (c == NC - 2) { CP_WAIT(1); }
        else                  { CP_WAIT(0); }
        __syncthreads();
        if (c + 3 < NC) {
            load_chunk(c + 3, (c + 3) & 3);
            CP_COMMIT();
        }

        const uint32_t sbase = smb + (uint32_t)(c & 3) * STG_B;

#pragma unroll
        for (int ks = 0; ks < 2; ks++) {
            const int kk = ks * 16;
            uint32_t ah[4][4], bh[16];
#pragma unroll
            for (int mf = 0; mf < 4; mf++) {
                uint32_t idx = (uint32_t)((wm * 64 + mf * 16) * PITCH + kk + laneA) * 2;
                ldsm4(ah[mf], sbase + AH_OFF + idx);
            }
#pragma unroll
            for (int nf2 = 0; nf2 < 4; nf2++) {
                uint32_t idx = (uint32_t)((wn * 64 + nf2 * 16) * PITCH + kk + laneB) * 2;
                ldsm4(bh + nf2 * 4, sbase + BH_OFF + idx);
            }
#pragma unroll
            for (int mf = 0; mf < 4; mf++)
#pragma unroll
                for (int nf = 0; nf < 8; nf++) {
                    int bi = (nf >> 1) * 4 + (nf & 1) * 2;
                    mma16816(acc[mf][nf], ah[mf], bh[bi], bh[bi + 1]);
                }
        }
    }

    // epilogue
#pragma unroll
    for (int mf = 0; mf < 4; mf++) {
#pragma unroll
        for (int nf = 0; nf < 8; nf++) {
            int m = m0 + wm * 64 + mf * 16 + (lane >> 2);
            int n = n0 + wn * 64 + nf * 8 + (lane & 3) * 2;
            float bx = bias[n], by = bias[n + 1];
#pragma unroll
            for (int hh = 0; hh < 2; hh++) {
                int mm = m + hh * 8;
                float vx = acc[mf][nf][hh * 2 + 0] + bx;
                float vy = acc[mf][nf][hh * 2 + 1] + by;
                if (remap) {
                    int b = mm >> 11, s = mm & (S_LEN - 1);
                    int h = n >> 6, d = n & (DK - 1);
                    size_t idx = ((size_t)((b << 4) + h) * S_LEN + s) * DK + d;
                    *(__half2*)(Ch + idx) = __floats2half2_rn(vx, vy);
                } else {
                    float2 v; v.x = vx; v.y = vy;
                    *(float2*)(Cf + (size_t)mm * DMODEL + n) = v;
                }
            }
        }
    }
}

// ---------------- HMMA causal flash attention (BKV=128, paired) ---------
// Each CTA processes q-tiles (15-pair, pair) sequentially -> uniform work.
// BQ=128 (8 warps x m16), BKV=128, d=64. QK/PV 1-pass fp16.
// 4-stage KV pipeline.
#define FPITCH 72                          // halves
#define QBUF   (128 * FPITCH * 2)          // 18432 B
#define KVBUF  (128 * FPITCH * 2)          // 18432 B (K or V tile, 128 rows)
#define OFF_QH 0
#define OFF_KV QBUF
#define KVSTG  (2 * KVBUF)                 // 36864 (K + V)
#define SMEM_FLASH (OFF_KV + 4 * KVSTG)    // 165888

__global__ __launch_bounds__(256, 1) void flash_mma(
    const __half* __restrict__ Qh,
    const __half* __restrict__ Kh, const __half* __restrict__ Vh,
    __half* __restrict__ Oh)
{
    extern __shared__ char sm[];
    const uint32_t smb = cvta_smem(sm);
    const int tid = threadIdx.x;
    const int w = tid >> 5, lane = tid & 31;
    const int pair = blockIdx.x;          // 0..7
    const int bh = blockIdx.y;            // 0..63

    const size_t seqbase = (size_t)bh * S_LEN * DK;

    const int ldrow = tid >> 3;           // 0..31
    const int ldq = tid & 7;

    const int laneA = (lane & 15) * FPITCH + ((lane >> 4) & 1) * 8;
    const int laneB = ((lane & 7) + ((lane >> 4) & 1) * 8) * FPITCH + ((lane >> 3) & 1) * 8;
    const int laneV = ((lane & 7) + ((lane >> 3) & 1) * 8) * FPITCH + ((lane >> 4) & 1) * 8;

    const float cs = 0.18033688f;         // (1/8) * log2(e)
    const int b = bh >> 4, h = bh & 15;
    const int cbase = (lane & 3) * 2;

    for (int ph = 0; ph < 2; ph++) {
        const int qi = ph == 0 ? (15 - pair) : pair;   // heavy tile first
        const int q0 = qi * 128;
        const int T = qi + 1;             // KV tiles of 128
        const int rbase = q0 + w * 16 + (lane >> 2);

        if (ph == 1) __syncthreads();     // protect smem reuse across phases

        // load Q tile + prime KV pipeline
#pragma unroll
        for (int i = 0; i < 4; i++) {
            int r = ldrow + i * 32;
            uint32_t so = (uint32_t)r * (FPITCH * 2) + (uint32_t)ldq * 16u;
            size_t g = seqbase + (size_t)(q0 + r) * DK + ldq * 8;
            cp16(smb + OFF_QH + so, Qh + g);
        }
        auto load_tile = [&](int kt, int stage) {
            const uint32_t sb = smb + OFF_KV + (uint32_t)stage * KVSTG;
#pragma unroll
            for (int i = 0; i < 4; i++) {
                int r = ldrow + i * 32;   // 0..127
                uint32_t so = (uint32_t)r * (FPITCH * 2) + (uint32_t)ldq * 16u;
                size_t g = seqbase + (size_t)(kt * 128 + r) * DK + ldq * 8;
                cp16(sb + 0 * KVBUF + so, Kh + g);
                cp16(sb + 1 * KVBUF + so, Vh + g);
            }
        };
        load_tile(0, 0); CP_COMMIT();
        if (T > 1) { load_tile(1, 1); CP_COMMIT(); }
        if (T > 2) { load_tile(2, 2); CP_COMMIT(); }

        uint32_t qhf[4][4];
        float oacc[8][4];
#pragma unroll
        for (int nf = 0; nf < 8; nf++)
#pragma unroll
            for (int j = 0; j < 4; j++) oacc[nf][j] = 0.0f;
        float m0r = -1e30f, m1r = -1e30f, l0r = 0.0f, l1r = 0.0f;

        for (int kt = 0; kt < T; kt++) {
            int rem = T - 1 - kt;
            if (rem >= 2)      { CP_WAIT(2); }
            else if (rem == 1) { CP_WAIT(1); }
            else               { CP_WAIT(0); }
            __syncthreads();

            if (kt == 0) {
#pragma unroll
                for (int ks = 0; ks < 4; ks++) {
                    uint32_t a = smb + OFF_QH +
                        (uint32_t)((w * 16) * FPITCH + ks * 16 + laneA) * 2;
                    ldsm4(qhf[ks], a);
                }
            }
            if (kt + 3 < T) {
                load_tile(kt + 3, (kt + 3) & 3);
                CP_COMMIT();
            }

            const uint32_t kvb = smb + OFF_KV + (uint32_t)(kt & 3) * KVSTG;

            // ---- S = Q K^T  (128 q-rows x 128 kv-cols per CTA) ----
            float sacc[16][4];
#pragma unroll
            for (int nf = 0; nf < 16; nf++)
#pragma unroll
                for (int j = 0; j < 4; j++) sacc[nf][j] = 0.0f;

#pragma unroll
            for (int ks = 0; ks < 4; ks++) {
                uint32_t kb[32];
#pragma unroll
                for (int nb = 0; nb < 8; nb++) {
                    uint32_t a = kvb +
                        (uint32_t)((nb * 16) * FPITCH + ks * 16 + laneB) * 2;
                    ldsm4(kb + nb * 4, a);
                }
#pragma unroll
                for (int nf = 0; nf < 16; nf++) {
                    int bi = (nf >> 1) * 4 + (nf & 1) * 2;
                    mma16816(sacc[nf], qhf[ks], kb[bi], kb[bi + 1]);
                }
            }

            // ---- scale (+ causal mask on the diagonal tile) ----
            if (kt == T - 1) {
#pragma unroll
                for (int nf = 0; nf < 16; nf++) {
#pragma unroll
                    for (int j = 0; j < 4; j++) {
                        int col = kt * 128 + nf * 8 + cbase + (j & 1);
                        int row = rbase + ((j >> 1) << 3);
                        sacc[nf][j] = (col <= row) ? sacc[nf][j] * cs : -1e30f;
                    }
                }
            } else {
#pragma unroll
                for (int nf = 0; nf < 16; nf++)
#pragma unroll
                    for (int j = 0; j < 4; j++) sacc[nf][j] *= cs;
            }

            // ---- online softmax (base-2) ----
            float mx0 = -1e30f, mx1 = -1e30f;
#pragma unroll
            for (int nf = 0; nf < 16; nf++) {
                mx0 = fmaxf(mx0, fmaxf(sacc[nf][0], sacc[nf][1]));
                mx1 = fmaxf(mx1, fmaxf(sacc[nf][2], sacc[nf][3]));
            }
            mx0 = fmaxf(mx0, __shfl_xor_sync(0xffffffffu, mx0, 1));
            mx0 = fmaxf(mx0, __shfl_xor_sync(0xffffffffu, mx0, 2));
            mx1 = fmaxf(mx1, __shfl_xor_sync(0xffffffffu, mx1, 1));
            mx1 = fmaxf(mx1, __shfl_xor_sync(0xffffffffu, mx1, 2));

            float mn0 = fmaxf(m0r, mx0), mn1 = fmaxf(m1r, mx1);
            float c0 = ex2(m0r - mn0), c1 = ex2(m1r - mn1);
            m0r = mn0; m1r = mn1;

            uint32_t pHa[16], pHb[16];
            float ls0 = 0.0f, ls1 = 0.0f;
#pragma unroll
            for (int nf = 0; nf < 16; nf++) {
                float p0 = ex2(sacc[nf][0] - mn0);
                float p1 = ex2(sacc[nf][1] - mn0);
                float p2 = ex2(sacc[nf][2] - mn1);
                float p3 = ex2(sacc[nf][3] - mn1);
                ls0 += p0 + p1;
                ls1 += p2 + p3;
                __half2 h01 = __floats2half2_rn(p0, p1);
                __half2 h23 = __floats2half2_rn(p2, p3);
                pHa[nf] = *(uint32_t*)&h01;
                pHb[nf] = *(uint32_t*)&h23;
            }
            ls0 += __shfl_xor_sync(0xffffffffu, ls0, 1);
            ls0 += __shfl_xor_sync(0xffffffffu, ls0, 2);
            ls1 += __shfl_xor_sync(0xffffffffu, ls1, 1);
            ls1 += __shfl_xor_sync(0xffffffffu, ls1, 2);
            l0r = l0r * c0 + ls0;
            l1r = l1r * c1 + ls1;
#pragma unroll
            for (int nf = 0; nf < 8; nf++) {
                oacc[nf][0] *= c0; oacc[nf][1] *= c0;
                oacc[nf][2] *= c1; oacc[nf][3] *= c1;
            }

            // ---- O += P V  (P: 128x128, V: 128x64) ----
            const uint32_t vbb = kvb + KVBUF;
#pragma unroll
            for (int ks = 0; ks < 8; ks++) {
                uint32_t vb[16];
#pragma unroll
                for (int nb = 0; nb < 4; nb++) {
                    uint32_t a = vbb +
                        (uint32_t)((ks * 16) * FPITCH + nb * 16 + laneV) * 2;
                    ldsm4t(vb + nb * 4, a);
                }
                uint32_t pa[4] = { pHa[2 * ks], pHb[2 * ks],
                                   pHa[2 * ks + 1], pHb[2 * ks + 1] };
#pragma unroll
                for (int nf = 0; nf < 8; nf++) {
                    int bi = (nf >> 1) * 4 + (nf & 1) * 2;
                    mma16816(oacc[nf], pa, vb[bi], vb[bi + 1]);
                }
            }
        }

        // ---- epilogue: write fp16 context [B,S,1024] for this q-tile ----
        const float inv0 = 1.0f / l0r, inv1 = 1.0f / l1r;
        const int s0 = q0 + w * 16 + (lane >> 2);
#pragma unroll
        for (int nf = 0; nf < 8; nf++) {
            int col = h * DK + nf * 8 + cbase;
#pragma unroll
            for (int hh = 0; hh < 2; hh++) {
                int s = s0 + hh * 8;
                float vx = oacc[nf][hh * 2 + 0] * (hh ? inv1 : inv0);
                float vy = oacc[nf][hh * 2 + 1] * (hh ? inv1 : inv0);
                size_t idx = ((size_t)(b * S_LEN + s)) * DMODEL + col;
                *(__half2*)(Oh + idx) = __floats2half2_rn(vx, vy);
            }
        }
    }
}

// ===========================================================================
extern "C" void kernel_launch(void* const* d_in, const int* in_sizes, int n_in,
                              void* d_out, int out_size)
{
    const float* query = (const float*)d_in[0];
    const float* key   = (const float*)d_in[1];
    const float* value = (const float*)d_in[2];
    // d_in[3] = causal mask — handled analytically.
    const float* Wq = (const float*)d_in[4];
    const float* bq = (const float*)d_in[5];
    const float* Wk = (const float*)d_in[6];
    const float* bk = (const float*)d_in[7];
    const float* Wv = (const float*)d_in[8];
    const float* bv = (const float*)d_in[9];
    const float* Wo = (const float*)d_in[10];
    const float* bo = (const float*)d_in[11];
    float* out = (float*)d_out;

    __half *Aq, *Ak, *Av, *Qh, *Kh, *Vh, *Wqh, *Wkh, *Wvh, *Woh;
    cudaGetSymbolAddress((void**)&Aq, g_Aq);
    cudaGetSymbolAddress((void**)&Ak, g_Ak);
    cudaGetSymbolAddress((void**)&Av, g_Av);
    cudaGetSymbolAddress((void**)&Qh, g_Qh);
    cudaGetSymbolAddress((void**)&Kh, g_Kh);
    cudaGetSymbolAddress((void**)&Vh, g_Vh);
    cudaGetSymbolAddress((void**)&Wqh, g_Wqh);
    cudaGetSymbolAddress((void**)&Wkh, g_Wkh);
    cudaGetSymbolAddress((void**)&Wvh, g_Wvh);
    cudaGetSymbolAddress((void**)&Woh, g_Woh);

    cudaFuncSetAttribute(proj_gemm_mma,
                         cudaFuncAttributeMaxDynamicSharedMemorySize, SMEM_GEMM);
    cudaFuncSetAttribute(flash_mma,
                         cudaFuncAttributeMaxDynamicSharedMemorySize, SMEM_FLASH);

    dim3 gg(DMODEL / TILE_N, MTOT / TILE_M);   // (8, 32)

    // one consolidated conversion pass
    split_all<<<SPLIT_GRID, 256>>>(
        (const float4*)query, (const float4*)key, (const float4*)value,
        (const float4*)Wq, (const float4*)Wk, (const float4*)Wv, (const float4*)Wo,
        (uint2*)Aq, (uint2*)Ak, (uint2*)Av,
        (uint2*)Wqh, (uint2*)Wkh, (uint2*)Wvh, (uint2*)Woh);

    // projections (all 1-pass)
    proj_gemm_mma<<<gg, 256, SMEM_GEMM>>>(Aq, Wqh, bq, nullptr, Qh, 1);
    proj_gemm_mma<<<gg, 256, SMEM_GEMM>>>(Ak, Wkh, bk, nullptr, Kh, 1);
    proj_gemm_mma<<<gg, 256, SMEM_GEMM>>>(Av, Wvh, bv, nullptr, Vh, 1);

    // attention: writes fp16 context into Aq (query f16 no longer needed)
    flash_mma<<<dim3(8, BATCH * NHEAD), 256, SMEM_FLASH>>>(Qh, Kh, Vh, Aq);

    // out = Ctx @ Wo^T + bo (fp32 out)
    proj_gemm_mma<<<gg, 256, SMEM_GEMM>>>(Aq, Woh, bo, out, nullptr, 0);
}

// round 10
// speedup vs baseline: 8.8585x; 1.1160x over previous
#include <cuda_runtime.h>
#include <cuda_fp16.h>
#include <cstdint>

#define S_LEN  2048
#define DMODEL 1024
#define NHEAD  16
#define DK     64
#define BATCH  4
#define MTOT   (BATCH * S_LEN)     // 8192

// ---------------- scratch (module-scope device memory) ----------------
__device__ __half g_Aq[MTOT * DMODEL];   // query f16 (later: ctx f16)
__device__ __half g_Ak[MTOT * DMODEL];   // key f16
__device__ __half g_Av[MTOT * DMODEL];   // value f16
__device__ __half g_Qh[BATCH * NHEAD * S_LEN * DK];
__device__ __half g_Kh[BATCH * NHEAD * S_LEN * DK];
__device__ __half g_Vh[BATCH * NHEAD * S_LEN * DK];
__device__ __half g_Wqh[DMODEL * DMODEL];
__device__ __half g_Wkh[DMODEL * DMODEL];
__device__ __half g_Wvh[DMODEL * DMODEL];
__device__ __half g_Woh[DMODEL * DMODEL];

// ---------------- PTX helpers (baseline PTX only) ----------------------
__device__ __forceinline__ uint32_t cvta_smem(const void* p) {
    uint32_t a;
    asm("{ .reg .u64 t; cvta.to.shared.u64 t, %1; cvt.u32.u64 %0, t; }"
        : "=r"(a) : "l"(p));
    return a;
}
__device__ __forceinline__ void cp16(uint32_t dst, const void* src) {
    asm volatile("cp.async.cg.shared.global [%0], [%1], 16;"
                 :: "r"(dst), "l"(src));
}
#define CP_COMMIT() asm volatile("cp.async.commit_group;" ::: "memory")
#define CP_WAIT(n)  asm volatile("cp.async.wait_group %0;" :: "n"(n) : "memory")

__device__ __forceinline__ void ldsm4(uint32_t* r, uint32_t addr) {
    asm volatile("ldmatrix.sync.aligned.m8n8.x4.shared.b16 {%0,%1,%2,%3}, [%4];"
                 : "=r"(r[0]), "=r"(r[1]), "=r"(r[2]), "=r"(r[3]) : "r"(addr));
}
__device__ __forceinline__ void ldsm4t(uint32_t* r, uint32_t addr) {
    asm volatile("ldmatrix.sync.aligned.m8n8.x4.trans.shared.b16 {%0,%1,%2,%3}, [%4];"
                 : "=r"(r[0]), "=r"(r[1]), "=r"(r[2]), "=r"(r[3]) : "r"(addr));
}
__device__ __forceinline__ void mma16816(float* d, const uint32_t* a,
                                         uint32_t b0, uint32_t b1) {
    asm volatile(
        "mma.sync.aligned.m16n8k16.row.col.f32.f16.f16.f32 "
        "{%0,%1,%2,%3}, {%4,%5,%6,%7}, {%8,%9}, {%0,%1,%2,%3};"
        : "+f"(d[0]), "+f"(d[1]), "+f"(d[2]), "+f"(d[3])
        : "r"(a[0]), "r"(a[1]), "r"(a[2]), "r"(a[3]), "r"(b0), "r"(b1));
}
__device__ __forceinline__ float ex2(float x) {
    float y;
    asm("ex2.approx.f32 %0, %1;" : "=f"(y) : "f"(x));
    return y;
}

__device__ __forceinline__ uint2 pack_hi(float4 v) {
    __half h0 = __float2half_rn(v.x), h1 = __float2half_rn(v.y);
    __half h2 = __float2half_rn(v.z), h3 = __float2half_rn(v.w);
    uint2 H;
    H.x = (uint32_t)__half_as_ushort(h0) | ((uint32_t)__half_as_ushort(h1) << 16);
    H.y = (uint32_t)__half_as_ushort(h2) | ((uint32_t)__half_as_ushort(h3) << 16);
    return H;
}

// ---------------- single consolidated split kernel ----------------------
#define ACT_BLKS  8192        // (MTOT*DMODEL/4)/256
#define W_BLKS    1024        // (DMODEL*DMODEL/4)/256
#define SPLIT_GRID (3 * ACT_BLKS + 4 * W_BLKS)

__global__ __launch_bounds__(256) void split_all(
    const float4* __restrict__ q, const float4* __restrict__ k,
    const float4* __restrict__ v,
    const float4* __restrict__ wq, const float4* __restrict__ wk,
    const float4* __restrict__ wv, const float4* __restrict__ wo,
    uint2* __restrict__ aq, uint2* __restrict__ ak, uint2* __restrict__ av,
    uint2* __restrict__ wqh, uint2* __restrict__ wkh,
    uint2* __restrict__ wvh, uint2* __restrict__ woh)
{
    const int b = blockIdx.x, t = threadIdx.x;
    if (b < 3 * ACT_BLKS) {
        const int which = b / ACT_BLKS;
        const int i = (b % ACT_BLKS) * 256 + t;
        const float4* src = which == 0 ? q : (which == 1 ? k : v);
        uint2* dst = which == 0 ? aq : (which == 1 ? ak : av);
        dst[i] = pack_hi(src[i]);
    } else {
        const int wb = b - 3 * ACT_BLKS;
        const int which = wb / W_BLKS;
        const int i = (wb % W_BLKS) * 256 + t;
        const float4* src = which == 0 ? wq : (which == 1 ? wk
                          : (which == 2 ? wv : wo));
        uint2* dst = which == 0 ? wqh : (which == 1 ? wkh
                   : (which == 2 ? wvh : woh));
        dst[i] = pack_hi(src[i]);
    }
}

// ---------------- HMMA projection GEMM (128x128 tile, 2 CTAs/SM) --------
// C = A[M,1024] @ W[1024,1024]^T + bias.  A, W fp16 (1-pass).
// remap=1: head-split [B,H,S,DK] fp16; remap=0: fp32 [M,1024].
// 4 warps (128 thr), warp tile 64x64, K-chunk 64, 3-stage pipeline.
#define TILE_M 128
#define TILE_N 128
#define KCH    64
#define NC     (DMODEL / KCH)  // 16
#define PITCH  72              // halves per smem row (144B)
#define ROWB   144
#define A_OFF  0
#define B_OFF  (128 * ROWB)    // 18432
#define STG_B  (2 * 128 * ROWB)// 36864
#define SMEM_GEMM (3 * STG_B)  // 110592

__global__ __launch_bounds__(128, 2) void proj_gemm_mma(
    const __half* __restrict__ Ahg, const __half* __restrict__ Whg,
    const float* __restrict__ bias, float* __restrict__ Cf,
    __half* __restrict__ Ch, int remap)
{
    extern __shared__ char sm[];
    const uint32_t smb = cvta_smem(sm);
    const int tid = threadIdx.x;
    const int wid = tid >> 5, lane = tid & 31;
    const int wm = wid & 1;          // 2 m-slices of 64
    const int wn = wid >> 1;         // 2 n-slices of 64
    const int m0 = blockIdx.y * TILE_M;
    const int n0 = blockIdx.x * TILE_N;

    const int laneA = (lane & 15) * PITCH + ((lane >> 4) & 1) * 8;
    const int laneB = ((lane & 7) + ((lane >> 4) & 1) * 8) * PITCH + ((lane >> 3) & 1) * 8;

    auto load_chunk = [&](int c, int stage) {
        const uint32_t sbase = smb + (uint32_t)stage * STG_B;
        // A: 128 rows x 8 quads = 1024 slots; 128 threads -> 8 iters
#pragma unroll
        for (int i = 0; i < 8; i++) {
            int slot = tid + i * 128;
            int row = slot >> 3, quad = slot & 7;
            uint32_t soff = (uint32_t)row * ROWB + (uint32_t)quad * 16u;
            size_t goff = (size_t)(m0 + row) * DMODEL + c * KCH + quad * 8;
            cp16(sbase + A_OFF + soff, Ahg + goff);
        }
#pragma unroll
        for (int i = 0; i < 8; i++) {
            int slot = tid + i * 128;
            int row = slot >> 3, quad = slot & 7;
            uint32_t soff = (uint32_t)row * ROWB + (uint32_t)quad * 16u;
            size_t goff = (size_t)(n0 + row) * DMODEL + c * KCH + quad * 8;
            cp16(sbase + B_OFF + soff, Whg + goff);
        }
    };

    float acc[2][8][4];
#pragma unroll
    for (int mf = 0; mf < 2; mf++)
#pragma unroll
        for (int nf = 0; nf < 8; nf++)
#pragma unroll
            for (int j = 0; j < 4; j++) acc[mf][nf][j] = 0.0f;
    // acc covers mf 0..3 via two m16 frags per mf-pair; we use 4 mf frags:
    float acc2[2][8][4];
#pragma unroll
    for (int mf = 0; mf < 2; mf++)
#pragma unroll
        for (int nf = 0; nf < 8; nf++)
#pragma unroll
            for (int j = 0; j < 4; j++) acc2[mf][nf][j] = 0.0f;

    load_chunk(0, 0); CP_COMMIT();
    load_chunk(1, 1); CP_COMMIT();

    int stage = 0;
    for (int c = 0; c < NC; c++) {
        if (c < NC - 1) { CP_WAIT(1); } else { CP_WAIT(0); }
        __syncthreads();
        if (c + 2 < NC) {
            int ls = stage + 2; if (ls >= 3) ls -= 3;
            load_chunk(c + 2, ls);
            CP_COMMIT();
        }

        const uint32_t sbase = smb + (uint32_t)stage * STG_B;

#pragma unroll
        for (int ks = 0; ks < 4; ks++) {
            const int kk = ks * 16;
            uint32_t ah[4][4], bh[16];
#pragma unroll
            for (int mf = 0; mf < 4; mf++) {
                uint32_t idx = (uint32_t)((wm * 64 + mf * 16) * PITCH + kk + laneA) * 2;
                ldsm4(ah[mf], sbase + A_OFF + idx);
            }
#pragma unroll
            for (int nf2 = 0; nf2 < 4; nf2++) {
                uint32_t idx = (uint32_t)((wn * 64 + nf2 * 16) * PITCH + kk + laneB) * 2;
                ldsm4(bh + nf2 * 4, sbase + B_OFF + idx);
            }
#pragma unroll
            for (int mf = 0; mf < 2; mf++)
#pragma unroll
                for (int nf = 0; nf < 8; nf++) {
                    int bi = (nf >> 1) * 4 + (nf & 1) * 2;
                    mma16816(acc[mf][nf], ah[mf], bh[bi], bh[bi + 1]);
                }
#pragma unroll
            for (int mf = 0; mf < 2; mf++)
#pragma unroll
                for (int nf = 0; nf < 8; nf++) {
                    int bi = (nf >> 1) * 4 + (nf & 1) * 2;
                    mma16816(acc2[mf][nf], ah[mf + 2], bh[bi], bh[bi + 1]);
                }
        }
        stage++; if (stage == 3) stage = 0;
    }

    // epilogue (mf 0..3: frags 0,1 in acc; 2,3 in acc2)
#pragma unroll
    for (int mf = 0; mf < 4; mf++) {
        float (*ac)[4] = (mf < 2) ? acc[mf] : acc2[mf - 2];
#pragma unroll
        for (int nf = 0; nf < 8; nf++) {
            int m = m0 + wm * 64 + mf * 16 + (lane >> 2);
            int n = n0 + wn * 64 + nf * 8 + (lane & 3) * 2;
            float bx = bias[n], by = bias[n + 1];
#pragma unroll
            for (int hh = 0; hh < 2; hh++) {
                int mm = m + hh * 8;
                float vx = ac[nf][hh * 2 + 0] + bx;
                float vy = ac[nf][hh * 2 + 1] + by;
                if (remap) {
                    int b = mm >> 11, s = mm & (S_LEN - 1);
                    int h = n >> 6, d = n & (DK - 1);
                    size_t idx = ((size_t)((b << 4) + h) * S_LEN + s) * DK + d;
                    *(__half2*)(Ch + idx) = __floats2half2_rn(vx, vy);
                } else {
                    float2 v; v.x = vx; v.y = vy;
                    *(float2*)(Cf + (size_t)mm * DMODEL + n) = v;
                }
            }
        }
    }
}

// ---------------- HMMA causal flash attention (BKV=128, paired) ---------
// Each CTA processes q-tiles (15-pair, pair) sequentially -> uniform work.
// BQ=128 (8 warps x m16), BKV=128, d=64. QK/PV 1-pass fp16.
#define FPITCH 72                          // halves
#define QBUF   (128 * FPITCH * 2)          // 18432 B
#define KVBUF  (128 * FPITCH * 2)          // 18432 B
#define OFF_QH 0
#define OFF_KV QBUF
#define KVSTG  (2 * KVBUF)                 // 36864 (K + V)
#define SMEM_FLASH (OFF_KV + 4 * KVSTG)    // 165888

__global__ __launch_bounds__(256, 1) void flash_mma(
    const __half* __restrict__ Qh,
    const __half* __restrict__ Kh, const __half* __restrict__ Vh,
    __half* __restrict__ Oh)
{
    extern __shared__ char sm[];
    const uint32_t smb = cvta_smem(sm);
    const int tid = threadIdx.x;
    const int w = tid >> 5, lane = tid & 31;
    const int pair = blockIdx.x;          // 0..7
    const int bh = blockIdx.y;            // 0..63

    const size_t seqbase = (size_t)bh * S_LEN * DK;

    const int ldrow = tid >> 3;           // 0..31
    const int ldq = tid & 7;

    const int laneA = (lane & 15) * FPITCH + ((lane >> 4) & 1) * 8;
    const int laneB = ((lane & 7) + ((lane >> 4) & 1) * 8) * FPITCH + ((lane >> 3) & 1) * 8;
    const int laneV = ((lane & 7) + ((lane >> 3) & 1) * 8) * FPITCH + ((lane >> 4) & 1) * 8;

    const float cs = 0.18033688f;         // (1/8) * log2(e)
    const int b = bh >> 4, h = bh & 15;
    const int cbase = (lane & 3) * 2;

    for (int ph = 0; ph < 2; ph++) {
        const int qi = ph == 0 ? (15 - pair) : pair;   // heavy tile first
        const int q0 = qi * 128;
        const int T = qi + 1;             // KV tiles of 128
        const int rbase = q0 + w * 16 + (lane >> 2);

        if (ph == 1) __syncthreads();     // protect smem reuse across phases

        // load Q tile + prime KV pipeline
#pragma unroll
        for (int i = 0; i < 4; i++) {
            int r = ldrow + i * 32;
            uint32_t so = (uint32_t)r * (FPITCH * 2) + (uint32_t)ldq * 16u;
            size_t g = seqbase + (size_t)(q0 + r) * DK + ldq * 8;
            cp16(smb + OFF_QH + so, Qh + g);
        }
        auto load_tile = [&](int kt, int stage) {
            const uint32_t sb = smb + OFF_KV + (uint32_t)stage * KVSTG;
#pragma unroll
            for (int i = 0; i < 4; i++) {
                int r = ldrow + i * 32;   // 0..127
                uint32_t so = (uint32_t)r * (FPITCH * 2) + (uint32_t)ldq * 16u;
                size_t g = seqbase + (size_t)(kt * 128 + r) * DK + ldq * 8;
                cp16(sb + 0 * KVBUF + so, Kh + g);
                cp16(sb + 1 * KVBUF + so, Vh + g);
            }
        };
        load_tile(0, 0); CP_COMMIT();
        if (T > 1) { load_tile(1, 1); CP_COMMIT(); }
        if (T > 2) { load_tile(2, 2); CP_COMMIT(); }

        uint32_t qhf[4][4];
        float oacc[8][4];
#pragma unroll
        for (int nf = 0; nf < 8; nf++)
#pragma unroll
            for (int j = 0; j < 4; j++) oacc[nf][j] = 0.0f;
        float m0r = -1e30f, m1r = -1e30f, l0r = 0.0f, l1r = 0.0f;

        for (int kt = 0; kt < T; kt++) {
            int rem = T - 1 - kt;
            if (rem >= 2)      { CP_WAIT(2); }
            else if (rem == 1) { CP_WAIT(1); }
            else               { CP_WAIT(0); }
            __syncthreads();

            if (kt == 0) {
#pragma unroll
                for (int ks = 0; ks < 4; ks++) {
                    uint32_t a = smb + OFF_QH +
                        (uint32_t)((w * 16) * FPITCH + ks * 16 + laneA) * 2;
                    ldsm4(qhf[ks], a);
                }
            }
            if (kt + 3 < T) {
                load_tile(kt + 3, (kt + 3) & 3);
                CP_COMMIT();
            }

            const uint32_t kvb = smb + OFF_KV + (uint32_t)(kt & 3) * KVSTG;

            // ---- S = Q K^T ----
            float sacc[16][4];
#pragma unroll
            for (int nf = 0; nf < 16; nf++)
#pragma unroll
                for (int j = 0; j < 4; j++) sacc[nf][j] = 0.0f;

#pragma unroll
            for (int ks = 0; ks < 4; ks++) {
                uint32_t kb[32];
#pragma unroll
                for (int nb = 0; nb < 8; nb++) {
                    uint32_t a = kvb +
                        (uint32_t)((nb * 16) * FPITCH + ks * 16 + laneB) * 2;
                    ldsm4(kb + nb * 4, a);
                }
#pragma unroll
                for (int nf = 0; nf < 16; nf++) {
                    int bi = (nf >> 1) * 4 + (nf & 1) * 2;
                    mma16816(sacc[nf], qhf[ks], kb[bi], kb[bi + 1]);
                }
            }

            // ---- scale (+ causal mask on the diagonal tile) ----
            if (kt == T - 1) {
#pragma unroll
                for (int nf = 0; nf < 16; nf++) {
#pragma unroll
                    for (int j = 0; j < 4; j++) {
                        int col = kt * 128 + nf * 8 + cbase + (j & 1);
                        int row = rbase + ((j >> 1) << 3);
                        sacc[nf][j] = (col <= row) ? sacc[nf][j] * cs : -1e30f;
                    }
                }
            } else {
#pragma unroll
                for (int nf = 0; nf < 16; nf++)
#pragma unroll
                    for (int j = 0; j < 4; j++) sacc[nf][j] *= cs;
            }

            // ---- online softmax (base-2) ----
            float mx0 = -1e30f, mx1 = -1e30f;
#pragma unroll
            for (int nf = 0; nf < 16; nf++) {
                mx0 = fmaxf(mx0, fmaxf(sacc[nf][0], sacc[nf][1]));
                mx1 = fmaxf(mx1, fmaxf(sacc[nf][2], sacc[nf][3]));
            }
            mx0 = fmaxf(mx0, __shfl_xor_sync(0xffffffffu, mx0, 1));
            mx0 = fmaxf(mx0, __shfl_xor_sync(0xffffffffu, mx0, 2));
            mx1 = fmaxf(mx1, __shfl_xor_sync(0xffffffffu, mx1, 1));
            mx1 = fmaxf(mx1, __shfl_xor_sync(0xffffffffu, mx1, 2));

            float mn0 = fmaxf(m0r, mx0), mn1 = fmaxf(m1r, mx1);
            float c0 = ex2(m0r - mn0), c1 = ex2(m1r - mn1);
            m0r = mn0; m1r = mn1;

            uint32_t pHa[16], pHb[16];
            float ls0 = 0.0f, ls1 = 0.0f;
#pragma unroll
            for (int nf = 0; nf < 16; nf++) {
                float p0 = ex2(sacc[nf][0] - mn0);
                float p1 = ex2(sacc[nf][1] - mn0);
                float p2 = ex2(sacc[nf][2] - mn1);
                float p3 = ex2(sacc[nf][3] - mn1);
                ls0 += p0 + p1;
                ls1 += p2 + p3;
                __half2 h01 = __floats2half2_rn(p0, p1);
                __half2 h23 = __floats2half2_rn(p2, p3);
                pHa[nf] = *(uint32_t*)&h01;
                pHb[nf] = *(uint32_t*)&h23;
            }
            ls0 += __shfl_xor_sync(0xffffffffu, ls0, 1);
            ls0 += __shfl_xor_sync(0xffffffffu, ls0, 2);
            ls1 += __shfl_xor_sync(0xffffffffu, ls1, 1);
            ls1 += __shfl_xor_sync(0xffffffffu, ls1, 2);
            l0r = l0r * c0 + ls0;
            l1r = l1r * c1 + ls1;
#pragma unroll
            for (int nf = 0; nf < 8; nf++) {
                oacc[nf][0] *= c0; oacc[nf][1] *= c0;
                oacc[nf][2] *= c1; oacc[nf][3] *= c1;
            }

            // ---- O += P V ----
            const uint32_t vbb = kvb + KVBUF;
#pragma unroll
            for (int ks = 0; ks < 8; ks++) {
                uint32_t vb[16];
#pragma unroll
                for (int nb = 0; nb < 4; nb++) {
                    uint32_t a = vbb +
                        (uint32_t)((ks * 16) * FPITCH + nb * 16 + laneV) * 2;
                    ldsm4t(vb + nb * 4, a);
                }
                uint32_t pa[4] = { pHa[2 * ks], pHb[2 * ks],
                                   pHa[2 * ks + 1], pHb[2 * ks + 1] };
#pragma unroll
                for (int nf = 0; nf < 8; nf++) {
                    int bi = (nf >> 1) * 4 + (nf & 1) * 2;
                    mma16816(oacc[nf], pa, vb[bi], vb[bi + 1]);
                }
            }
        }

        // ---- epilogue: write fp16 context [B,S,1024] for this q-tile ----
        const float inv0 = 1.0f / l0r, inv1 = 1.0f / l1r;
        const int s0 = q0 + w * 16 + (lane >> 2);
#pragma unroll
        for (int nf = 0; nf < 8; nf++) {
            int col = h * DK + nf * 8 + cbase;
#pragma unroll
            for (int hh = 0; hh < 2; hh++) {
                int s = s0 + hh * 8;
                float vx = oacc[nf][hh * 2 + 0] * (hh ? inv1 : inv0);
                float vy = oacc[nf][hh * 2 + 1] * (hh ? inv1 : inv0);
                size_t idx = ((size_t)(b * S_LEN + s)) * DMODEL + col;
                *(__half2*)(Oh + idx) = __floats2half2_rn(vx, vy);
            }
        }
    }
}

// ===========================================================================
extern "C" void kernel_launch(void* const* d_in, const int* in_sizes, int n_in,
                              void* d_out, int out_size)
{
    const float* query = (const float*)d_in[0];
    const float* key   = (const float*)d_in[1];
    const float* value = (const float*)d_in[2];
    // d_in[3] = causal mask — handled analytically.
    const float* Wq = (const float*)d_in[4];
    const float* bq = (const float*)d_in[5];
    const float* Wk = (const float*)d_in[6];
    const float* bk = (const float*)d_in[7];
    const float* Wv = (const float*)d_in[8];
    const float* bv = (const float*)d_in[9];
    const float* Wo = (const float*)d_in[10];
    const float* bo = (const float*)d_in[11];
    float* out = (float*)d_out;

    __half *Aq, *Ak, *Av, *Qh, *Kh, *Vh, *Wqh, *Wkh, *Wvh, *Woh;
    cudaGetSymbolAddress((void**)&Aq, g_Aq);
    cudaGetSymbolAddress((void**)&Ak, g_Ak);
    cudaGetSymbolAddress((void**)&Av, g_Av);
    cudaGetSymbolAddress((void**)&Qh, g_Qh);
    cudaGetSymbolAddress((void**)&Kh, g_Kh);
    cudaGetSymbolAddress((void**)&Vh, g_Vh);
    cudaGetSymbolAddress((void**)&Wqh, g_Wqh);
    cudaGetSymbolAddress((void**)&Wkh, g_Wkh);
    cudaGetSymbolAddress((void**)&Wvh, g_Wvh);
    cudaGetSymbolAddress((void**)&Woh, g_Woh);

    cudaFuncSetAttribute(proj_gemm_mma,
                         cudaFuncAttributeMaxDynamicSharedMemorySize, SMEM_GEMM);
    cudaFuncSetAttribute(flash_mma,
                         cudaFuncAttributeMaxDynamicSharedMemorySize, SMEM_FLASH);

    dim3 gg(DMODEL / TILE_N, MTOT / TILE_M);   // (8, 64)

    // one consolidated conversion pass
    split_all<<<SPLIT_GRID, 256>>>(
        (const float4*)query, (const float4*)key, (const float4*)value,
        (const float4*)Wq, (const float4*)Wk, (const float4*)Wv, (const float4*)Wo,
        (uint2*)Aq, (uint2*)Ak, (uint2*)Av,
        (uint2*)Wqh, (uint2*)Wkh, (uint2*)Wvh, (uint2*)Woh);

    // projections (all 1-pass)
    proj_gemm_mma<<<gg, 128, SMEM_GEMM>>>(Aq, Wqh, bq, nullptr, Qh, 1);
    proj_gemm_mma<<<gg, 128, SMEM_GEMM>>>(Ak, Wkh, bk, nullptr, Kh, 1);
    proj_gemm_mma<<<gg, 128, SMEM_GEMM>>>(Av, Wvh, bv, nullptr, Vh, 1);

    // attention: writes fp16 context into Aq (query f16 no longer needed)
    flash_mma<<<dim3(8, BATCH * NHEAD), 256, SMEM_FLASH>>>(Qh, Kh, Vh, Aq);

    // out = Ctx @ Wo^T + bo (fp32 out)
    proj_gemm_mma<<<gg, 128, SMEM_GEMM>>>(Aq, Woh, bo, out, nullptr, 0);
}

// round 11
// speedup vs baseline: 9.8547x; 1.1125x over previous
#include <cuda_runtime.h>
#include <cuda_fp16.h>
#include <cstdint>

#define S_LEN  2048
#define DMODEL 1024
#define NHEAD  16
#define DK     64
#define BATCH  4
#define MTOT   (BATCH * S_LEN)     // 8192

// ---------------- scratch (module-scope device memory) ----------------
__device__ __half g_Aq[MTOT * DMODEL];   // query f16 (later: ctx f16)
__device__ __half g_Ak[MTOT * DMODEL];   // key f16
__device__ __half g_Av[MTOT * DMODEL];   // value f16
__device__ __half g_Qh[BATCH * NHEAD * S_LEN * DK];
__device__ __half g_Kh[BATCH * NHEAD * S_LEN * DK];
__device__ __half g_Vh[BATCH * NHEAD * S_LEN * DK];
__device__ __half g_Wqh[DMODEL * DMODEL];
__device__ __half g_Wkh[DMODEL * DMODEL];
__device__ __half g_Wvh[DMODEL * DMODEL];
__device__ __half g_Woh[DMODEL * DMODEL];

// ---------------- PTX helpers (baseline PTX only) ----------------------
__device__ __forceinline__ uint32_t cvta_smem(const void* p) {
    uint32_t a;
    asm("{ .reg .u64 t; cvta.to.shared.u64 t, %1; cvt.u32.u64 %0, t; }"
        : "=r"(a) : "l"(p));
    return a;
}
__device__ __forceinline__ void cp16(uint32_t dst, const void* src) {
    asm volatile("cp.async.cg.shared.global [%0], [%1], 16;"
                 :: "r"(dst), "l"(src));
}
#define CP_COMMIT() asm volatile("cp.async.commit_group;" ::: "memory")
#define CP_WAIT(n)  asm volatile("cp.async.wait_group %0;" :: "n"(n) : "memory")

__device__ __forceinline__ void ldsm4(uint32_t* r, uint32_t addr) {
    asm volatile("ldmatrix.sync.aligned.m8n8.x4.shared.b16 {%0,%1,%2,%3}, [%4];"
                 : "=r"(r[0]), "=r"(r[1]), "=r"(r[2]), "=r"(r[3]) : "r"(addr));
}
__device__ __forceinline__ void ldsm4t(uint32_t* r, uint32_t addr) {
    asm volatile("ldmatrix.sync.aligned.m8n8.x4.trans.shared.b16 {%0,%1,%2,%3}, [%4];"
                 : "=r"(r[0]), "=r"(r[1]), "=r"(r[2]), "=r"(r[3]) : "r"(addr));
}
__device__ __forceinline__ void mma16816(float* d, const uint32_t* a,
                                         uint32_t b0, uint32_t b1) {
    asm volatile(
        "mma.sync.aligned.m16n8k16.row.col.f32.f16.f16.f32 "
        "{%0,%1,%2,%3}, {%4,%5,%6,%7}, {%8,%9}, {%0,%1,%2,%3};"
        : "+f"(d[0]), "+f"(d[1]), "+f"(d[2]), "+f"(d[3])
        : "r"(a[0]), "r"(a[1]), "r"(a[2]), "r"(a[3]), "r"(b0), "r"(b1));
}
__device__ __forceinline__ float ex2(float x) {
    float y;
    asm("ex2.approx.f32 %0, %1;" : "=f"(y) : "f"(x));
    return y;
}

__device__ __forceinline__ uint2 pack_hi(float4 v) {
    __half h0 = __float2half_rn(v.x), h1 = __float2half_rn(v.y);
    __half h2 = __float2half_rn(v.z), h3 = __float2half_rn(v.w);
    uint2 H;
    H.x = (uint32_t)__half_as_ushort(h0) | ((uint32_t)__half_as_ushort(h1) << 16);
    H.y = (uint32_t)__half_as_ushort(h2) | ((uint32_t)__half_as_ushort(h3) << 16);
    return H;
}

// ---------------- single consolidated split kernel ----------------------
#define ACT_BLKS  8192        // (MTOT*DMODEL/4)/256
#define W_BLKS    1024        // (DMODEL*DMODEL/4)/256
#define SPLIT_GRID (3 * ACT_BLKS + 4 * W_BLKS)

__global__ __launch_bounds__(256) void split_all(
    const float4* __restrict__ q, const float4* __restrict__ k,
    const float4* __restrict__ v,
    const float4* __restrict__ wq, const float4* __restrict__ wk,
    const float4* __restrict__ wv, const float4* __restrict__ wo,
    uint2* __restrict__ aq, uint2* __restrict__ ak, uint2* __restrict__ av,
    uint2* __restrict__ wqh, uint2* __restrict__ wkh,
    uint2* __restrict__ wvh, uint2* __restrict__ woh)
{
    const int b = blockIdx.x, t = threadIdx.x;
    if (b < 3 * ACT_BLKS) {
        const int which = b / ACT_BLKS;
        const int i = (b % ACT_BLKS) * 256 + t;
        const float4* src = which == 0 ? q : (which == 1 ? k : v);
        uint2* dst = which == 0 ? aq : (which == 1 ? ak : av);
        dst[i] = pack_hi(src[i]);
    } else {
        const int wb = b - 3 * ACT_BLKS;
        const int which = wb / W_BLKS;
        const int i = (wb % W_BLKS) * 256 + t;
        const float4* src = which == 0 ? wq : (which == 1 ? wk
                          : (which == 2 ? wv : wo));
        uint2* dst = which == 0 ? wqh : (which == 1 ? wkh
                   : (which == 2 ? wvh : woh));
        dst[i] = pack_hi(src[i]);
    }
}

// ---------------- HMMA projection GEMM (128x128 tile, 2 CTAs/SM) --------
// C = A[M,1024] @ W[1024,1024]^T + bias.  A, W fp16 (1-pass).
// QKV=1: grid.z selects (A,W,bias,C) set, head-split fp16 output.
// QKV=0: single fp32 output GEMM.
// 4 warps (128 thr), warp tile 64x64, K-chunk 64, 3-stage pipeline.
#define TILE_M 128
#define TILE_N 128
#define KCH    64
#define NC     (DMODEL / KCH)  // 16
#define PITCH  72              // halves per smem row (144B)
#define ROWB   144
#define A_OFF  0
#define B_OFF  (128 * ROWB)    // 18432
#define STG_B  (2 * 128 * ROWB)// 36864
#define SMEM_GEMM (3 * STG_B)  // 110592

template <int QKV>
__global__ __launch_bounds__(128, 2) void proj_gemm_mma(
    const __half* __restrict__ A0, const __half* __restrict__ A1,
    const __half* __restrict__ A2,
    const __half* __restrict__ W0, const __half* __restrict__ W1,
    const __half* __restrict__ W2,
    const float* __restrict__ b0, const float* __restrict__ b1,
    const float* __restrict__ b2,
    __half* __restrict__ C0, __half* __restrict__ C1,
    __half* __restrict__ C2, float* __restrict__ Cf)
{
    extern __shared__ char sm[];
    const uint32_t smb = cvta_smem(sm);
    const int tid = threadIdx.x;
    const int wid = tid >> 5, lane = tid & 31;
    const int wm = wid & 1;
    const int wn = wid >> 1;
    const int m0 = blockIdx.y * TILE_M;
    const int n0 = blockIdx.x * TILE_N;

    const __half* Ahg; const __half* Whg; const float* bias; __half* Ch;
    if (QKV) {
        const int z = blockIdx.z;
        Ahg  = z == 0 ? A0 : (z == 1 ? A1 : A2);
        Whg  = z == 0 ? W0 : (z == 1 ? W1 : W2);
        bias = z == 0 ? b0 : (z == 1 ? b1 : b2);
        Ch   = z == 0 ? C0 : (z == 1 ? C1 : C2);
    } else {
        Ahg = A0; Whg = W0; bias = b0; Ch = nullptr;
    }

    const int laneA = (lane & 15) * PITCH + ((lane >> 4) & 1) * 8;
    const int laneB = ((lane & 7) + ((lane >> 4) & 1) * 8) * PITCH + ((lane >> 3) & 1) * 8;

    auto load_chunk = [&](int c, int stage) {
        const uint32_t sbase = smb + (uint32_t)stage * STG_B;
#pragma unroll
        for (int i = 0; i < 8; i++) {
            int slot = tid + i * 128;
            int row = slot >> 3, quad = slot & 7;
            uint32_t soff = (uint32_t)row * ROWB + (uint32_t)quad * 16u;
            size_t goff = (size_t)(m0 + row) * DMODEL + c * KCH + quad * 8;
            cp16(sbase + A_OFF + soff, Ahg + goff);
        }
#pragma unroll
        for (int i = 0; i < 8; i++) {
            int slot = tid + i * 128;
            int row = slot >> 3, quad = slot & 7;
            uint32_t soff = (uint32_t)row * ROWB + (uint32_t)quad * 16u;
            size_t goff = (size_t)(n0 + row) * DMODEL + c * KCH + quad * 8;
            cp16(sbase + B_OFF + soff, Whg + goff);
        }
    };

    float acc[2][8][4], acc2[2][8][4];
#pragma unroll
    for (int mf = 0; mf < 2; mf++)
#pragma unroll
        for (int nf = 0; nf < 8; nf++)
#pragma unroll
            for (int j = 0; j < 4; j++) { acc[mf][nf][j] = 0.0f; acc2[mf][nf][j] = 0.0f; }

    load_chunk(0, 0); CP_COMMIT();
    load_chunk(1, 1); CP_COMMIT();

    int stage = 0;
    for (int c = 0; c < NC; c++) {
        if (c < NC - 1) { CP_WAIT(1); } else { CP_WAIT(0); }
        __syncthreads();
        if (c + 2 < NC) {
            int ls = stage + 2; if (ls >= 3) ls -= 3;
            load_chunk(c + 2, ls);
            CP_COMMIT();
        }

        const uint32_t sbase = smb + (uint32_t)stage * STG_B;

#pragma unroll
        for (int ks = 0; ks < 4; ks++) {
            const int kk = ks * 16;
            uint32_t ah[4][4], bh[16];
#pragma unroll
            for (int mf = 0; mf < 4; mf++) {
                uint32_t idx = (uint32_t)((wm * 64 + mf * 16) * PITCH + kk + laneA) * 2;
                ldsm4(ah[mf], sbase + A_OFF + idx);
            }
#pragma unroll
            for (int nf2 = 0; nf2 < 4; nf2++) {
                uint32_t idx = (uint32_t)((wn * 64 + nf2 * 16) * PITCH + kk + laneB) * 2;
                ldsm4(bh + nf2 * 4, sbase + B_OFF + idx);
            }
#pragma unroll
            for (int mf = 0; mf < 2; mf++)
#pragma unroll
                for (int nf = 0; nf < 8; nf++) {
                    int bi = (nf >> 1) * 4 + (nf & 1) * 2;
                    mma16816(acc[mf][nf], ah[mf], bh[bi], bh[bi + 1]);
                }
#pragma unroll
            for (int mf = 0; mf < 2; mf++)
#pragma unroll
                for (int nf = 0; nf < 8; nf++) {
                    int bi = (nf >> 1) * 4 + (nf & 1) * 2;
                    mma16816(acc2[mf][nf], ah[mf + 2], bh[bi], bh[bi + 1]);
                }
        }
        stage++; if (stage == 3) stage = 0;
    }

    // epilogue
#pragma unroll
    for (int mf = 0; mf < 4; mf++) {
        float (*ac)[4] = (mf < 2) ? acc[mf] : acc2[mf - 2];
#pragma unroll
        for (int nf = 0; nf < 8; nf++) {
            int m = m0 + wm * 64 + mf * 16 + (lane >> 2);
            int n = n0 + wn * 64 + nf * 8 + (lane & 3) * 2;
            float bx = bias[n], by = bias[n + 1];
#pragma unroll
            for (int hh = 0; hh < 2; hh++) {
                int mm = m + hh * 8;
                float vx = ac[nf][hh * 2 + 0] + bx;
                float vy = ac[nf][hh * 2 + 1] + by;
                if (QKV) {
                    int b = mm >> 11, s = mm & (S_LEN - 1);
                    int h = n >> 6, d = n & (DK - 1);
                    size_t idx = ((size_t)((b << 4) + h) * S_LEN + s) * DK + d;
                    *(__half2*)(Ch + idx) = __floats2half2_rn(vx, vy);
                } else {
                    float2 v; v.x = vx; v.y = vy;
                    *(float2*)(Cf + (size_t)mm * DMODEL + n) = v;
                }
            }
        }
    }
}

// ---------------- HMMA causal flash attention (BQ=64, 2 CTAs/SM) --------
// 128 threads (4 warps x m16 rows), BKV=128, 2-stage depth-1 prefetch.
// CTA handles q-tiles (31-pair, pair) -> uniform 17 KV-tiles per CTA.
#define FPITCH 72                          // halves
#define FROWB  144
#define QBUF   (64 * FROWB)                // 9216 B
#define KVBUF  (128 * FROWB)               // 18432 B
#define OFF_QH 0
#define OFF_KV QBUF
#define KVSTG  (2 * KVBUF)                 // 36864 (K + V)
#define SMEM_FLASH (OFF_KV + 2 * KVSTG)    // 82944

__global__ __launch_bounds__(128, 2) void flash_mma(
    const __half* __restrict__ Qh,
    const __half* __restrict__ Kh, const __half* __restrict__ Vh,
    __half* __restrict__ Oh)
{
    extern __shared__ char sm[];
    const uint32_t smb = cvta_smem(sm);
    const int tid = threadIdx.x;
    const int w = tid >> 5, lane = tid & 31;
    const int pair = blockIdx.x;          // 0..15
    const int bh = blockIdx.y;            // 0..63

    const size_t seqbase = (size_t)bh * S_LEN * DK;

    const int laneA = (lane & 15) * FPITCH + ((lane >> 4) & 1) * 8;
    const int laneB = ((lane & 7) + ((lane >> 4) & 1) * 8) * FPITCH + ((lane >> 3) & 1) * 8;
    const int laneV = ((lane & 7) + ((lane >> 3) & 1) * 8) * FPITCH + ((lane >> 4) & 1) * 8;

    const float cs = 0.18033688f;         // (1/8) * log2(e)
    const int b = bh >> 4, h = bh & 15;
    const int cbase = (lane & 3) * 2;

    for (int ph = 0; ph < 2; ph++) {
        const int qi = ph == 0 ? (31 - pair) : pair;   // heavy tile first
        const int q0 = qi * 64;
        const int T = (qi + 2) >> 1;      // KV tiles of 128 cols
        const int rbase = q0 + w * 16 + (lane >> 2);

        if (ph == 1) __syncthreads();     // protect smem reuse across phases

        // load Q tile (64 rows)
#pragma unroll
        for (int i = 0; i < 4; i++) {
            int slot = tid + i * 128;
            int r = slot >> 3, quad = slot & 7;
            uint32_t so = (uint32_t)r * FROWB + (uint32_t)quad * 16u;
            size_t g = seqbase + (size_t)(q0 + r) * DK + quad * 8;
            cp16(smb + OFF_QH + so, Qh + g);
        }
        auto load_tile = [&](int kt, int stage) {
            const uint32_t sb = smb + OFF_KV + (uint32_t)stage * KVSTG;
#pragma unroll
            for (int i = 0; i < 8; i++) {
                int slot = tid + i * 128;
                int r = slot >> 3, quad = slot & 7;   // r: 0..127
                uint32_t so = (uint32_t)r * FROWB + (uint32_t)quad * 16u;
                size_t g = seqbase + (size_t)(kt * 128 + r) * DK + quad * 8;
                cp16(sb + 0 * KVBUF + so, Kh + g);
                cp16(sb + 1 * KVBUF + so, Vh + g);
            }
        };
        load_tile(0, 0); CP_COMMIT();

        uint32_t qhf[4][4];
        float oacc[8][4];
#pragma unroll
        for (int nf = 0; nf < 8; nf++)
#pragma unroll
            for (int j = 0; j < 4; j++) oacc[nf][j] = 0.0f;
        float m0r = -1e30f, m1r = -1e30f, l0r = 0.0f, l1r = 0.0f;

        for (int kt = 0; kt < T; kt++) {
            CP_WAIT(0);
            __syncthreads();

            if (kt == 0) {
#pragma unroll
                for (int ks = 0; ks < 4; ks++) {
                    uint32_t a = smb + OFF_QH +
                        (uint32_t)((w * 16) * FPITCH + ks * 16 + laneA) * 2;
                    ldsm4(qhf[ks], a);
                }
            }
            // depth-1 prefetch: overlaps with compute of this tile
            if (kt + 1 < T) {
                load_tile(kt + 1, (kt + 1) & 1);
                CP_COMMIT();
            }

            const uint32_t kvb = smb + OFF_KV + (uint32_t)(kt & 1) * KVSTG;

            // ---- S = Q K^T  (64 q-rows x 128 kv-cols) ----
            float sacc[16][4];
#pragma unroll
            for (int nf = 0; nf < 16; nf++)
#pragma unroll
                for (int j = 0; j < 4; j++) sacc[nf][j] = 0.0f;

#pragma unroll
            for (int ks = 0; ks < 4; ks++) {
                uint32_t kb[32];
#pragma unroll
                for (int nb = 0; nb < 8; nb++) {
                    uint32_t a = kvb +
                        (uint32_t)((nb * 16) * FPITCH + ks * 16 + laneB) * 2;
                    ldsm4(kb + nb * 4, a);
                }
#pragma unroll
                for (int nf = 0; nf < 16; nf++) {
                    int bi = (nf >> 1) * 4 + (nf & 1) * 2;
                    mma16816(sacc[nf], qhf[ks], kb[bi], kb[bi + 1]);
                }
            }

            // ---- scale (+ causal mask on the last tile) ----
            if (kt == T - 1) {
#pragma unroll
                for (int nf = 0; nf < 16; nf++) {
#pragma unroll
                    for (int j = 0; j < 4; j++) {
                        int col = kt * 128 + nf * 8 + cbase + (j & 1);
                        int row = rbase + ((j >> 1) << 3);
                        sacc[nf][j] = (col <= row) ? sacc[nf][j] * cs : -1e30f;
                    }
                }
            } else {
#pragma unroll
                for (int nf = 0; nf < 16; nf++)
#pragma unroll
                    for (int j = 0; j < 4; j++) sacc[nf][j] *= cs;
            }

            // ---- online softmax (base-2) ----
            float mx0 = -1e30f, mx1 = -1e30f;
#pragma unroll
            for (int nf = 0; nf < 16; nf++) {
                mx0 = fmaxf(mx0, fmaxf(sacc[nf][0], sacc[nf][1]));
                mx1 = fmaxf(mx1, fmaxf(sacc[nf][2], sacc[nf][3]));
            }
            mx0 = fmaxf(mx0, __shfl_xor_sync(0xffffffffu, mx0, 1));
            mx0 = fmaxf(mx0, __shfl_xor_sync(0xffffffffu, mx0, 2));
            mx1 = fmaxf(mx1, __shfl_xor_sync(0xffffffffu, mx1, 1));
            mx1 = fmaxf(mx1, __shfl_xor_sync(0xffffffffu, mx1, 2));

            float mn0 = fmaxf(m0r, mx0), mn1 = fmaxf(m1r, mx1);
            float c0 = ex2(m0r - mn0), c1 = ex2(m1r - mn1);
            m0r = mn0; m1r = mn1;

            uint32_t pHa[16], pHb[16];
            float ls0 = 0.0f, ls1 = 0.0f;
#pragma unroll
            for (int nf = 0; nf < 16; nf++) {
                float p0 = ex2(sacc[nf][0] - mn0);
                float p1 = ex2(sacc[nf][1] - mn0);
                float p2 = ex2(sacc[nf][2] - mn1);
                float p3 = ex2(sacc[nf][3] - mn1);
                ls0 += p0 + p1;
                ls1 += p2 + p3;
                __half2 h01 = __floats2half2_rn(p0, p1);
                __half2 h23 = __floats2half2_rn(p2, p3);
                pHa[nf] = *(uint32_t*)&h01;
                pHb[nf] = *(uint32_t*)&h23;
            }
            ls0 += __shfl_xor_sync(0xffffffffu, ls0, 1);
            ls0 += __shfl_xor_sync(0xffffffffu, ls0, 2);
            ls1 += __shfl_xor_sync(0xffffffffu, ls1, 1);
            ls1 += __shfl_xor_sync(0xffffffffu, ls1, 2);
            l0r = l0r * c0 + ls0;
            l1r = l1r * c1 + ls1;
#pragma unroll
            for (int nf = 0; nf < 8; nf++) {
                oacc[nf][0] *= c0; oacc[nf][1] *= c0;
                oacc[nf][2] *= c1; oacc[nf][3] *= c1;
            }

            // ---- O += P V  (P: 64x128, V: 128x64) ----
            const uint32_t vbb = kvb + KVBUF;
#pragma unroll
            for (int ks = 0; ks < 8; ks++) {
                uint32_t vb[16];
#pragma unroll
                for (int nb = 0; nb < 4; nb++) {
                    uint32_t a = vbb +
                        (uint32_t)((ks * 16) * FPITCH + nb * 16 + laneV) * 2;
                    ldsm4t(vb + nb * 4, a);
                }
                uint32_t pa[4] = { pHa[2 * ks], pHb[2 * ks],
                                   pHa[2 * ks + 1], pHb[2 * ks + 1] };
#pragma unroll
                for (int nf = 0; nf < 8; nf++) {
                    int bi = (nf >> 1) * 4 + (nf & 1) * 2;
                    mma16816(oacc[nf], pa, vb[bi], vb[bi + 1]);
                }
            }
        }

        // ---- epilogue: write fp16 context [B,S,1024] for this q-tile ----
        const float inv0 = 1.0f / l0r, inv1 = 1.0f / l1r;
        const int s0 = q0 + w * 16 + (lane >> 2);
#pragma unroll
        for (int nf = 0; nf < 8; nf++) {
            int col = h * DK + nf * 8 + cbase;
#pragma unroll
            for (int hh = 0; hh < 2; hh++) {
                int s = s0 + hh * 8;
                float vx = oacc[nf][hh * 2 + 0] * (hh ? inv1 : inv0);
                float vy = oacc[nf][hh * 2 + 1] * (hh ? inv1 : inv0);
                size_t idx = ((size_t)(b * S_LEN + s)) * DMODEL + col;
                *(__half2*)(Oh + idx) = __floats2half2_rn(vx, vy);
            }
        }
    }
}

// ===========================================================================
extern "C" void kernel_launch(void* const* d_in, const int* in_sizes, int n_in,
                              void* d_out, int out_size)
{
    const float* query = (const float*)d_in[0];
    const float* key   = (const float*)d_in[1];
    const float* value = (const float*)d_in[2];
    // d_in[3] = causal mask — handled analytically.
    const float* Wq = (const float*)d_in[4];
    const float* bq = (const float*)d_in[5];
    const float* Wk = (const float*)d_in[6];
    const float* bk = (const float*)d_in[7];
    const float* Wv = (const float*)d_in[8];
    const float* bv = (const float*)d_in[9];
    const float* Wo = (const float*)d_in[10];
    const float* bo = (const float*)d_in[11];
    float* out = (float*)d_out;

    __half *Aq, *Ak, *Av, *Qh, *Kh, *Vh, *Wqh, *Wkh, *Wvh, *Woh;
    cudaGetSymbolAddress((void**)&Aq, g_Aq);
    cudaGetSymbolAddress((void**)&Ak, g_Ak);
    cudaGetSymbolAddress((void**)&Av, g_Av);
    cudaGetSymbolAddress((void**)&Qh, g_Qh);
    cudaGetSymbolAddress((void**)&Kh, g_Kh);
    cudaGetSymbolAddress((void**)&Vh, g_Vh);
    cudaGetSymbolAddress((void**)&Wqh, g_Wqh);
    cudaGetSymbolAddress((void**)&Wkh, g_Wkh);
    cudaGetSymbolAddress((void**)&Wvh, g_Wvh);
    cudaGetSymbolAddress((void**)&Woh, g_Woh);

    cudaFuncSetAttribute(proj_gemm_mma<1>,
                         cudaFuncAttributeMaxDynamicSharedMemorySize, SMEM_GEMM);
    cudaFuncSetAttribute(proj_gemm_mma<0>,
                         cudaFuncAttributeMaxDynamicSharedMemorySize, SMEM_GEMM);
    cudaFuncSetAttribute(flash_mma,
                         cudaFuncAttributeMaxDynamicSharedMemorySize, SMEM_FLASH);

    // one consolidated conversion pass
    split_all<<<SPLIT_GRID, 256>>>(
        (const float4*)query, (const float4*)key, (const float4*)value,
        (const float4*)Wq, (const float4*)Wk, (const float4*)Wv, (const float4*)Wo,
        (uint2*)Aq, (uint2*)Ak, (uint2*)Av,
        (uint2*)Wqh, (uint2*)Wkh, (uint2*)Wvh, (uint2*)Woh);

    // Q, K, V projections batched in one launch
    dim3 gq(DMODEL / TILE_N, MTOT / TILE_M, 3);   // (8, 64, 3)
    proj_gemm_mma<1><<<gq, 128, SMEM_GEMM>>>(
        Aq, Ak, Av, Wqh, Wkh, Wvh, bq, bk, bv, Qh, Kh, Vh, nullptr);

    // attention: writes fp16 context into Aq
    flash_mma<<<dim3(16, BATCH * NHEAD), 128, SMEM_FLASH>>>(Qh, Kh, Vh, Aq);

    // out = Ctx @ Wo^T + bo (fp32 out)
    dim3 go(DMODEL / TILE_N, MTOT / TILE_M, 1);
    proj_gemm_mma<0><<<go, 128, SMEM_GEMM>>>(
        Aq, nullptr, nullptr, Woh, nullptr, nullptr,
        bo, nullptr, nullptr, nullptr, nullptr, nullptr, out);
}

// round 12
// speedup vs baseline: 10.2183x; 1.0369x over previous
#include <cuda_runtime.h>
#include <cuda_fp16.h>
#include <cstdint>

#define S_LEN  2048
#define DMODEL 1024
#define NHEAD  16
#define DK     64
#define BATCH  4
#define MTOT   (BATCH * S_LEN)     // 8192

// ---------------- scratch (module-scope device memory) ----------------
__device__ __half g_Aq[MTOT * DMODEL];   // query f16 (later: ctx f16)
__device__ __half g_Ak[MTOT * DMODEL];   // key f16
__device__ __half g_Av[MTOT * DMODEL];   // value f16
__device__ __half g_Qh[BATCH * NHEAD * S_LEN * DK];
__device__ __half g_Kh[BATCH * NHEAD * S_LEN * DK];
__device__ __half g_Vh[BATCH * NHEAD * S_LEN * DK];
__device__ __half g_Wqh[DMODEL * DMODEL];
__device__ __half g_Wkh[DMODEL * DMODEL];
__device__ __half g_Wvh[DMODEL * DMODEL];
__device__ __half g_Woh[DMODEL * DMODEL];

// ---------------- PTX helpers (baseline PTX only) ----------------------
__device__ __forceinline__ uint32_t cvta_smem(const void* p) {
    uint32_t a;
    asm("{ .reg .u64 t; cvta.to.shared.u64 t, %1; cvt.u32.u64 %0, t; }"
        : "=r"(a) : "l"(p));
    return a;
}
__device__ __forceinline__ void cp16(uint32_t dst, const void* src) {
    asm volatile("cp.async.cg.shared.global [%0], [%1], 16;"
                 :: "r"(dst), "l"(src));
}
#define CP_COMMIT() asm volatile("cp.async.commit_group;" ::: "memory")
#define CP_WAIT(n)  asm volatile("cp.async.wait_group %0;" :: "n"(n) : "memory")

__device__ __forceinline__ void ldsm4(uint32_t* r, uint32_t addr) {
    asm volatile("ldmatrix.sync.aligned.m8n8.x4.shared.b16 {%0,%1,%2,%3}, [%4];"
                 : "=r"(r[0]), "=r"(r[1]), "=r"(r[2]), "=r"(r[3]) : "r"(addr));
}
__device__ __forceinline__ void ldsm4t(uint32_t* r, uint32_t addr) {
    asm volatile("ldmatrix.sync.aligned.m8n8.x4.trans.shared.b16 {%0,%1,%2,%3}, [%4];"
                 : "=r"(r[0]), "=r"(r[1]), "=r"(r[2]), "=r"(r[3]) : "r"(addr));
}
__device__ __forceinline__ void mma16816(float* d, const uint32_t* a,
                                         uint32_t b0, uint32_t b1) {
    asm volatile(
        "mma.sync.aligned.m16n8k16.row.col.f32.f16.f16.f32 "
        "{%0,%1,%2,%3}, {%4,%5,%6,%7}, {%8,%9}, {%0,%1,%2,%3};"
        : "+f"(d[0]), "+f"(d[1]), "+f"(d[2]), "+f"(d[3])
        : "r"(a[0]), "r"(a[1]), "r"(a[2]), "r"(a[3]), "r"(b0), "r"(b1));
}
__device__ __forceinline__ float ex2(float x) {
    float y;
    asm("ex2.approx.f32 %0, %1;" : "=f"(y) : "f"(x));
    return y;
}

__device__ __forceinline__ uint2 pack_hi(float4 v) {
    __half h0 = __float2half_rn(v.x), h1 = __float2half_rn(v.y);
    __half h2 = __float2half_rn(v.z), h3 = __float2half_rn(v.w);
    uint2 H;
    H.x = (uint32_t)__half_as_ushort(h0) | ((uint32_t)__half_as_ushort(h1) << 16);
    H.y = (uint32_t)__half_as_ushort(h2) | ((uint32_t)__half_as_ushort(h3) << 16);
    return H;
}

// ---------------- single consolidated split kernel ----------------------
#define ACT_BLKS  8192        // (MTOT*DMODEL/4)/256
#define W_BLKS    1024        // (DMODEL*DMODEL/4)/256
#define SPLIT_GRID (3 * ACT_BLKS + 4 * W_BLKS)

__global__ __launch_bounds__(256) void split_all(
    const float4* __restrict__ q, const float4* __restrict__ k,
    const float4* __restrict__ v,
    const float4* __restrict__ wq, const float4* __restrict__ wk,
    const float4* __restrict__ wv, const float4* __restrict__ wo,
    uint2* __restrict__ aq, uint2* __restrict__ ak, uint2* __restrict__ av,
    uint2* __restrict__ wqh, uint2* __restrict__ wkh,
    uint2* __restrict__ wvh, uint2* __restrict__ woh)
{
    const int b = blockIdx.x, t = threadIdx.x;
    if (b < 3 * ACT_BLKS) {
        const int which = b / ACT_BLKS;
        const int i = (b % ACT_BLKS) * 256 + t;
        const float4* src = which == 0 ? q : (which == 1 ? k : v);
        uint2* dst = which == 0 ? aq : (which == 1 ? ak : av);
        dst[i] = pack_hi(src[i]);
    } else {
        const int wb = b - 3 * ACT_BLKS;
        const int which = wb / W_BLKS;
        const int i = (wb % W_BLKS) * 256 + t;
        const float4* src = which == 0 ? wq : (which == 1 ? wk
                          : (which == 2 ? wv : wo));
        uint2* dst = which == 0 ? wqh : (which == 1 ? wkh
                   : (which == 2 ? wvh : woh));
        dst[i] = pack_hi(src[i]);
    }
}

// ---------------- HMMA projection GEMM (128x64 tile, 3 CTAs/SM) ---------
// C = A[M,1024] @ W[1024,1024]^T + bias.  A, W fp16 (1-pass).
// QKV=1: grid.z selects (A,W,bias,C) set, head-split fp16 output.
// QKV=0: single fp32 output GEMM.
// 4 warps (128 thr), warp tile 64x32, K-chunk 64, 2-stage pipeline.
#define TILE_M 128
#define TILE_N 64
#define KCH    64
#define NC     (DMODEL / KCH)  // 16
#define PITCH  72              // halves per smem row (144B)
#define ROWB   144
#define A_OFF  0
#define B_OFF  (128 * ROWB)              // 18432
#define STG_B  (B_OFF + 64 * ROWB)       // 27648
#define SMEM_GEMM (2 * STG_B)            // 55296

template <int QKV>
__global__ __launch_bounds__(128, 3) void proj_gemm_mma(
    const __half* __restrict__ A0, const __half* __restrict__ A1,
    const __half* __restrict__ A2,
    const __half* __restrict__ W0, const __half* __restrict__ W1,
    const __half* __restrict__ W2,
    const float* __restrict__ b0, const float* __restrict__ b1,
    const float* __restrict__ b2,
    __half* __restrict__ C0, __half* __restrict__ C1,
    __half* __restrict__ C2, float* __restrict__ Cf)
{
    extern __shared__ char sm[];
    const uint32_t smb = cvta_smem(sm);
    const int tid = threadIdx.x;
    const int wid = tid >> 5, lane = tid & 31;
    const int wm = wid & 1;          // 2 m-slices of 64
    const int wn = wid >> 1;         // 2 n-slices of 32
    const int m0 = blockIdx.y * TILE_M;
    const int n0 = blockIdx.x * TILE_N;

    const __half* Ahg; const __half* Whg; const float* bias; __half* Ch;
    if (QKV) {
        const int z = blockIdx.z;
        Ahg  = z == 0 ? A0 : (z == 1 ? A1 : A2);
        Whg  = z == 0 ? W0 : (z == 1 ? W1 : W2);
        bias = z == 0 ? b0 : (z == 1 ? b1 : b2);
        Ch   = z == 0 ? C0 : (z == 1 ? C1 : C2);
    } else {
        Ahg = A0; Whg = W0; bias = b0; Ch = nullptr;
    }

    const int laneA = (lane & 15) * PITCH + ((lane >> 4) & 1) * 8;
    const int laneB = ((lane & 7) + ((lane >> 4) & 1) * 8) * PITCH + ((lane >> 3) & 1) * 8;

    auto load_chunk = [&](int c, int stage) {
        const uint32_t sbase = smb + (uint32_t)stage * STG_B;
        // A: 128 rows x 8 quads = 1024 slots; 128 threads -> 8 iters
#pragma unroll
        for (int i = 0; i < 8; i++) {
            int slot = tid + i * 128;
            int row = slot >> 3, quad = slot & 7;
            uint32_t soff = (uint32_t)row * ROWB + (uint32_t)quad * 16u;
            size_t goff = (size_t)(m0 + row) * DMODEL + c * KCH + quad * 8;
            cp16(sbase + A_OFF + soff, Ahg + goff);
        }
        // B: 64 rows x 8 quads = 512 slots; 4 iters
#pragma unroll
        for (int i = 0; i < 4; i++) {
            int slot = tid + i * 128;
            int row = slot >> 3, quad = slot & 7;
            uint32_t soff = (uint32_t)row * ROWB + (uint32_t)quad * 16u;
            size_t goff = (size_t)(n0 + row) * DMODEL + c * KCH + quad * 8;
            cp16(sbase + B_OFF + soff, Whg + goff);
        }
    };

    float acc[4][4][4];
#pragma unroll
    for (int mf = 0; mf < 4; mf++)
#pragma unroll
        for (int nf = 0; nf < 4; nf++)
#pragma unroll
            for (int j = 0; j < 4; j++) acc[mf][nf][j] = 0.0f;

    load_chunk(0, 0); CP_COMMIT();

    for (int c = 0; c < NC; c++) {
        CP_WAIT(0);
        __syncthreads();
        if (c + 1 < NC) {
            load_chunk(c + 1, (c + 1) & 1);
            CP_COMMIT();
        }

        const uint32_t sbase = smb + (uint32_t)(c & 1) * STG_B;

#pragma unroll
        for (int ks = 0; ks < 4; ks++) {
            const int kk = ks * 16;
            uint32_t ah[4][4], bh[8];
#pragma unroll
            for (int mf = 0; mf < 4; mf++) {
                uint32_t idx = (uint32_t)((wm * 64 + mf * 16) * PITCH + kk + laneA) * 2;
                ldsm4(ah[mf], sbase + A_OFF + idx);
            }
#pragma unroll
            for (int nf2 = 0; nf2 < 2; nf2++) {
                uint32_t idx = (uint32_t)((wn * 32 + nf2 * 16) * PITCH + kk + laneB) * 2;
                ldsm4(bh + nf2 * 4, sbase + B_OFF + idx);
            }
#pragma unroll
            for (int mf = 0; mf < 4; mf++)
#pragma unroll
                for (int nf = 0; nf < 4; nf++) {
                    int bi = (nf >> 1) * 4 + (nf & 1) * 2;
                    mma16816(acc[mf][nf], ah[mf], bh[bi], bh[bi + 1]);
                }
        }
        __syncthreads();
    }

    // epilogue
#pragma unroll
    for (int mf = 0; mf < 4; mf++) {
#pragma unroll
        for (int nf = 0; nf < 4; nf++) {
            int m = m0 + wm * 64 + mf * 16 + (lane >> 2);
            int n = n0 + wn * 32 + nf * 8 + (lane & 3) * 2;
            float bx = bias[n], by = bias[n + 1];
#pragma unroll
            for (int hh = 0; hh < 2; hh++) {
                int mm = m + hh * 8;
                float vx = acc[mf][nf][hh * 2 + 0] + bx;
                float vy = acc[mf][nf][hh * 2 + 1] + by;
                if (QKV) {
                    int b = mm >> 11, s = mm & (S_LEN - 1);
                    int h = n >> 6, d = n & (DK - 1);
                    size_t idx = ((size_t)((b << 4) + h) * S_LEN + s) * DK + d;
                    *(__half2*)(Ch + idx) = __floats2half2_rn(vx, vy);
                } else {
                    float2 v; v.x = vx; v.y = vy;
                    *(float2*)(Cf + (size_t)mm * DMODEL + n) = v;
                }
            }
        }
    }
}

// ---------------- HMMA causal flash attention (BQ=64, 2 CTAs/SM) --------
// 128 threads (4 warps x m16 rows), BKV=128, 2-stage depth-1 prefetch.
// CTA handles q-tiles (31-pair, pair) -> uniform 17 KV-tiles per CTA.
#define FPITCH 72                          // halves
#define FROWB  144
#define QBUF   (64 * FROWB)                // 9216 B
#define KVBUF  (128 * FROWB)               // 18432 B
#define OFF_QH 0
#define OFF_KV QBUF
#define KVSTG  (2 * KVBUF)                 // 36864 (K + V)
#define SMEM_FLASH (OFF_KV + 2 * KVSTG)    // 82944

__global__ __launch_bounds__(128, 2) void flash_mma(
    const __half* __restrict__ Qh,
    const __half* __restrict__ Kh, const __half* __restrict__ Vh,
    __half* __restrict__ Oh)
{
    extern __shared__ char sm[];
    const uint32_t smb = cvta_smem(sm);
    const int tid = threadIdx.x;
    const int w = tid >> 5, lane = tid & 31;
    const int pair = blockIdx.x;          // 0..15
    const int bh = blockIdx.y;            // 0..63

    const size_t seqbase = (size_t)bh * S_LEN * DK;

    const int laneA = (lane & 15) * FPITCH + ((lane >> 4) & 1) * 8;
    const int laneB = ((lane & 7) + ((lane >> 4) & 1) * 8) * FPITCH + ((lane >> 3) & 1) * 8;
    const int laneV = ((lane & 7) + ((lane >> 3) & 1) * 8) * FPITCH + ((lane >> 4) & 1) * 8;

    const float cs = 0.18033688f;         // (1/8) * log2(e)
    const int b = bh >> 4, h = bh & 15;
    const int cbase = (lane & 3) * 2;

    for (int ph = 0; ph < 2; ph++) {
        const int qi = ph == 0 ? (31 - pair) : pair;   // heavy tile first
        const int q0 = qi * 64;
        const int T = (qi + 2) >> 1;      // KV tiles of 128 cols
        const int rbase = q0 + w * 16 + (lane >> 2);

        if (ph == 1) __syncthreads();     // protect smem reuse across phases

        // load Q tile (64 rows)
#pragma unroll
        for (int i = 0; i < 4; i++) {
            int slot = tid + i * 128;
            int r = slot >> 3, quad = slot & 7;
            uint32_t so = (uint32_t)r * FROWB + (uint32_t)quad * 16u;
            size_t g = seqbase + (size_t)(q0 + r) * DK + quad * 8;
            cp16(smb + OFF_QH + so, Qh + g);
        }
        auto load_tile = [&](int kt, int stage) {
            const uint32_t sb = smb + OFF_KV + (uint32_t)stage * KVSTG;
#pragma unroll
            for (int i = 0; i < 8; i++) {
                int slot = tid + i * 128;
                int r = slot >> 3, quad = slot & 7;   // r: 0..127
                uint32_t so = (uint32_t)r * FROWB + (uint32_t)quad * 16u;
                size_t g = seqbase + (size_t)(kt * 128 + r) * DK + quad * 8;
                cp16(sb + 0 * KVBUF + so, Kh + g);
                cp16(sb + 1 * KVBUF + so, Vh + g);
            }
        };
        load_tile(0, 0); CP_COMMIT();

        uint32_t qhf[4][4];
        float oacc[8][4];
#pragma unroll
        for (int nf = 0; nf < 8; nf++)
#pragma unroll
            for (int j = 0; j < 4; j++) oacc[nf][j] = 0.0f;
        float m0r = -1e30f, m1r = -1e30f, l0r = 0.0f, l1r = 0.0f;

        for (int kt = 0; kt < T; kt++) {
            CP_WAIT(0);
            __syncthreads();

            if (kt == 0) {
#pragma unroll
                for (int ks = 0; ks < 4; ks++) {
                    uint32_t a = smb + OFF_QH +
                        (uint32_t)((w * 16) * FPITCH + ks * 16 + laneA) * 2;
                    ldsm4(qhf[ks], a);
                }
            }
            // depth-1 prefetch: overlaps with compute of this tile
            if (kt + 1 < T) {
                load_tile(kt + 1, (kt + 1) & 1);
                CP_COMMIT();
            }

            const uint32_t kvb = smb + OFF_KV + (uint32_t)(kt & 1) * KVSTG;

            // ---- S = Q K^T  (64 q-rows x 128 kv-cols) ----
            float sacc[16][4];
#pragma unroll
            for (int nf = 0; nf < 16; nf++)
#pragma unroll
                for (int j = 0; j < 4; j++) sacc[nf][j] = 0.0f;

#pragma unroll
            for (int ks = 0; ks < 4; ks++) {
                uint32_t kb[32];
#pragma unroll
                for (int nb = 0; nb < 8; nb++) {
                    uint32_t a = kvb +
                        (uint32_t)((nb * 16) * FPITCH + ks * 16 + laneB) * 2;
                    ldsm4(kb + nb * 4, a);
                }
#pragma unroll
                for (int nf = 0; nf < 16; nf++) {
                    int bi = (nf >> 1) * 4 + (nf & 1) * 2;
                    mma16816(sacc[nf], qhf[ks], kb[bi], kb[bi + 1]);
                }
            }

            // ---- scale (+ causal mask on the last tile) ----
            if (kt == T - 1) {
#pragma unroll
                for (int nf = 0; nf < 16; nf++) {
#pragma unroll
                    for (int j = 0; j < 4; j++) {
                        int col = kt * 128 + nf * 8 + cbase + (j & 1);
                        int row = rbase + ((j >> 1) << 3);
                        sacc[nf][j] = (col <= row) ? sacc[nf][j] * cs : -1e30f;
                    }
                }
            } else {
#pragma unroll
                for (int nf = 0; nf < 16; nf++)
#pragma unroll
                    for (int j = 0; j < 4; j++) sacc[nf][j] *= cs;
            }

            // ---- online softmax (base-2) ----
            float mx0 = -1e30f, mx1 = -1e30f;
#pragma unroll
            for (int nf = 0; nf < 16; nf++) {
                mx0 = fmaxf(mx0, fmaxf(sacc[nf][0], sacc[nf][1]));
                mx1 = fmaxf(mx1, fmaxf(sacc[nf][2], sacc[nf][3]));
            }
            mx0 = fmaxf(mx0, __shfl_xor_sync(0xffffffffu, mx0, 1));
            mx0 = fmaxf(mx0, __shfl_xor_sync(0xffffffffu, mx0, 2));
            mx1 = fmaxf(mx1, __shfl_xor_sync(0xffffffffu, mx1, 1));
            mx1 = fmaxf(mx1, __shfl_xor_sync(0xffffffffu, mx1, 2));

            float mn0 = fmaxf(m0r, mx0), mn1 = fmaxf(m1r, mx1);
            float c0 = ex2(m0r - mn0), c1 = ex2(m1r - mn1);
            m0r = mn0; m1r = mn1;

            uint32_t pHa[16], pHb[16];
            float ls0 = 0.0f, ls1 = 0.0f;
#pragma unroll
            for (int nf = 0; nf < 16; nf++) {
                float p0 = ex2(sacc[nf][0] - mn0);
                float p1 = ex2(sacc[nf][1] - mn0);
                float p2 = ex2(sacc[nf][2] - mn1);
                float p3 = ex2(sacc[nf][3] - mn1);
                ls0 += p0 + p1;
                ls1 += p2 + p3;
                __half2 h01 = __floats2half2_rn(p0, p1);
                __half2 h23 = __floats2half2_rn(p2, p3);
                pHa[nf] = *(uint32_t*)&h01;
                pHb[nf] = *(uint32_t*)&h23;
            }
            ls0 += __shfl_xor_sync(0xffffffffu, ls0, 1);
            ls0 += __shfl_xor_sync(0xffffffffu, ls0, 2);
            ls1 += __shfl_xor_sync(0xffffffffu, ls1, 1);
            ls1 += __shfl_xor_sync(0xffffffffu, ls1, 2);
            l0r = l0r * c0 + ls0;
            l1r = l1r * c1 + ls1;
#pragma unroll
            for (int nf = 0; nf < 8; nf++) {
                oacc[nf][0] *= c0; oacc[nf][1] *= c0;
                oacc[nf][2] *= c1; oacc[nf][3] *= c1;
            }

            // ---- O += P V  (P: 64x128, V: 128x64) ----
            const uint32_t vbb = kvb + KVBUF;
#pragma unroll
            for (int ks = 0; ks < 8; ks++) {
                uint32_t vb[16];
#pragma unroll
                for (int nb = 0; nb < 4; nb++) {
                    uint32_t a = vbb +
                        (uint32_t)((ks * 16) * FPITCH + nb * 16 + laneV) * 2;
                    ldsm4t(vb + nb * 4, a);
                }
                uint32_t pa[4] = { pHa[2 * ks], pHb[2 * ks],
                                   pHa[2 * ks + 1], pHb[2 * ks + 1] };
#pragma unroll
                for (int nf = 0; nf < 8; nf++) {
                    int bi = (nf >> 1) * 4 + (nf & 1) * 2;
                    mma16816(oacc[nf], pa, vb[bi], vb[bi + 1]);
                }
            }
        }

        // ---- epilogue: write fp16 context [B,S,1024] for this q-tile ----
        const float inv0 = 1.0f / l0r, inv1 = 1.0f / l1r;
        const int s0 = q0 + w * 16 + (lane >> 2);
#pragma unroll
        for (int nf = 0; nf < 8; nf++) {
            int col = h * DK + nf * 8 + cbase;
#pragma unroll
            for (int hh = 0; hh < 2; hh++) {
                int s = s0 + hh * 8;
                float vx = oacc[nf][hh * 2 + 0] * (hh ? inv1 : inv0);
                float vy = oacc[nf][hh * 2 + 1] * (hh ? inv1 : inv0);
                size_t idx = ((size_t)(b * S_LEN + s)) * DMODEL + col;
                *(__half2*)(Oh + idx) = __floats2half2_rn(vx, vy);
            }
        }
    }
}

// ===========================================================================
extern "C" void kernel_launch(void* const* d_in, const int* in_sizes, int n_in,
                              void* d_out, int out_size)
{
    const float* query = (const float*)d_in[0];
    const float* key   = (const float*)d_in[1];
    const float* value = (const float*)d_in[2];
    // d_in[3] = causal mask — handled analytically.
    const float* Wq = (const float*)d_in[4];
    const float* bq = (const float*)d_in[5];
    const float* Wk = (const float*)d_in[6];
    const float* bk = (const float*)d_in[7];
    const float* Wv = (const float*)d_in[8];
    const float* bv = (const float*)d_in[9];
    const float* Wo = (const float*)d_in[10];
    const float* bo = (const float*)d_in[11];
    float* out = (float*)d_out;

    __half *Aq, *Ak, *Av, *Qh, *Kh, *Vh, *Wqh, *Wkh, *Wvh, *Woh;
    cudaGetSymbolAddress((void**)&Aq, g_Aq);
    cudaGetSymbolAddress((void**)&Ak, g_Ak);
    cudaGetSymbolAddress((void**)&Av, g_Av);
    cudaGetSymbolAddress((void**)&Qh, g_Qh);
    cudaGetSymbolAddress((void**)&Kh, g_Kh);
    cudaGetSymbolAddress((void**)&Vh, g_Vh);
    cudaGetSymbolAddress((void**)&Wqh, g_Wqh);
    cudaGetSymbolAddress((void**)&Wkh, g_Wkh);
    cudaGetSymbolAddress((void**)&Wvh, g_Wvh);
    cudaGetSymbolAddress((void**)&Woh, g_Woh);

    cudaFuncSetAttribute(proj_gemm_mma<1>,
                         cudaFuncAttributeMaxDynamicSharedMemorySize, SMEM_GEMM);
    cudaFuncSetAttribute(proj_gemm_mma<0>,
                         cudaFuncAttributeMaxDynamicSharedMemorySize, SMEM_GEMM);
    cudaFuncSetAttribute(flash_mma,
                         cudaFuncAttributeMaxDynamicSharedMemorySize, SMEM_FLASH);

    // one consolidated conversion pass
    split_all<<<SPLIT_GRID, 256>>>(
        (const float4*)query, (const float4*)key, (const float4*)value,
        (const float4*)Wq, (const float4*)Wk, (const float4*)Wv, (const float4*)Wo,
        (uint2*)Aq, (uint2*)Ak, (uint2*)Av,
        (uint2*)Wqh, (uint2*)Wkh, (uint2*)Wvh, (uint2*)Woh);

    // Q, K, V projections batched in one launch
    dim3 gq(DMODEL / TILE_N, MTOT / TILE_M, 3);   // (16, 64, 3)
    proj_gemm_mma<1><<<gq, 128, SMEM_GEMM>>>(
        Aq, Ak, Av, Wqh, Wkh, Wvh, bq, bk, bv, Qh, Kh, Vh, nullptr);

    // attention: writes fp16 context into Aq
    flash_mma<<<dim3(16, BATCH * NHEAD), 128, SMEM_FLASH>>>(Qh, Kh, Vh, Aq);

    // out = Ctx @ Wo^T + bo (fp32 out)
    dim3 go(DMODEL / TILE_N, MTOT / TILE_M, 1);   // (16, 64)
    proj_gemm_mma<0><<<go, 128, SMEM_GEMM>>>(
        Aq, nullptr, nullptr, Woh, nullptr, nullptr,
        bo, nullptr, nullptr, nullptr, nullptr, nullptr, out);
}

// round 13
// speedup vs baseline: 10.5530x; 1.0328x over previous
#include <cuda_runtime.h>
#include <cuda_fp16.h>
#include <cstdint>

#define S_LEN  2048
#define DMODEL 1024
#define NHEAD  16
#define DK     64
#define BATCH  4
#define MTOT   (BATCH * S_LEN)     // 8192

// ---------------- scratch (module-scope device memory) ----------------
__device__ __half g_Aq[MTOT * DMODEL];   // query f16 (later: ctx f16)
__device__ __half g_Ak[MTOT * DMODEL];   // key f16
__device__ __half g_Av[MTOT * DMODEL];   // value f16
__device__ __half g_Qh[BATCH * NHEAD * S_LEN * DK];
__device__ __half g_Kh[BATCH * NHEAD * S_LEN * DK];
__device__ __half g_Vh[BATCH * NHEAD * S_LEN * DK];
__device__ __half g_Wqh[DMODEL * DMODEL];
__device__ __half g_Wkh[DMODEL * DMODEL];
__device__ __half g_Wvh[DMODEL * DMODEL];
__device__ __half g_Woh[DMODEL * DMODEL];

// ---------------- PTX helpers (baseline PTX only) ----------------------
__device__ __forceinline__ uint32_t cvta_smem(const void* p) {
    uint32_t a;
    asm("{ .reg .u64 t; cvta.to.shared.u64 t, %1; cvt.u32.u64 %0, t; }"
        : "=r"(a) : "l"(p));
    return a;
}
__device__ __forceinline__ void cp16(uint32_t dst, const void* src) {
    asm volatile("cp.async.cg.shared.global [%0], [%1], 16;"
                 :: "r"(dst), "l"(src));
}
#define CP_COMMIT() asm volatile("cp.async.commit_group;" ::: "memory")
#define CP_WAIT(n)  asm volatile("cp.async.wait_group %0;" :: "n"(n) : "memory")

__device__ __forceinline__ void ldsm4(uint32_t* r, uint32_t addr) {
    asm volatile("ldmatrix.sync.aligned.m8n8.x4.shared.b16 {%0,%1,%2,%3}, [%4];"
                 : "=r"(r[0]), "=r"(r[1]), "=r"(r[2]), "=r"(r[3]) : "r"(addr));
}
__device__ __forceinline__ void ldsm4t(uint32_t* r, uint32_t addr) {
    asm volatile("ldmatrix.sync.aligned.m8n8.x4.trans.shared.b16 {%0,%1,%2,%3}, [%4];"
                 : "=r"(r[0]), "=r"(r[1]), "=r"(r[2]), "=r"(r[3]) : "r"(addr));
}
__device__ __forceinline__ void mma16816(float* d, const uint32_t* a,
                                         uint32_t b0, uint32_t b1) {
    asm volatile(
        "mma.sync.aligned.m16n8k16.row.col.f32.f16.f16.f32 "
        "{%0,%1,%2,%3}, {%4,%5,%6,%7}, {%8,%9}, {%0,%1,%2,%3};"
        : "+f"(d[0]), "+f"(d[1]), "+f"(d[2]), "+f"(d[3])
        : "r"(a[0]), "r"(a[1]), "r"(a[2]), "r"(a[3]), "r"(b0), "r"(b1));
}
__device__ __forceinline__ float ex2(float x) {
    float y;
    asm("ex2.approx.f32 %0, %1;" : "=f"(y) : "f"(x));
    return y;
}

__device__ __forceinline__ uint2 pack_hi(float4 v) {
    __half h0 = __float2half_rn(v.x), h1 = __float2half_rn(v.y);
    __half h2 = __float2half_rn(v.z), h3 = __float2half_rn(v.w);
    uint2 H;
    H.x = (uint32_t)__half_as_ushort(h0) | ((uint32_t)__half_as_ushort(h1) << 16);
    H.y = (uint32_t)__half_as_ushort(h2) | ((uint32_t)__half_as_ushort(h3) << 16);
    return H;
}

// ---------------- single consolidated split kernel (MLP=4) --------------
#define ACT_BLKS  2048        // (MTOT*DMODEL/4)/256/4
#define W_BLKS    256         // (DMODEL*DMODEL/4)/256/4
#define SPLIT_GRID (3 * ACT_BLKS + 4 * W_BLKS)

__global__ __launch_bounds__(256) void split_all(
    const float4* __restrict__ q, const float4* __restrict__ k,
    const float4* __restrict__ v,
    const float4* __restrict__ wq, const float4* __restrict__ wk,
    const float4* __restrict__ wv, const float4* __restrict__ wo,
    uint2* __restrict__ aq, uint2* __restrict__ ak, uint2* __restrict__ av,
    uint2* __restrict__ wqh, uint2* __restrict__ wkh,
    uint2* __restrict__ wvh, uint2* __restrict__ woh)
{
    const int b = blockIdx.x, t = threadIdx.x;
    const float4* src;
    uint2* dst;
    int base;
    if (b < 3 * ACT_BLKS) {
        const int which = b / ACT_BLKS;
        base = (b % ACT_BLKS) * 1024 + t;
        src = which == 0 ? q : (which == 1 ? k : v);
        dst = which == 0 ? aq : (which == 1 ? ak : av);
    } else {
        const int wb = b - 3 * ACT_BLKS;
        const int which = wb / W_BLKS;
        base = (wb % W_BLKS) * 1024 + t;
        src = which == 0 ? wq : (which == 1 ? wk : (which == 2 ? wv : wo));
        dst = which == 0 ? wqh : (which == 1 ? wkh : (which == 2 ? wvh : woh));
    }
    float4 v0 = src[base];
    float4 v1 = src[base + 256];
    float4 v2 = src[base + 512];
    float4 v3 = src[base + 768];
    dst[base]       = pack_hi(v0);
    dst[base + 256] = pack_hi(v1);
    dst[base + 512] = pack_hi(v2);
    dst[base + 768] = pack_hi(v3);
}

// ---------------- HMMA projection GEMM (128x64 tile, 3 CTAs/SM) ---------
#define TILE_M 128
#define TILE_N 64
#define KCH    64
#define NC     (DMODEL / KCH)  // 16
#define PITCH  72              // halves per smem row (144B)
#define ROWB   144
#define A_OFF  0
#define B_OFF  (128 * ROWB)              // 18432
#define STG_B  (B_OFF + 64 * ROWB)       // 27648
#define SMEM_GEMM (2 * STG_B)            // 55296

template <int QKV>
__global__ __launch_bounds__(128, 3) void proj_gemm_mma(
    const __half* __restrict__ A0, const __half* __restrict__ A1,
    const __half* __restrict__ A2,
    const __half* __restrict__ W0, const __half* __restrict__ W1,
    const __half* __restrict__ W2,
    const float* __restrict__ b0, const float* __restrict__ b1,
    const float* __restrict__ b2,
    __half* __restrict__ C0, __half* __restrict__ C1,
    __half* __restrict__ C2, float* __restrict__ Cf)
{
    extern __shared__ char sm[];
    const uint32_t smb = cvta_smem(sm);
    const int tid = threadIdx.x;
    const int wid = tid >> 5, lane = tid & 31;
    const int wm = wid & 1;
    const int wn = wid >> 1;
    const int m0 = blockIdx.y * TILE_M;
    const int n0 = blockIdx.x * TILE_N;

    const __half* Ahg; const __half* Whg; const float* bias; __half* Ch;
    if (QKV) {
        const int z = blockIdx.z;
        Ahg  = z == 0 ? A0 : (z == 1 ? A1 : A2);
        Whg  = z == 0 ? W0 : (z == 1 ? W1 : W2);
        bias = z == 0 ? b0 : (z == 1 ? b1 : b2);
        Ch   = z == 0 ? C0 : (z == 1 ? C1 : C2);
    } else {
        Ahg = A0; Whg = W0; bias = b0; Ch = nullptr;
    }

    const int laneA = (lane & 15) * PITCH + ((lane >> 4) & 1) * 8;
    const int laneB = ((lane & 7) + ((lane >> 4) & 1) * 8) * PITCH + ((lane >> 3) & 1) * 8;

    auto load_chunk = [&](int c, int stage) {
        const uint32_t sbase = smb + (uint32_t)stage * STG_B;
#pragma unroll
        for (int i = 0; i < 8; i++) {
            int slot = tid + i * 128;
            int row = slot >> 3, quad = slot & 7;
            uint32_t soff = (uint32_t)row * ROWB + (uint32_t)quad * 16u;
            size_t goff = (size_t)(m0 + row) * DMODEL + c * KCH + quad * 8;
            cp16(sbase + A_OFF + soff, Ahg + goff);
        }
#pragma unroll
        for (int i = 0; i < 4; i++) {
            int slot = tid + i * 128;
            int row = slot >> 3, quad = slot & 7;
            uint32_t soff = (uint32_t)row * ROWB + (uint32_t)quad * 16u;
            size_t goff = (size_t)(n0 + row) * DMODEL + c * KCH + quad * 8;
            cp16(sbase + B_OFF + soff, Whg + goff);
        }
    };

    float acc[4][4][4];
#pragma unroll
    for (int mf = 0; mf < 4; mf++)
#pragma unroll
        for (int nf = 0; nf < 4; nf++)
#pragma unroll
            for (int j = 0; j < 4; j++) acc[mf][nf][j] = 0.0f;

    load_chunk(0, 0); CP_COMMIT();

    for (int c = 0; c < NC; c++) {
        CP_WAIT(0);
        __syncthreads();
        if (c + 1 < NC) {
            load_chunk(c + 1, (c + 1) & 1);
            CP_COMMIT();
        }

        const uint32_t sbase = smb + (uint32_t)(c & 1) * STG_B;

#pragma unroll
        for (int ks = 0; ks < 4; ks++) {
            const int kk = ks * 16;
            uint32_t ah[4][4], bh[8];
#pragma unroll
            for (int mf = 0; mf < 4; mf++) {
                uint32_t idx = (uint32_t)((wm * 64 + mf * 16) * PITCH + kk + laneA) * 2;
                ldsm4(ah[mf], sbase + A_OFF + idx);
            }
#pragma unroll
            for (int nf2 = 0; nf2 < 2; nf2++) {
                uint32_t idx = (uint32_t)((wn * 32 + nf2 * 16) * PITCH + kk + laneB) * 2;
                ldsm4(bh + nf2 * 4, sbase + B_OFF + idx);
            }
#pragma unroll
            for (int mf = 0; mf < 4; mf++)
#pragma unroll
                for (int nf = 0; nf < 4; nf++) {
                    int bi = (nf >> 1) * 4 + (nf & 1) * 2;
                    mma16816(acc[mf][nf], ah[mf], bh[bi], bh[bi + 1]);
                }
        }
        __syncthreads();
    }

    // epilogue
#pragma unroll
    for (int mf = 0; mf < 4; mf++) {
#pragma unroll
        for (int nf = 0; nf < 4; nf++) {
            int m = m0 + wm * 64 + mf * 16 + (lane >> 2);
            int n = n0 + wn * 32 + nf * 8 + (lane & 3) * 2;
            float bx = bias[n], by = bias[n + 1];
#pragma unroll
            for (int hh = 0; hh < 2; hh++) {
                int mm = m + hh * 8;
                float vx = acc[mf][nf][hh * 2 + 0] + bx;
                float vy = acc[mf][nf][hh * 2 + 1] + by;
                if (QKV) {
                    int b = mm >> 11, s = mm & (S_LEN - 1);
                    int h = n >> 6, d = n & (DK - 1);
                    size_t idx = ((size_t)((b << 4) + h) * S_LEN + s) * DK + d;
                    *(__half2*)(Ch + idx) = __floats2half2_rn(vx, vy);
                } else {
                    float2 v; v.x = vx; v.y = vy;
                    *(float2*)(Cf + (size_t)mm * DMODEL + n) = v;
                }
            }
        }
    }
}

// ---------------- HMMA causal flash attention (paired-q KV sharing) -----
// One CTA (128 thr, 4 warps) processes q-tiles qa=pair and qb=31-pair over
// a SINGLE shared KV stream: every tile qa needs is a prefix of qb's range.
// BQ=64 each, BKV=128, 2-stage depth-1 prefetch, 2 CTAs/SM.
#define FPITCH 72                          // halves
#define FROWB  144
#define QBUF   (64 * FROWB)                // 9216 B
#define KVBUF  (128 * FROWB)               // 18432 B
#define OFF_QA 0
#define OFF_QB QBUF
#define OFF_KV (2 * QBUF)                  // 18432
#define KVSTG  (2 * KVBUF)                 // 36864 (K + V)
#define SMEM_FLASH (OFF_KV + 2 * KVSTG)    // 92160

__global__ __launch_bounds__(128, 2) void flash_mma(
    const __half* __restrict__ Qh,
    const __half* __restrict__ Kh, const __half* __restrict__ Vh,
    __half* __restrict__ Oh)
{
    extern __shared__ char sm[];
    const uint32_t smb = cvta_smem(sm);
    const int tid = threadIdx.x;
    const int w = tid >> 5, lane = tid & 31;
    const int pair = blockIdx.x;          // 0..15
    const int bh = blockIdx.y;            // 0..63

    const size_t seqbase = (size_t)bh * S_LEN * DK;

    const int qa = pair, qb = 31 - pair;  // qa < qb always
    const int q0a = qa * 64, q0b = qb * 64;
    const int Ta = (qa + 2) >> 1, Tb = (qb + 2) >> 1;

    const int laneA = (lane & 15) * FPITCH + ((lane >> 4) & 1) * 8;
    const int laneB = ((lane & 7) + ((lane >> 4) & 1) * 8) * FPITCH + ((lane >> 3) & 1) * 8;
    const int laneV = ((lane & 7) + ((lane >> 3) & 1) * 8) * FPITCH + ((lane >> 4) & 1) * 8;

    const float cs = 0.18033688f;         // (1/8) * log2(e)
    const int b = bh >> 4, h = bh & 15;
    const int cbase = (lane & 3) * 2;

    // load both Q tiles (64 rows each)
#pragma unroll
    for (int i = 0; i < 4; i++) {
        int slot = tid + i * 128;
        int r = slot >> 3, quad = slot & 7;
        uint32_t so = (uint32_t)r * FROWB + (uint32_t)quad * 16u;
        cp16(smb + OFF_QA + so, Qh + seqbase + (size_t)(q0a + r) * DK + quad * 8);
        cp16(smb + OFF_QB + so, Qh + seqbase + (size_t)(q0b + r) * DK + quad * 8);
    }
    auto load_tile = [&](int kt, int stage) {
        const uint32_t sb = smb + OFF_KV + (uint32_t)stage * KVSTG;
#pragma unroll
        for (int i = 0; i < 8; i++) {
            int slot = tid + i * 128;
            int r = slot >> 3, quad = slot & 7;   // r: 0..127
            uint32_t so = (uint32_t)r * FROWB + (uint32_t)quad * 16u;
            size_t g = seqbase + (size_t)(kt * 128 + r) * DK + quad * 8;
            cp16(sb + 0 * KVBUF + so, Kh + g);
            cp16(sb + 1 * KVBUF + so, Vh + g);
        }
    };
    load_tile(0, 0); CP_COMMIT();

    uint32_t qhfA[4][4], qhfB[4][4];
    float oaccA[8][4], oaccB[8][4];
#pragma unroll
    for (int nf = 0; nf < 8; nf++)
#pragma unroll
        for (int j = 0; j < 4; j++) { oaccA[nf][j] = 0.0f; oaccB[nf][j] = 0.0f; }
    float mA0 = -1e30f, mA1 = -1e30f, lA0 = 0.0f, lA1 = 0.0f;
    float mB0 = -1e30f, mB1 = -1e30f, lB0 = 0.0f, lB1 = 0.0f;

    // per-tile compute for one q-subtile (inlined lambda)
    auto process = [&](const uint32_t (&qhf)[4][4], float (&oacc)[8][4],
                       float& m0r, float& m1r, float& l0r, float& l1r,
                       int q0, bool lastTile, uint32_t kvb, int kt) {
        const int rbase = q0 + w * 16 + (lane >> 2);

        // ---- S = Q K^T ----
        float sacc[16][4];
#pragma unroll
        for (int nf = 0; nf < 16; nf++)
#pragma unroll
            for (int j = 0; j < 4; j++) sacc[nf][j] = 0.0f;

#pragma unroll
        for (int ks = 0; ks < 4; ks++) {
            uint32_t kb[32];
#pragma unroll
            for (int nb = 0; nb < 8; nb++) {
                uint32_t a = kvb + (uint32_t)((nb * 16) * FPITCH + ks * 16 + laneB) * 2;
                ldsm4(kb + nb * 4, a);
            }
#pragma unroll
            for (int nf = 0; nf < 16; nf++) {
                int bi = (nf >> 1) * 4 + (nf & 1) * 2;
                mma16816(sacc[nf], qhf[ks], kb[bi], kb[bi + 1]);
            }
        }

        // ---- scale (+ causal mask on the last tile) ----
        if (lastTile) {
#pragma unroll
            for (int nf = 0; nf < 16; nf++) {
#pragma unroll
                for (int j = 0; j < 4; j++) {
                    int col = kt * 128 + nf * 8 + cbase + (j & 1);
                    int row = rbase + ((j >> 1) << 3);
                    sacc[nf][j] = (col <= row) ? sacc[nf][j] * cs : -1e30f;
                }
            }
        } else {
#pragma unroll
            for (int nf = 0; nf < 16; nf++)
#pragma unroll
                for (int j = 0; j < 4; j++) sacc[nf][j] *= cs;
        }

        // ---- online softmax (base-2) ----
        float mx0 = -1e30f, mx1 = -1e30f;
#pragma unroll
        for (int nf = 0; nf < 16; nf++) {
            mx0 = fmaxf(mx0, fmaxf(sacc[nf][0], sacc[nf][1]));
            mx1 = fmaxf(mx1, fmaxf(sacc[nf][2], sacc[nf][3]));
        }
        mx0 = fmaxf(mx0, __shfl_xor_sync(0xffffffffu, mx0, 1));
        mx0 = fmaxf(mx0, __shfl_xor_sync(0xffffffffu, mx0, 2));
        mx1 = fmaxf(mx1, __shfl_xor_sync(0xffffffffu, mx1, 1));
        mx1 = fmaxf(mx1, __shfl_xor_sync(0xffffffffu, mx1, 2));

        float mn0 = fmaxf(m0r, mx0), mn1 = fmaxf(m1r, mx1);
        float c0 = ex2(m0r - mn0), c1 = ex2(m1r - mn1);
        m0r = mn0; m1r = mn1;

        uint32_t pHa[16], pHb[16];
        float ls0 = 0.0f, ls1 = 0.0f;
#pragma unroll
        for (int nf = 0; nf < 16; nf++) {
            float p0 = ex2(sacc[nf][0] - mn0);
            float p1 = ex2(sacc[nf][1] - mn0);
            float p2 = ex2(sacc[nf][2] - mn1);
            float p3 = ex2(sacc[nf][3] - mn1);
            ls0 += p0 + p1;
            ls1 += p2 + p3;
            __half2 h01 = __floats2half2_rn(p0, p1);
            __half2 h23 = __floats2half2_rn(p2, p3);
            pHa[nf] = *(uint32_t*)&h01;
            pHb[nf] = *(uint32_t*)&h23;
        }
        ls0 += __shfl_xor_sync(0xffffffffu, ls0, 1);
        ls0 += __shfl_xor_sync(0xffffffffu, ls0, 2);
        ls1 += __shfl_xor_sync(0xffffffffu, ls1, 1);
        ls1 += __shfl_xor_sync(0xffffffffu, ls1, 2);
        l0r = l0r * c0 + ls0;
        l1r = l1r * c1 + ls1;
#pragma unroll
        for (int nf = 0; nf < 8; nf++) {
            oacc[nf][0] *= c0; oacc[nf][1] *= c0;
            oacc[nf][2] *= c1; oacc[nf][3] *= c1;
        }

        // ---- O += P V ----
        const uint32_t vbb = kvb + KVBUF;
#pragma unroll
        for (int ks = 0; ks < 8; ks++) {
            uint32_t vb[16];
#pragma unroll
            for (int nb = 0; nb < 4; nb++) {
                uint32_t a = vbb + (uint32_t)((ks * 16) * FPITCH + nb * 16 + laneV) * 2;
                ldsm4t(vb + nb * 4, a);
            }
            uint32_t pa[4] = { pHa[2 * ks], pHb[2 * ks],
                               pHa[2 * ks + 1], pHb[2 * ks + 1] };
#pragma unroll
            for (int nf = 0; nf < 8; nf++) {
                int bi = (nf >> 1) * 4 + (nf & 1) * 2;
                mma16816(oacc[nf], pa, vb[bi], vb[bi + 1]);
            }
        }
    };

    for (int kt = 0; kt < Tb; kt++) {
        CP_WAIT(0);
        __syncthreads();

        if (kt == 0) {
#pragma unroll
            for (int ks = 0; ks < 4; ks++) {
                uint32_t off = (uint32_t)((w * 16) * FPITCH + ks * 16 + laneA) * 2;
                ldsm4(qhfA[ks], smb + OFF_QA + off);
                ldsm4(qhfB[ks], smb + OFF_QB + off);
            }
        }
        if (kt + 1 < Tb) {
            load_tile(kt + 1, (kt + 1) & 1);
            CP_COMMIT();
        }

        const uint32_t kvb = smb + OFF_KV + (uint32_t)(kt & 1) * KVSTG;

        process(qhfB, oaccB, mB0, mB1, lB0, lB1, q0b, kt == Tb - 1, kvb, kt);
        if (kt < Ta)
            process(qhfA, oaccA, mA0, mA1, lA0, lA1, q0a, kt == Ta - 1, kvb, kt);
    }

    // ---- epilogue: write fp16 context [B,S,1024] for both q-tiles ----
#pragma unroll
    for (int which = 0; which < 2; which++) {
        float (*oacc)[4] = which ? oaccB : oaccA;
        const float inv0 = 1.0f / (which ? lB0 : lA0);
        const float inv1 = 1.0f / (which ? lB1 : lA1);
        const int q0 = which ? q0b : q0a;
        const int s0 = q0 + w * 16 + (lane >> 2);
#pragma unroll
        for (int nf = 0; nf < 8; nf++) {
            int col = h * DK + nf * 8 + cbase;
#pragma unroll
            for (int hh = 0; hh < 2; hh++) {
                int s = s0 + hh * 8;
                float vx = oacc[nf][hh * 2 + 0] * (hh ? inv1 : inv0);
                float vy = oacc[nf][hh * 2 + 1] * (hh ? inv1 : inv0);
                size_t idx = ((size_t)(b * S_LEN + s)) * DMODEL + col;
                *(__half2*)(Oh + idx) = __floats2half2_rn(vx, vy);
            }
        }
    }
}

// ===========================================================================
extern "C" void kernel_launch(void* const* d_in, const int* in_sizes, int n_in,
                              void* d_out, int out_size)
{
    const float* query = (const float*)d_in[0];
    const float* key   = (const float*)d_in[1];
    const float* value = (const float*)d_in[2];
    // d_in[3] = causal mask — handled analytically.
    const float* Wq = (const float*)d_in[4];
    const float* bq = (const float*)d_in[5];
    const float* Wk = (const float*)d_in[6];
    const float* bk = (const float*)d_in[7];
    const float* Wv = (const float*)d_in[8];
    const float* bv = (const float*)d_in[9];
    const float* Wo = (const float*)d_in[10];
    const float* bo = (const float*)d_in[11];
    float* out = (float*)d_out;

    __half *Aq, *Ak, *Av, *Qh, *Kh, *Vh, *Wqh, *Wkh, *Wvh, *Woh;
    cudaGetSymbolAddress((void**)&Aq, g_Aq);
    cudaGetSymbolAddress((void**)&Ak, g_Ak);
    cudaGetSymbolAddress((void**)&Av, g_Av);
    cudaGetSymbolAddress((void**)&Qh, g_Qh);
    cudaGetSymbolAddress((void**)&Kh, g_Kh);
    cudaGetSymbolAddress((void**)&Vh, g_Vh);
    cudaGetSymbolAddress((void**)&Wqh, g_Wqh);
    cudaGetSymbolAddress((void**)&Wkh, g_Wkh);
    cudaGetSymbolAddress((void**)&Wvh, g_Wvh);
    cudaGetSymbolAddress((void**)&Woh, g_Woh);

    cudaFuncSetAttribute(proj_gemm_mma<1>,
                         cudaFuncAttributeMaxDynamicSharedMemorySize, SMEM_GEMM);
    cudaFuncSetAttribute(proj_gemm_mma<0>,
                         cudaFuncAttributeMaxDynamicSharedMemorySize, SMEM_GEMM);
    cudaFuncSetAttribute(flash_mma,
                         cudaFuncAttributeMaxDynamicSharedMemorySize, SMEM_FLASH);

    // one consolidated conversion pass
    split_all<<<SPLIT_GRID, 256>>>(
        (const float4*)query, (const float4*)key, (const float4*)value,
        (const float4*)Wq, (const float4*)Wk, (const float4*)Wv, (const float4*)Wo,
        (uint2*)Aq, (uint2*)Ak, (uint2*)Av,
        (uint2*)Wqh, (uint2*)Wkh, (uint2*)Wvh, (uint2*)Woh);

    // Q, K, V projections batched in one launch
    dim3 gq(DMODEL / TILE_N, MTOT / TILE_M, 3);   // (16, 64, 3)
    proj_gemm_mma<1><<<gq, 128, SMEM_GEMM>>>(
        Aq, Ak, Av, Wqh, Wkh, Wvh, bq, bk, bv, Qh, Kh, Vh, nullptr);

    // attention: paired q-tiles, writes fp16 context into Aq
    flash_mma<<<dim3(16, BATCH * NHEAD), 128, SMEM_FLASH>>>(Qh, Kh, Vh, Aq);

    // out = Ctx @ Wo^T + bo (fp32 out)
    dim3 go(DMODEL / TILE_N, MTOT / TILE_M, 1);   // (16, 64)
    proj_gemm_mma<0><<<go, 128, SMEM_GEMM>>>(
        Aq, nullptr, nullptr, Woh, nullptr, nullptr,
        bo, nullptr, nullptr, nullptr, nullptr, nullptr, out);
}